// round 1
// baseline (speedup 1.0000x reference)
#include <cuda_runtime.h>

// ---------------- dims ----------------
#define BB 2
#define CIN 64
#define COUT 128
#define CHALF 64
#define HIN 128
#define H 64
#define P (H*H)          // 4096
#define LT 11882         // 64^2 + 57^2 + 51^2 + 44^2
#define K9 576           // CHALF*9
#define K18 1152         // COUT*9

// ---------------- scratch (device globals; allocation-free) ----------------
__device__ float g_h0[BB*CIN*P];
__device__ float g_h1[BB*COUT*P];
__device__ float g_h2[BB*COUT*P];
__device__ float g_tmp[BB*COUT*P];
__device__ float g_h3[BB*COUT*P];
__device__ float g_mb[BB*CHALF*P];
__device__ float g_ref[BB*COUT*3249];
__device__ float g_base[(size_t)BB*COUT*LT];
__device__ float g_refm[(size_t)BB*CHALF*LT];
__device__ float g_XP[(size_t)BB*K9*P];
__device__ float g_WN[(size_t)BB*LT*K9];
__device__ float g_RWt[(size_t)BB*K18*LT];
__device__ float g_scores[(size_t)BB*LT*P];
__device__ float g_T[(size_t)BB*K18*P];

// ---------------- maxpool 2x2 ----------------
__global__ void maxpool_kernel(const float* __restrict__ in, float* __restrict__ out) {
    int idx = blockIdx.x*blockDim.x + threadIdx.x;
    const int total = BB*CIN*P;
    if (idx >= total) return;
    int x = idx % H; int y = (idx / H) % H; int bc = idx / P;
    const float* p = in + ((size_t)bc*HIN + 2*y)*HIN + 2*x;
    out[idx] = fmaxf(fmaxf(p[0], p[1]), fmaxf(p[HIN], p[HIN+1]));
}

// ---------------- 3x3 conv (pad 1), optional relu/prelu/residual ----------------
// grid: (W/16, H/16, BB*Co), block (16,16). Ci % 8 == 0.
__global__ void conv3_kernel(const float* __restrict__ in, const float* __restrict__ w,
                             const float* __restrict__ bias, const float* __restrict__ res,
                             float* __restrict__ out, int Ci, int Co,
                             int act, const float* __restrict__ alpha_p) {
    int bx = blockIdx.x*16, by = blockIdx.y*16;
    int co = blockIdx.z % Co, b = blockIdx.z / Co;
    int tx = threadIdx.x, ty = threadIdx.y;
    int tid = ty*16 + tx;
    __shared__ float tile[8][18][18];
    __shared__ float wsh[8][9];
    float acc = bias[co];
    for (int c0 = 0; c0 < Ci; c0 += 8) {
        for (int idx = tid; idx < 8*18*18; idx += 256) {
            int c = idx / 324; int r = idx % 324; int yy = r/18, xx = r%18;
            int gy = by + yy - 1, gx = bx + xx - 1;
            float v = 0.f;
            if (gy >= 0 && gy < H && gx >= 0 && gx < H)
                v = in[(((size_t)b*Ci + c0 + c)*H + gy)*H + gx];
            tile[c][yy][xx] = v;
        }
        if (tid < 72) {
            int c = tid/9, k = tid%9;
            wsh[c][k] = w[((size_t)co*Ci + c0 + c)*9 + k];
        }
        __syncthreads();
        #pragma unroll
        for (int c = 0; c < 8; c++)
            #pragma unroll
            for (int ky = 0; ky < 3; ky++)
                #pragma unroll
                for (int kx = 0; kx < 3; kx++)
                    acc += tile[c][ty+ky][tx+kx] * wsh[c][ky*3+kx];
        __syncthreads();
    }
    float v = acc;
    if (act == 1) v = fmaxf(v, 0.f);
    else if (act == 2) { float a = *alpha_p; v = v >= 0.f ? v : a*v; }
    size_t o = (((size_t)b*Co + co)*H + (by+ty))*H + (bx+tx);
    if (res) v += res[o];
    out[o] = v;
}

// ---------------- 1x1 conv + PReLU ----------------
// grid: (ceil(Pn/256), Co, BB)
__global__ void conv1_kernel(const float* __restrict__ in, const float* __restrict__ w,
                             const float* __restrict__ bias, const float* __restrict__ alpha_p,
                             float* __restrict__ out, int Ci, int Co, int Pn) {
    int p = blockIdx.x*256 + threadIdx.x;
    int o = blockIdx.y, b = blockIdx.z;
    if (p >= Pn) return;
    const float* ip = in + (size_t)b*Ci*Pn + p;
    const float* wp = w + (size_t)o*Ci;
    float acc = bias[o];
    #pragma unroll 8
    for (int i = 0; i < Ci; i++) acc += wp[i] * ip[(size_t)i*Pn];
    float a = *alpha_p;
    out[((size_t)b*Co + o)*Pn + p] = acc >= 0.f ? acc : a*acc;
}

// ---------------- bilinear resize with antialias (jax.image.resize semantics) ----------------
__global__ void resize_kernel(const float* __restrict__ in, float* __restrict__ out, int Hout) {
    int total = BB*COUT*Hout*Hout;
    int idx = blockIdx.x*blockDim.x + threadIdx.x;
    if (idx >= total) return;
    int xo = idx % Hout; int yo = (idx / Hout) % Hout; int bc = idx / (Hout*Hout);
    float scale = (float)Hout / (float)H;      // out/in < 1
    float inv = 1.0f / scale;                  // kernel_scale = inv (antialias downsample)
    float sy = (yo + 0.5f)*inv - 0.5f;
    float sx = (xo + 0.5f)*inv - 0.5f;
    float wy[4], wx[4]; int jy[4], jx[4];
    int ny = 0, nx = 0; float sumy = 0.f, sumx = 0.f;
    int lo = (int)ceilf(sy - inv), hi = (int)floorf(sy + inv);
    if (lo < 0) lo = 0; if (hi > H-1) hi = H-1;
    for (int j = lo; j <= hi && ny < 4; j++) {
        float w = 1.0f - fabsf(sy - (float)j)/inv;
        if (w > 0.f) { wy[ny] = w; jy[ny] = j; sumy += w; ny++; }
    }
    lo = (int)ceilf(sx - inv); hi = (int)floorf(sx + inv);
    if (lo < 0) lo = 0; if (hi > H-1) hi = H-1;
    for (int j = lo; j <= hi && nx < 4; j++) {
        float w = 1.0f - fabsf(sx - (float)j)/inv;
        if (w > 0.f) { wx[nx] = w; jx[nx] = j; sumx += w; nx++; }
    }
    const float* ip = in + (size_t)bc*P;
    float acc = 0.f;
    for (int a = 0; a < ny; a++)
        for (int bx = 0; bx < nx; bx++)
            acc += wy[a]*wx[bx]*ip[jy[a]*H + jx[bx]];
    out[idx] = acc / (sumy*sumx);
}

// ---------------- query patches XP[b][k][p] ----------------
__global__ void xp_kernel(const float* __restrict__ mb, float* __restrict__ XP) {
    size_t total = (size_t)BB*K9*P;
    size_t idx = (size_t)blockIdx.x*blockDim.x + threadIdx.x;
    if (idx >= total) return;
    int p = idx % P; int k = (idx / P) % K9; int b = idx / ((size_t)P*K9);
    int c = k/9, r = k%9; int ky = r/3, kx = r%3;
    int y = p/H + ky - 1, x = p%H + kx - 1;
    float v = 0.f;
    if ((unsigned)y < H && (unsigned)x < H) v = mb[((size_t)b*CHALF + c)*P + y*H + x];
    XP[idx] = v;
}

__device__ __forceinline__ void decode_l(int l, int& Hs, int& loff) {
    if (l < 4096)      { Hs = 64; loff = 0; }
    else if (l < 7345) { Hs = 57; loff = 4096; }
    else if (l < 9946) { Hs = 51; loff = 7345; }
    else               { Hs = 44; loff = 9946; }
}

// ---------------- normalized key patches WN[b][l][k] ----------------
__global__ void wn_kernel(const float* __restrict__ refm, float* __restrict__ WN) {
    int l = blockIdx.x, b = blockIdx.y;
    int tid = threadIdx.x;
    int Hs, loff; decode_l(l, Hs, loff);
    int Ls = Hs*Hs; int ll = l - loff; int lh = ll/Hs, lw = ll%Hs;
    const float* rp = refm + (size_t)BB*CHALF*loff + (size_t)b*CHALF*Ls;
    __shared__ float vals[K9];
    __shared__ float red[128];
    float ss = 0.f;
    for (int k = tid; k < K9; k += 128) {
        int c = k/9, r = k%9; int ky = r/3, kx = r%3;
        int y = lh + ky - 1, x = lw + kx - 1;
        float v = 0.f;
        if ((unsigned)y < (unsigned)Hs && (unsigned)x < (unsigned)Hs) v = rp[(size_t)c*Ls + y*Hs + x];
        vals[k] = v; ss += v*v;
    }
    red[tid] = ss; __syncthreads();
    for (int o = 64; o > 0; o >>= 1) { if (tid < o) red[tid] += red[tid+o]; __syncthreads(); }
    float rn = 1.0f / fmaxf(sqrtf(red[0]), 1e-4f);
    float* wp = WN + ((size_t)b*LT + l)*K9;
    for (int k = tid; k < K9; k += 128) wp[k] = vals[k]*rn;
}

// ---------------- assembly patches, transposed: RWt[b][j][l] ----------------
__global__ void rwt_kernel(const float* __restrict__ base, float* __restrict__ RWt) {
    int l = blockIdx.x*blockDim.x + threadIdx.x;
    if (l >= LT) return;
    int j = blockIdx.y, b = blockIdx.z;
    int c = j/9, r = j%9; int ky = r/3, kx = r%3;
    int Hs, loff; decode_l(l, Hs, loff);
    int Ls = Hs*Hs; int ll = l - loff; int lh = ll/Hs, lw = ll%Hs;
    int y = lh + ky - 1, x = lw + kx - 1;
    float v = 0.f;
    if ((unsigned)y < (unsigned)Hs && (unsigned)x < (unsigned)Hs)
        v = base[(size_t)BB*COUT*loff + ((size_t)b*COUT + c)*Ls + y*Hs + x];
    RWt[((size_t)b*K18 + j)*LT + l] = v;
}

// ---------------- 128x128x8 SGEMM, 8x8 per thread, row-major A/B/C, batched ----------------
__global__ void sgemm_kernel(const float* __restrict__ A, const float* __restrict__ B,
                             float* __restrict__ C, int M, int N, int K,
                             size_t sA, size_t sB, size_t sC) {
    int b = blockIdx.z;
    A += (size_t)b*sA; B += (size_t)b*sB; C += (size_t)b*sC;
    int row0 = blockIdx.y*128, col0 = blockIdx.x*128;
    __shared__ float As[8][128];
    __shared__ float Bs[8][128];
    int tid = threadIdx.x;
    int tx = tid % 16, ty = tid / 16;
    float acc[8][8];
    #pragma unroll
    for (int i = 0; i < 8; i++)
        #pragma unroll
        for (int j = 0; j < 8; j++) acc[i][j] = 0.f;

    for (int k0 = 0; k0 < K; k0 += 8) {
        #pragma unroll
        for (int q = 0; q < 4; q++) {
            int idx = tid + q*256;
            int m = idx / 8, ka = idx % 8;
            int gm = row0 + m, gka = k0 + ka;
            As[ka][m] = (gm < M && gka < K) ? A[(size_t)gm*K + gka] : 0.f;
            int n = idx % 128, kb = idx / 128;
            int gn = col0 + n, gkb = k0 + kb;
            Bs[kb][n] = (gkb < K && gn < N) ? B[(size_t)gkb*N + gn] : 0.f;
        }
        __syncthreads();
        #pragma unroll
        for (int kk = 0; kk < 8; kk++) {
            float a[8], bb[8];
            #pragma unroll
            for (int i = 0; i < 4; i++) {
                a[i]    = As[kk][ty*4 + i];
                a[4+i]  = As[kk][64 + ty*4 + i];
                bb[i]   = Bs[kk][tx*4 + i];
                bb[4+i] = Bs[kk][64 + tx*4 + i];
            }
            #pragma unroll
            for (int i = 0; i < 8; i++)
                #pragma unroll
                for (int j = 0; j < 8; j++)
                    acc[i][j] += a[i]*bb[j];
        }
        __syncthreads();
    }
    #pragma unroll
    for (int i = 0; i < 8; i++) {
        int gm = row0 + (i < 4 ? ty*4 + i : 64 + ty*4 + (i-4));
        if (gm >= M) continue;
        #pragma unroll
        for (int j = 0; j < 8; j++) {
            int gn = col0 + (j < 4 ? tx*4 + j : 64 + tx*4 + (j-4));
            if (gn < N) C[(size_t)gm*N + gn] = acc[i][j];
        }
    }
}

// ---------------- softmax over l (column-wise), in place, scale 10 ----------------
__global__ void softmax_kernel(float* __restrict__ scores) {
    int p = blockIdx.x, b = blockIdx.y;
    int tid = threadIdx.x;
    float* col = scores + (size_t)b*LT*P + p;
    __shared__ float red[256];
    float m = -1e30f;
    for (int l = tid; l < LT; l += 256) m = fmaxf(m, col[(size_t)l*P]);
    red[tid] = m; __syncthreads();
    for (int o = 128; o > 0; o >>= 1) { if (tid < o) red[tid] = fmaxf(red[tid], red[tid+o]); __syncthreads(); }
    m = red[0]; __syncthreads();
    float s = 0.f;
    for (int l = tid; l < LT; l += 256) s += expf(10.f*(col[(size_t)l*P] - m));
    red[tid] = s; __syncthreads();
    for (int o = 128; o > 0; o >>= 1) { if (tid < o) red[tid] += red[tid+o]; __syncthreads(); }
    float inv = 1.0f / red[0];
    for (int l = tid; l < LT; l += 256) {
        float v = expf(10.f*(col[(size_t)l*P] - m));
        col[(size_t)l*P] = v*inv;
    }
}

// ---------------- col2im gather for conv_transpose + residual ----------------
__global__ void col2im_kernel(const float* __restrict__ T, const float* __restrict__ h2,
                              float* __restrict__ out) {
    int idx = blockIdx.x*blockDim.x + threadIdx.x;
    const int total = BB*COUT*P;
    if (idx >= total) return;
    int w = idx % H; int hh = (idx / H) % H; int c = (idx / P) % COUT; int b = idx / (P*COUT);
    float acc = 0.f;
    #pragma unroll
    for (int a = 0; a < 3; a++) {
        int y = hh + 1 - a;
        if ((unsigned)y >= H) continue;
        #pragma unroll
        for (int d = 0; d < 3; d++) {
            int x = w + 1 - d;
            if ((unsigned)x >= H) continue;
            acc += T[((size_t)b*K18 + c*9 + a*3 + d)*P + y*H + x];
        }
    }
    out[idx] = h2[idx] + 0.25f*acc;
}

// ---------------- launch ----------------
extern "C" void kernel_launch(void* const* d_in, const int* in_sizes, int n_in,
                              void* d_out, int out_size) {
    (void)in_sizes; (void)n_in; (void)out_size;
    const float* x      = (const float*)d_in[0];
    const float* bb0_w  = (const float*)d_in[1];
    const float* bb0_b  = (const float*)d_in[2];
    const float* bb0_a  = (const float*)d_in[3];
    const float* rb1_w1 = (const float*)d_in[4];
    const float* rb1_b1 = (const float*)d_in[5];
    const float* rb1_w2 = (const float*)d_in[6];
    const float* rb1_b2 = (const float*)d_in[7];
    const float* pamb_w = (const float*)d_in[8];
    const float* pamb_b = (const float*)d_in[9];
    const float* pamb_a = (const float*)d_in[10];
    const float* pam_w  = (const float*)d_in[11];
    const float* pam_b  = (const float*)d_in[12];
    const float* pam_a  = (const float*)d_in[13];
    const float* paa_w  = (const float*)d_in[14];
    const float* paa_b  = (const float*)d_in[15];
    const float* paa_a  = (const float*)d_in[16];
    const float* rb2_w1 = (const float*)d_in[17];
    const float* rb2_b1 = (const float*)d_in[18];
    const float* rb2_w2 = (const float*)d_in[19];
    const float* rb2_b2 = (const float*)d_in[20];
    float* out = (float*)d_out;

    float *h0,*h1,*h2,*tmp,*h3,*mb,*ref,*base,*refm,*XP,*WN,*RWt,*scores,*T;
    cudaGetSymbolAddress((void**)&h0, g_h0);
    cudaGetSymbolAddress((void**)&h1, g_h1);
    cudaGetSymbolAddress((void**)&h2, g_h2);
    cudaGetSymbolAddress((void**)&tmp, g_tmp);
    cudaGetSymbolAddress((void**)&h3, g_h3);
    cudaGetSymbolAddress((void**)&mb, g_mb);
    cudaGetSymbolAddress((void**)&ref, g_ref);
    cudaGetSymbolAddress((void**)&base, g_base);
    cudaGetSymbolAddress((void**)&refm, g_refm);
    cudaGetSymbolAddress((void**)&XP, g_XP);
    cudaGetSymbolAddress((void**)&WN, g_WN);
    cudaGetSymbolAddress((void**)&RWt, g_RWt);
    cudaGetSymbolAddress((void**)&scores, g_scores);
    cudaGetSymbolAddress((void**)&T, g_T);

    dim3 cb(16,16);
    dim3 cg(4,4,BB*COUT);

    // pool + head
    maxpool_kernel<<<(BB*CIN*P + 255)/256, 256>>>(x, h0);
    conv3_kernel<<<cg, cb>>>(h0, bb0_w, bb0_b, nullptr, h1, CIN, COUT, 2, bb0_a);
    // resblock 1
    conv3_kernel<<<cg, cb>>>(h1, rb1_w1, rb1_b1, nullptr, tmp, COUT, COUT, 1, nullptr);
    conv3_kernel<<<cg, cb>>>(tmp, rb1_w2, rb1_b2, h1, h2, COUT, COUT, 0, nullptr);

    // pyramid attention
    conv1_kernel<<<dim3(P/256, CHALF, BB), 256>>>(h2, pamb_w, pamb_b, pamb_a, mb, COUT, CHALF, P);
    xp_kernel<<<(int)(((size_t)BB*K9*P + 255)/256), 256>>>(mb, XP);

    const int Hs[4]   = {64, 57, 51, 44};
    const int loff[4] = {0, 4096, 7345, 9946};
    for (int s = 0; s < 4; s++) {
        int Ls = Hs[s]*Hs[s];
        const float* refp;
        if (s == 0) refp = h2;
        else {
            int n = BB*COUT*Ls;
            resize_kernel<<<(n + 255)/256, 256>>>(h2, ref, Hs[s]);
            refp = ref;
        }
        conv1_kernel<<<dim3((Ls + 255)/256, COUT, BB), 256>>>(
            refp, paa_w, paa_b, paa_a, base + (size_t)BB*COUT*loff[s], COUT, COUT, Ls);
        conv1_kernel<<<dim3((Ls + 255)/256, CHALF, BB), 256>>>(
            refp, pam_w, pam_b, pam_a, refm + (size_t)BB*CHALF*loff[s], COUT, CHALF, Ls);
    }

    wn_kernel<<<dim3(LT, BB), 128>>>(refm, WN);
    rwt_kernel<<<dim3((LT + 255)/256, K18, BB), 256>>>(base, RWt);

    // scores = WN x XP   [LT,576]x[576,4096]
    sgemm_kernel<<<dim3(P/128, (LT + 127)/128, BB), 256>>>(
        WN, XP, scores, LT, P, K9, (size_t)LT*K9, (size_t)K9*P, (size_t)LT*P);

    softmax_kernel<<<dim3(P, BB), 256>>>(scores);

    // T = RWt x att    [1152,LT]x[LT,4096]
    sgemm_kernel<<<dim3(P/128, K18/128, BB), 256>>>(
        RWt, scores, T, K18, P, LT, (size_t)K18*LT, (size_t)LT*P, (size_t)K18*P);

    col2im_kernel<<<(BB*COUT*P + 255)/256, 256>>>(T, h2, h3);

    // resblock 2 -> output
    conv3_kernel<<<cg, cb>>>(h3, rb2_w1, rb2_b1, nullptr, tmp, COUT, COUT, 1, nullptr);
    conv3_kernel<<<cg, cb>>>(tmp, rb2_w2, rb2_b2, h3, out, COUT, COUT, 0, nullptr);
}

// round 2
// speedup vs baseline: 2.5592x; 2.5592x over previous
#include <cuda_runtime.h>
#include <cuda_bf16.h>
#include <cstdint>

// ---------------- dims ----------------
#define BB 2
#define CIN 64
#define COUT 128
#define CHALF 64
#define HIN 128
#define H 64
#define P (H*H)          // 4096
#define LT 11882         // 64^2 + 57^2 + 51^2 + 44^2
#define LTP 11904        // LT padded to multiple of 32
#define K9 576           // CHALF*9
#define K18 1152         // COUT*9
#define NCH 32
#define SCH 372          // ceil(LT/NCH)

// ---------------- scratch (device globals; allocation-free) ----------------
__device__ __align__(128) float g_h0[BB*CIN*P];
__device__ __align__(128) float g_h1[BB*COUT*P];
__device__ __align__(128) float g_h2[BB*COUT*P];
__device__ __align__(128) float g_tmp[BB*COUT*P];
__device__ __align__(128) float g_h3[BB*COUT*P];
__device__ __align__(128) float g_mb[BB*CHALF*P];
__device__ __align__(128) float g_ref[BB*COUT*3249];
__device__ __align__(128) float g_base[(size_t)BB*COUT*LT];
__device__ __align__(128) float g_refm[(size_t)BB*CHALF*LT];
__device__ __align__(128) float g_scores[(size_t)BB*LT*P];
__device__ __align__(128) float g_T[(size_t)BB*K18*P];
__device__ __align__(128) __nv_bfloat16 g_XPh[(size_t)BB*K9*P];
__device__ __align__(128) __nv_bfloat16 g_XPl[(size_t)BB*K9*P];
__device__ __align__(128) __nv_bfloat16 g_WNh[(size_t)BB*LT*K9];
__device__ __align__(128) __nv_bfloat16 g_WNl[(size_t)BB*LT*K9];
__device__ __align__(128) __nv_bfloat16 g_RWth[(size_t)BB*K18*LTP];
__device__ __align__(128) __nv_bfloat16 g_RWtl[(size_t)BB*K18*LTP];
__device__ __align__(128) __nv_bfloat16 g_atth[(size_t)BB*LTP*P];
__device__ __align__(128) __nv_bfloat16 g_attl[(size_t)BB*LTP*P];
__device__ __align__(128) float g_pmax[BB*NCH*P];
__device__ __align__(128) float g_psum[BB*NCH*P];
__device__ __align__(128) float g_gmax[BB*P];
__device__ __align__(128) float g_ginv[BB*P];

__device__ __forceinline__ void split2(float v, __nv_bfloat16& h, __nv_bfloat16& l) {
    h = __float2bfloat16(v);
    l = __float2bfloat16(v - __bfloat162float(h));
}

// ---------------- maxpool 2x2 ----------------
__global__ void maxpool_kernel(const float* __restrict__ in, float* __restrict__ out) {
    int idx = blockIdx.x*blockDim.x + threadIdx.x;
    const int total = BB*CIN*P;
    if (idx >= total) return;
    int x = idx % H; int y = (idx / H) % H; int bc = idx / P;
    const float* p = in + ((size_t)bc*HIN + 2*y)*HIN + 2*x;
    out[idx] = fmaxf(fmaxf(p[0], p[1]), fmaxf(p[HIN], p[HIN+1]));
}

// ---------------- 3x3 conv (pad 1), 2 output channels per block ----------------
__global__ void conv3_kernel(const float* __restrict__ in, const float* __restrict__ w,
                             const float* __restrict__ bias, const float* __restrict__ res,
                             float* __restrict__ out, int Ci, int Co,
                             int act, const float* __restrict__ alpha_p) {
    int bx = blockIdx.x*16, by = blockIdx.y*16;
    int cop = blockIdx.z % (Co >> 1), b = blockIdx.z / (Co >> 1);
    int co0 = cop*2;
    int tx = threadIdx.x, ty = threadIdx.y;
    int tid = ty*16 + tx;
    __shared__ float tile[8][18][18];
    __shared__ float wsh[8][2][9];
    float acc0 = bias[co0], acc1 = bias[co0+1];
    for (int c0 = 0; c0 < Ci; c0 += 8) {
        for (int idx = tid; idx < 8*18*18; idx += 256) {
            int c = idx / 324; int r = idx % 324; int yy = r/18, xx = r%18;
            int gy = by + yy - 1, gx = bx + xx - 1;
            float v = 0.f;
            if (gy >= 0 && gy < H && gx >= 0 && gx < H)
                v = in[(((size_t)b*Ci + c0 + c)*H + gy)*H + gx];
            tile[c][yy][xx] = v;
        }
        if (tid < 144) {
            int c = tid/18, o = (tid/9)%2, k = tid%9;
            wsh[c][o][k] = w[((size_t)(co0+o)*Ci + c0 + c)*9 + k];
        }
        __syncthreads();
        #pragma unroll
        for (int c = 0; c < 8; c++)
            #pragma unroll
            for (int ky = 0; ky < 3; ky++)
                #pragma unroll
                for (int kx = 0; kx < 3; kx++) {
                    float t = tile[c][ty+ky][tx+kx];
                    acc0 += t * wsh[c][0][ky*3+kx];
                    acc1 += t * wsh[c][1][ky*3+kx];
                }
        __syncthreads();
    }
    float a = (act == 2) ? *alpha_p : 0.f;
    #pragma unroll
    for (int o = 0; o < 2; o++) {
        float v = o ? acc1 : acc0;
        if (act == 1) v = fmaxf(v, 0.f);
        else if (act == 2) v = v >= 0.f ? v : a*v;
        size_t ofs = (((size_t)b*Co + co0 + o)*H + (by+ty))*H + (bx+tx);
        if (res) v += res[ofs];
        out[ofs] = v;
    }
}

// ---------------- 1x1 conv + PReLU ----------------
__global__ void conv1_kernel(const float* __restrict__ in, const float* __restrict__ w,
                             const float* __restrict__ bias, const float* __restrict__ alpha_p,
                             float* __restrict__ out, int Ci, int Co, int Pn) {
    int p = blockIdx.x*256 + threadIdx.x;
    int o = blockIdx.y, b = blockIdx.z;
    if (p >= Pn) return;
    const float* ip = in + (size_t)b*Ci*Pn + p;
    const float* wp = w + (size_t)o*Ci;
    float acc = bias[o];
    #pragma unroll 8
    for (int i = 0; i < Ci; i++) acc += wp[i] * ip[(size_t)i*Pn];
    float a = *alpha_p;
    out[((size_t)b*Co + o)*Pn + p] = acc >= 0.f ? acc : a*acc;
}

// ---------------- bilinear resize with antialias (jax.image.resize semantics) ----------------
__global__ void resize_kernel(const float* __restrict__ in, float* __restrict__ out, int Hout) {
    int total = BB*COUT*Hout*Hout;
    int idx = blockIdx.x*blockDim.x + threadIdx.x;
    if (idx >= total) return;
    int xo = idx % Hout; int yo = (idx / Hout) % Hout; int bc = idx / (Hout*Hout);
    float scale = (float)Hout / (float)H;
    float inv = 1.0f / scale;
    float sy = (yo + 0.5f)*inv - 0.5f;
    float sx = (xo + 0.5f)*inv - 0.5f;
    float wy[4], wx[4]; int jy[4], jx[4];
    int ny = 0, nx = 0; float sumy = 0.f, sumx = 0.f;
    int lo = (int)ceilf(sy - inv), hi = (int)floorf(sy + inv);
    if (lo < 0) lo = 0; if (hi > H-1) hi = H-1;
    for (int j = lo; j <= hi && ny < 4; j++) {
        float w = 1.0f - fabsf(sy - (float)j)/inv;
        if (w > 0.f) { wy[ny] = w; jy[ny] = j; sumy += w; ny++; }
    }
    lo = (int)ceilf(sx - inv); hi = (int)floorf(sx + inv);
    if (lo < 0) lo = 0; if (hi > H-1) hi = H-1;
    for (int j = lo; j <= hi && nx < 4; j++) {
        float w = 1.0f - fabsf(sx - (float)j)/inv;
        if (w > 0.f) { wx[nx] = w; jx[nx] = j; sumx += w; nx++; }
    }
    const float* ip = in + (size_t)bc*P;
    float acc = 0.f;
    for (int a = 0; a < ny; a++)
        for (int bx = 0; bx < nx; bx++)
            acc += wy[a]*wx[bx]*ip[jy[a]*H + jx[bx]];
    out[idx] = acc / (sumy*sumx);
}

// ---------------- query patches XP[b][k][p] -> bf16 hi/lo planes ----------------
__global__ void xp_kernel(const float* __restrict__ mb,
                          __nv_bfloat16* __restrict__ XPh, __nv_bfloat16* __restrict__ XPl) {
    size_t total = (size_t)BB*K9*P;
    size_t idx = (size_t)blockIdx.x*blockDim.x + threadIdx.x;
    if (idx >= total) return;
    int p = idx % P; int k = (idx / P) % K9; int b = idx / ((size_t)P*K9);
    int c = k/9, r = k%9; int ky = r/3, kx = r%3;
    int y = p/H + ky - 1, x = p%H + kx - 1;
    float v = 0.f;
    if ((unsigned)y < H && (unsigned)x < H) v = mb[((size_t)b*CHALF + c)*P + y*H + x];
    __nv_bfloat16 hh, ll; split2(v, hh, ll);
    XPh[idx] = hh; XPl[idx] = ll;
}

__device__ __forceinline__ void decode_l(int l, int& Hs, int& loff) {
    if (l < 4096)      { Hs = 64; loff = 0; }
    else if (l < 7345) { Hs = 57; loff = 4096; }
    else if (l < 9946) { Hs = 51; loff = 7345; }
    else               { Hs = 44; loff = 9946; }
}

// ---------------- normalized key patches WN[b][l][k] -> bf16 hi/lo ----------------
__global__ void wn_kernel(const float* __restrict__ refm,
                          __nv_bfloat16* __restrict__ WNh, __nv_bfloat16* __restrict__ WNl) {
    int l = blockIdx.x, b = blockIdx.y;
    int tid = threadIdx.x;
    int Hs, loff; decode_l(l, Hs, loff);
    int Ls = Hs*Hs; int ll = l - loff; int lh = ll/Hs, lw = ll%Hs;
    const float* rp = refm + (size_t)BB*CHALF*loff + (size_t)b*CHALF*Ls;
    __shared__ float vals[K9];
    __shared__ float red[128];
    float ss = 0.f;
    for (int k = tid; k < K9; k += 128) {
        int c = k/9, r = k%9; int ky = r/3, kx = r%3;
        int y = lh + ky - 1, x = lw + kx - 1;
        float v = 0.f;
        if ((unsigned)y < (unsigned)Hs && (unsigned)x < (unsigned)Hs) v = rp[(size_t)c*Ls + y*Hs + x];
        vals[k] = v; ss += v*v;
    }
    red[tid] = ss; __syncthreads();
    for (int o = 64; o > 0; o >>= 1) { if (tid < o) red[tid] += red[tid+o]; __syncthreads(); }
    float rn = 1.0f / fmaxf(sqrtf(red[0]), 1e-4f);
    size_t base = ((size_t)b*LT + l)*K9;
    for (int k = tid; k < K9; k += 128) {
        __nv_bfloat16 hh, lo; split2(vals[k]*rn, hh, lo);
        WNh[base + k] = hh; WNl[base + k] = lo;
    }
}

// ---------------- assembly patches, transposed+padded: RWt[b][j][LTP] bf16 hi/lo ----------------
__global__ void rwt_kernel(const float* __restrict__ base,
                           __nv_bfloat16* __restrict__ RWth, __nv_bfloat16* __restrict__ RWtl) {
    int l = blockIdx.x*blockDim.x + threadIdx.x;
    if (l >= LTP) return;
    int j = blockIdx.y, b = blockIdx.z;
    float v = 0.f;
    if (l < LT) {
        int c = j/9, r = j%9; int ky = r/3, kx = r%3;
        int Hs, loff; decode_l(l, Hs, loff);
        int Ls = Hs*Hs; int ll = l - loff; int lh = ll/Hs, lw = ll%Hs;
        int y = lh + ky - 1, x = lw + kx - 1;
        if ((unsigned)y < (unsigned)Hs && (unsigned)x < (unsigned)Hs)
            v = base[(size_t)BB*COUT*loff + ((size_t)b*COUT + c)*Ls + y*Hs + x];
    }
    __nv_bfloat16 hh, lo; split2(v, hh, lo);
    size_t o = ((size_t)b*K18 + j)*LTP + l;
    RWth[o] = hh; RWtl[o] = lo;
}

// ---------------- bf16-split tensor-core GEMM: C = (Ah+Al)x(Bh+Bl), 128x128 tile ----------------
#define APLANE 10240          // 128 rows * 80B
#define BPLANE 8704           // 32 rows * 272B
#define STAGE_BYTES (2*APLANE + 2*BPLANE)   // 37888

#define LDSM4(R, addr) asm volatile( \
    "ldmatrix.sync.aligned.m8n8.x4.shared.b16 {%0,%1,%2,%3},[%4];" \
    : "=r"((R)[0]),"=r"((R)[1]),"=r"((R)[2]),"=r"((R)[3]) : "r"(addr))
#define LDSM4T(R, addr) asm volatile( \
    "ldmatrix.sync.aligned.m8n8.x4.trans.shared.b16 {%0,%1,%2,%3},[%4];" \
    : "=r"((R)[0]),"=r"((R)[1]),"=r"((R)[2]),"=r"((R)[3]) : "r"(addr))
#define MMA16816(d, a, b0, b1) asm volatile( \
    "mma.sync.aligned.m16n8k16.row.col.f32.bf16.bf16.f32 " \
    "{%0,%1,%2,%3},{%4,%5,%6,%7},{%8,%9},{%0,%1,%2,%3};" \
    : "+f"((d)[0]),"+f"((d)[1]),"+f"((d)[2]),"+f"((d)[3]) \
    : "r"((a)[0]),"r"((a)[1]),"r"((a)[2]),"r"((a)[3]),"r"(b0),"r"(b1))
#define CPASYNC(dst, src, sz) asm volatile( \
    "cp.async.cg.shared.global [%0],[%1],16,%2;" :: "r"(dst),"l"(src),"r"(sz))

__global__ __launch_bounds__(256, 1) void gemm3_kernel(
    const __nv_bfloat16* __restrict__ Ah, const __nv_bfloat16* __restrict__ Al,
    const __nv_bfloat16* __restrict__ Bh, const __nv_bfloat16* __restrict__ Bl,
    float* __restrict__ C, int M, int K, int lda, int ldb,
    size_t sA, size_t sB, size_t sC)
{
    extern __shared__ char smem[];
    int b = blockIdx.z;
    const __nv_bfloat16* pAh = Ah + (size_t)b*sA;
    const __nv_bfloat16* pAl = Al + (size_t)b*sA;
    const __nv_bfloat16* pBh = Bh + (size_t)b*sB;
    const __nv_bfloat16* pBl = Bl + (size_t)b*sB;
    float* pC = C + (size_t)b*sC;
    int row0 = blockIdx.y*128, col0 = blockIdx.x*128;
    int tid = threadIdx.x, lane = tid & 31, wid = tid >> 5;
    int wm = (wid >> 2)*64, wn = (wid & 3)*32;
    uint32_t sb = (uint32_t)__cvta_generic_to_shared(smem);

    float acc[4][4][4];
    #pragma unroll
    for (int i = 0; i < 4; i++)
        #pragma unroll
        for (int j = 0; j < 4; j++)
            #pragma unroll
            for (int r = 0; r < 4; r++) acc[i][j][r] = 0.f;

    const int KIT = K >> 5;

    auto issue = [&](int it) {
        uint32_t st = sb + (uint32_t)(it & 1)*STAGE_BYTES;
        int k0 = it << 5;
        #pragma unroll
        for (int q = 0; q < 2; q++) {
            int v = tid + q*256;
            // A planes: 512 chunks of 16B each: row = v/4, kvec = v%4
            int r = v >> 2, kv = v & 3;
            int gr = row0 + r;
            int ok = (gr < M) ? 16 : 0;
            int grc = gr < M ? gr : (M-1);
            const __nv_bfloat16* ga = pAh + (size_t)grc*lda + k0 + kv*8;
            uint32_t da = st + (uint32_t)(r*80 + kv*16);
            CPASYNC(da, ga, ok);
            const __nv_bfloat16* ga2 = pAl + (size_t)grc*lda + k0 + kv*8;
            CPASYNC(da + APLANE, ga2, ok);
            // B planes: 512 chunks: krow = v/16, nvec = v%16
            int kr = v >> 4, nv = v & 15;
            const __nv_bfloat16* gb = pBh + (size_t)(k0 + kr)*ldb + col0 + nv*8;
            uint32_t db = st + 2*APLANE + (uint32_t)(kr*272 + nv*16);
            CPASYNC(db, gb, 16);
            const __nv_bfloat16* gb2 = pBl + (size_t)(k0 + kr)*ldb + col0 + nv*8;
            CPASYNC(db + BPLANE, gb2, 16);
        }
    };

    issue(0);
    asm volatile("cp.async.commit_group;");

    for (int it = 0; it < KIT; it++) {
        if (it + 1 < KIT) {
            issue(it + 1);
            asm volatile("cp.async.commit_group;");
            asm volatile("cp.async.wait_group 1;");
        } else {
            asm volatile("cp.async.wait_group 0;");
        }
        __syncthreads();
        uint32_t st = sb + (uint32_t)(it & 1)*STAGE_BYTES;
        #pragma unroll
        for (int ks = 0; ks < 2; ks++) {
            int koff = ks*16;
            uint32_t ah[4][4], alr[4][4];
            #pragma unroll
            for (int i = 0; i < 4; i++) {
                uint32_t addr = st + (uint32_t)((wm + i*16 + (lane & 15))*80
                                  + (koff + ((lane >> 4) << 3))*2);
                LDSM4(ah[i], addr);
                LDSM4(alr[i], addr + APLANE);
            }
            uint32_t bh[2][4], blr[2][4];
            #pragma unroll
            for (int hh = 0; hh < 2; hh++) {
                uint32_t addr = st + 2*APLANE
                    + (uint32_t)((koff + hh*8 + (lane & 7))*272 + (wn + ((lane >> 3) << 3))*2);
                LDSM4T(bh[hh], addr);
                LDSM4T(blr[hh], addr + BPLANE);
            }
            #pragma unroll
            for (int i = 0; i < 4; i++)
                #pragma unroll
                for (int j = 0; j < 4; j++) {
                    MMA16816(acc[i][j], ah[i], bh[0][j], bh[1][j]);   // hi*hi
                    MMA16816(acc[i][j], ah[i], blr[0][j], blr[1][j]); // hi*lo
                    MMA16816(acc[i][j], alr[i], bh[0][j], bh[1][j]);  // lo*hi
                }
        }
        __syncthreads();
    }

    #pragma unroll
    for (int i = 0; i < 4; i++) {
        int r = row0 + wm + i*16 + (lane >> 2);
        #pragma unroll
        for (int j = 0; j < 4; j++) {
            int c = col0 + wn + j*8 + ((lane & 3) << 1);
            if (r < M) *(float2*)&pC[(size_t)r*4096 + c] = make_float2(acc[i][j][0], acc[i][j][1]);
            if (r + 8 < M) *(float2*)&pC[(size_t)(r+8)*4096 + c] = make_float2(acc[i][j][2], acc[i][j][3]);
        }
    }
}

// ---------------- softmax over l: 3 coalesced passes ----------------
__global__ void softmax_part_kernel(const float* __restrict__ scores,
                                    float* __restrict__ pmax, float* __restrict__ psum) {
    int p = blockIdx.x*256 + threadIdx.x;
    int c = blockIdx.y, b = blockIdx.z;
    int l0 = c*SCH, l1 = l0 + SCH; if (l1 > LT) l1 = LT;
    const float* s = scores + (size_t)b*LT*P + p;
    float m = -1e30f;
    for (int l = l0; l < l1; l++) m = fmaxf(m, s[(size_t)l*P]);
    float sum = 0.f;
    for (int l = l0; l < l1; l++) sum += expf(10.f*(s[(size_t)l*P] - m));
    pmax[((size_t)b*NCH + c)*P + p] = m;
    psum[((size_t)b*NCH + c)*P + p] = sum;
}

__global__ void softmax_comb_kernel(const float* __restrict__ pmax, const float* __restrict__ psum,
                                    float* __restrict__ gm, float* __restrict__ gi) {
    int p = blockIdx.x*256 + threadIdx.x; int b = blockIdx.y;
    float M = -1e30f;
    for (int c = 0; c < NCH; c++) M = fmaxf(M, pmax[((size_t)b*NCH + c)*P + p]);
    float S = 0.f;
    for (int c = 0; c < NCH; c++)
        S += psum[((size_t)b*NCH + c)*P + p] * expf(10.f*(pmax[((size_t)b*NCH + c)*P + p] - M));
    gm[b*P + p] = M;
    gi[b*P + p] = 1.0f / S;
}

__global__ void softmax_norm_kernel(const float* __restrict__ scores,
                                    const float* __restrict__ gm, const float* __restrict__ gi,
                                    __nv_bfloat16* __restrict__ ah, __nv_bfloat16* __restrict__ al) {
    size_t idx = (size_t)blockIdx.x*256 + threadIdx.x;
    const size_t total = (size_t)BB*LTP*P;
    if (idx >= total) return;
    int p = idx % P; int l = (idx / P) % LTP; int b = idx / ((size_t)P*LTP);
    float v = 0.f;
    if (l < LT)
        v = expf(10.f*(scores[((size_t)b*LT + l)*P + p] - gm[b*P + p])) * gi[b*P + p];
    __nv_bfloat16 hh, lo; split2(v, hh, lo);
    ah[idx] = hh; al[idx] = lo;
}

// ---------------- col2im gather for conv_transpose + residual ----------------
__global__ void col2im_kernel(const float* __restrict__ T, const float* __restrict__ h2,
                              float* __restrict__ out) {
    int idx = blockIdx.x*blockDim.x + threadIdx.x;
    const int total = BB*COUT*P;
    if (idx >= total) return;
    int w = idx % H; int hh = (idx / H) % H; int c = (idx / P) % COUT; int b = idx / (P*COUT);
    float acc = 0.f;
    #pragma unroll
    for (int a = 0; a < 3; a++) {
        int y = hh + 1 - a;
        if ((unsigned)y >= H) continue;
        #pragma unroll
        for (int d = 0; d < 3; d++) {
            int x = w + 1 - d;
            if ((unsigned)x >= H) continue;
            acc += T[((size_t)b*K18 + c*9 + a*3 + d)*P + y*H + x];
        }
    }
    out[idx] = h2[idx] + 0.25f*acc;
}

// ---------------- launch ----------------
extern "C" void kernel_launch(void* const* d_in, const int* in_sizes, int n_in,
                              void* d_out, int out_size) {
    (void)in_sizes; (void)n_in; (void)out_size;
    const float* x      = (const float*)d_in[0];
    const float* bb0_w  = (const float*)d_in[1];
    const float* bb0_b  = (const float*)d_in[2];
    const float* bb0_a  = (const float*)d_in[3];
    const float* rb1_w1 = (const float*)d_in[4];
    const float* rb1_b1 = (const float*)d_in[5];
    const float* rb1_w2 = (const float*)d_in[6];
    const float* rb1_b2 = (const float*)d_in[7];
    const float* pamb_w = (const float*)d_in[8];
    const float* pamb_b = (const float*)d_in[9];
    const float* pamb_a = (const float*)d_in[10];
    const float* pam_w  = (const float*)d_in[11];
    const float* pam_b  = (const float*)d_in[12];
    const float* pam_a  = (const float*)d_in[13];
    const float* paa_w  = (const float*)d_in[14];
    const float* paa_b  = (const float*)d_in[15];
    const float* paa_a  = (const float*)d_in[16];
    const float* rb2_w1 = (const float*)d_in[17];
    const float* rb2_b1 = (const float*)d_in[18];
    const float* rb2_w2 = (const float*)d_in[19];
    const float* rb2_b2 = (const float*)d_in[20];
    float* out = (float*)d_out;

    float *h0,*h1,*h2,*tmp,*h3,*mb,*ref,*base,*refm,*scores,*T;
    float *pmax,*psum,*gmax,*ginv;
    __nv_bfloat16 *XPh,*XPl,*WNh,*WNl,*RWth,*RWtl,*atth,*attl;
    cudaGetSymbolAddress((void**)&h0, g_h0);
    cudaGetSymbolAddress((void**)&h1, g_h1);
    cudaGetSymbolAddress((void**)&h2, g_h2);
    cudaGetSymbolAddress((void**)&tmp, g_tmp);
    cudaGetSymbolAddress((void**)&h3, g_h3);
    cudaGetSymbolAddress((void**)&mb, g_mb);
    cudaGetSymbolAddress((void**)&ref, g_ref);
    cudaGetSymbolAddress((void**)&base, g_base);
    cudaGetSymbolAddress((void**)&refm, g_refm);
    cudaGetSymbolAddress((void**)&scores, g_scores);
    cudaGetSymbolAddress((void**)&T, g_T);
    cudaGetSymbolAddress((void**)&XPh, g_XPh);
    cudaGetSymbolAddress((void**)&XPl, g_XPl);
    cudaGetSymbolAddress((void**)&WNh, g_WNh);
    cudaGetSymbolAddress((void**)&WNl, g_WNl);
    cudaGetSymbolAddress((void**)&RWth, g_RWth);
    cudaGetSymbolAddress((void**)&RWtl, g_RWtl);
    cudaGetSymbolAddress((void**)&atth, g_atth);
    cudaGetSymbolAddress((void**)&attl, g_attl);
    cudaGetSymbolAddress((void**)&pmax, g_pmax);
    cudaGetSymbolAddress((void**)&psum, g_psum);
    cudaGetSymbolAddress((void**)&gmax, g_gmax);
    cudaGetSymbolAddress((void**)&ginv, g_ginv);

    cudaFuncSetAttribute(gemm3_kernel, cudaFuncAttributeMaxDynamicSharedMemorySize, 2*STAGE_BYTES);

    dim3 cb(16,16);
    dim3 cg(4,4,BB*COUT/2);

    // pool + head
    maxpool_kernel<<<(BB*CIN*P + 255)/256, 256>>>(x, h0);
    conv3_kernel<<<cg, cb>>>(h0, bb0_w, bb0_b, nullptr, h1, CIN, COUT, 2, bb0_a);
    // resblock 1
    conv3_kernel<<<cg, cb>>>(h1, rb1_w1, rb1_b1, nullptr, tmp, COUT, COUT, 1, nullptr);
    conv3_kernel<<<cg, cb>>>(tmp, rb1_w2, rb1_b2, h1, h2, COUT, COUT, 0, nullptr);

    // pyramid attention producers
    conv1_kernel<<<dim3(P/256, CHALF, BB), 256>>>(h2, pamb_w, pamb_b, pamb_a, mb, COUT, CHALF, P);
    xp_kernel<<<(int)(((size_t)BB*K9*P + 255)/256), 256>>>(mb, XPh, XPl);

    const int Hs[4]   = {64, 57, 51, 44};
    const int loff[4] = {0, 4096, 7345, 9946};
    for (int s = 0; s < 4; s++) {
        int Ls = Hs[s]*Hs[s];
        const float* refp;
        if (s == 0) refp = h2;
        else {
            int n = BB*COUT*Ls;
            resize_kernel<<<(n + 255)/256, 256>>>(h2, ref, Hs[s]);
            refp = ref;
        }
        conv1_kernel<<<dim3((Ls + 255)/256, COUT, BB), 256>>>(
            refp, paa_w, paa_b, paa_a, base + (size_t)BB*COUT*loff[s], COUT, COUT, Ls);
        conv1_kernel<<<dim3((Ls + 255)/256, CHALF, BB), 256>>>(
            refp, pam_w, pam_b, pam_a, refm + (size_t)BB*CHALF*loff[s], COUT, CHALF, Ls);
    }

    wn_kernel<<<dim3(LT, BB), 128>>>(refm, WNh, WNl);
    rwt_kernel<<<dim3((LTP + 255)/256, K18, BB), 256>>>(base, RWth, RWtl);

    // scores = WN x XP   [LT,576]x[576,4096]
    gemm3_kernel<<<dim3(P/128, (LT + 127)/128, BB), 256, 2*STAGE_BYTES>>>(
        WNh, WNl, XPh, XPl, scores, LT, K9, K9, P,
        (size_t)LT*K9, (size_t)K9*P, (size_t)LT*P);

    // softmax over l -> att bf16 hi/lo (padded rows zeroed)
    softmax_part_kernel<<<dim3(P/256, NCH, BB), 256>>>(scores, pmax, psum);
    softmax_comb_kernel<<<dim3(P/256, BB), 256>>>(pmax, psum, gmax, ginv);
    softmax_norm_kernel<<<(int)(((size_t)BB*LTP*P + 255)/256), 256>>>(scores, gmax, ginv, atth, attl);

    // T = RWt x att    [1152,LTP]x[LTP,4096]
    gemm3_kernel<<<dim3(P/128, K18/128, BB), 256, 2*STAGE_BYTES>>>(
        RWth, RWtl, atth, attl, T, K18, LTP, LTP, P,
        (size_t)K18*LTP, (size_t)LTP*P, (size_t)K18*P);

    col2im_kernel<<<(BB*COUT*P + 255)/256, 256>>>(T, h2, h3);

    // resblock 2 -> output
    conv3_kernel<<<cg, cb>>>(h3, rb2_w1, rb2_b1, nullptr, tmp, COUT, COUT, 1, nullptr);
    conv3_kernel<<<cg, cb>>>(tmp, rb2_w2, rb2_b2, h3, out, COUT, COUT, 0, nullptr);
}

// round 3
// speedup vs baseline: 2.7306x; 1.0670x over previous
#include <cuda_runtime.h>
#include <cuda_bf16.h>
#include <cstdint>

// ---------------- dims ----------------
#define BB 2
#define CIN 64
#define COUT 128
#define CHALF 64
#define HIN 128
#define H 64
#define P (H*H)          // 4096
#define LT 11882         // 64^2 + 57^2 + 51^2 + 44^2
#define LTP 11904        // LT padded to multiple of 32
#define K9 576           // CHALF*9
#define K18 1152         // COUT*9
#define NCH 32
#define SCH 372          // ceil(LT/NCH)

// ---------------- scratch (device globals; allocation-free) ----------------
__device__ __align__(128) float g_h0[BB*CIN*P];
__device__ __align__(128) float g_h1[BB*COUT*P];
__device__ __align__(128) float g_h2[BB*COUT*P];
__device__ __align__(128) float g_tmp[BB*COUT*P];
__device__ __align__(128) float g_h3[BB*COUT*P];
__device__ __align__(128) float g_mb[BB*CHALF*P];
__device__ __align__(128) float g_ref[BB*COUT*3249];
__device__ __align__(128) float g_base[(size_t)BB*COUT*LT];
__device__ __align__(128) float g_refm[(size_t)BB*CHALF*LT];
__device__ __align__(128) float g_scores[(size_t)BB*LT*P];
__device__ __align__(128) float g_T[(size_t)BB*K18*P];
__device__ __align__(128) __nv_bfloat16 g_XPh[(size_t)BB*K9*P];
__device__ __align__(128) __nv_bfloat16 g_XPl[(size_t)BB*K9*P];
__device__ __align__(128) __nv_bfloat16 g_WNh[(size_t)BB*LT*K9];
__device__ __align__(128) __nv_bfloat16 g_WNl[(size_t)BB*LT*K9];
__device__ __align__(128) __nv_bfloat16 g_RWth[(size_t)BB*K18*LTP];
__device__ __align__(128) __nv_bfloat16 g_RWtl[(size_t)BB*K18*LTP];
__device__ __align__(128) __nv_bfloat16 g_atth[(size_t)BB*LTP*P];
__device__ __align__(128) __nv_bfloat16 g_attl[(size_t)BB*LTP*P];
__device__ __align__(128) float g_pmax[BB*NCH*P];
__device__ __align__(128) float g_psum[BB*NCH*P];

__device__ __forceinline__ void split2(float v, __nv_bfloat16& h, __nv_bfloat16& l) {
    h = __float2bfloat16(v);
    l = __float2bfloat16(v - __bfloat162float(h));
}

// ---------------- maxpool 2x2 ----------------
__global__ void maxpool_kernel(const float* __restrict__ in, float* __restrict__ out) {
    int idx = blockIdx.x*blockDim.x + threadIdx.x;
    const int total = BB*CIN*P;
    if (idx >= total) return;
    int x = idx % H; int y = (idx / H) % H; int bc = idx / P;
    const float* p = in + ((size_t)bc*HIN + 2*y)*HIN + 2*x;
    out[idx] = fmaxf(fmaxf(p[0], p[1]), fmaxf(p[HIN], p[HIN+1]));
}

// ---------------- 3x3 conv (pad 1), 4 output channels per block ----------------
__global__ void conv3_kernel(const float* __restrict__ in, const float* __restrict__ w,
                             const float* __restrict__ bias, const float* __restrict__ res,
                             float* __restrict__ out, int Ci, int Co,
                             int act, const float* __restrict__ alpha_p) {
    int bx = blockIdx.x*16, by = blockIdx.y*16;
    int cop = blockIdx.z % (Co >> 2), b = blockIdx.z / (Co >> 2);
    int co0 = cop*4;
    int tx = threadIdx.x, ty = threadIdx.y;
    int tid = ty*16 + tx;
    __shared__ float tile[8][18][18];
    __shared__ float wsh[8][4][9];
    float acc[4];
    #pragma unroll
    for (int o = 0; o < 4; o++) acc[o] = bias[co0 + o];
    for (int c0 = 0; c0 < Ci; c0 += 8) {
        for (int idx = tid; idx < 8*18*18; idx += 256) {
            int c = idx / 324; int r = idx % 324; int yy = r/18, xx = r%18;
            int gy = by + yy - 1, gx = bx + xx - 1;
            float v = 0.f;
            if (gy >= 0 && gy < H && gx >= 0 && gx < H)
                v = in[(((size_t)b*Ci + c0 + c)*H + gy)*H + gx];
            tile[c][yy][xx] = v;
        }
        for (int idx = tid; idx < 288; idx += 256) {
            int c = idx/36, rr = idx%36, o = rr/9, k = rr%9;
            wsh[c][o][k] = w[((size_t)(co0+o)*Ci + c0 + c)*9 + k];
        }
        __syncthreads();
        #pragma unroll
        for (int c = 0; c < 8; c++)
            #pragma unroll
            for (int ky = 0; ky < 3; ky++)
                #pragma unroll
                for (int kx = 0; kx < 3; kx++) {
                    float t = tile[c][ty+ky][tx+kx];
                    #pragma unroll
                    for (int o = 0; o < 4; o++)
                        acc[o] += t * wsh[c][o][ky*3+kx];
                }
        __syncthreads();
    }
    float a = (act == 2) ? *alpha_p : 0.f;
    #pragma unroll
    for (int o = 0; o < 4; o++) {
        float v = acc[o];
        if (act == 1) v = fmaxf(v, 0.f);
        else if (act == 2) v = v >= 0.f ? v : a*v;
        size_t ofs = (((size_t)b*Co + co0 + o)*H + (by+ty))*H + (bx+tx);
        if (res) v += res[ofs];
        out[ofs] = v;
    }
}

// ---------------- 1x1 conv + PReLU ----------------
__global__ void conv1_kernel(const float* __restrict__ in, const float* __restrict__ w,
                             const float* __restrict__ bias, const float* __restrict__ alpha_p,
                             float* __restrict__ out, int Ci, int Co, int Pn) {
    int p = blockIdx.x*256 + threadIdx.x;
    int o = blockIdx.y, b = blockIdx.z;
    if (p >= Pn) return;
    const float* ip = in + (size_t)b*Ci*Pn + p;
    const float* wp = w + (size_t)o*Ci;
    float acc = bias[o];
    #pragma unroll 8
    for (int i = 0; i < Ci; i++) acc += wp[i] * ip[(size_t)i*Pn];
    float a = *alpha_p;
    out[((size_t)b*Co + o)*Pn + p] = acc >= 0.f ? acc : a*acc;
}

// ---------------- bilinear resize with antialias (jax.image.resize semantics) ----------------
__global__ void resize_kernel(const float* __restrict__ in, float* __restrict__ out, int Hout) {
    int total = BB*COUT*Hout*Hout;
    int idx = blockIdx.x*blockDim.x + threadIdx.x;
    if (idx >= total) return;
    int xo = idx % Hout; int yo = (idx / Hout) % Hout; int bc = idx / (Hout*Hout);
    float scale = (float)Hout / (float)H;
    float inv = 1.0f / scale;
    float sy = (yo + 0.5f)*inv - 0.5f;
    float sx = (xo + 0.5f)*inv - 0.5f;
    float wy[4], wx[4]; int jy[4], jx[4];
    int ny = 0, nx = 0; float sumy = 0.f, sumx = 0.f;
    int lo = (int)ceilf(sy - inv), hi = (int)floorf(sy + inv);
    if (lo < 0) lo = 0; if (hi > H-1) hi = H-1;
    for (int j = lo; j <= hi && ny < 4; j++) {
        float w = 1.0f - fabsf(sy - (float)j)/inv;
        if (w > 0.f) { wy[ny] = w; jy[ny] = j; sumy += w; ny++; }
    }
    lo = (int)ceilf(sx - inv); hi = (int)floorf(sx + inv);
    if (lo < 0) lo = 0; if (hi > H-1) hi = H-1;
    for (int j = lo; j <= hi && nx < 4; j++) {
        float w = 1.0f - fabsf(sx - (float)j)/inv;
        if (w > 0.f) { wx[nx] = w; jx[nx] = j; sumx += w; nx++; }
    }
    const float* ip = in + (size_t)bc*P;
    float acc = 0.f;
    for (int a = 0; a < ny; a++)
        for (int bx = 0; bx < nx; bx++)
            acc += wy[a]*wx[bx]*ip[jy[a]*H + jx[bx]];
    out[idx] = acc / (sumy*sumx);
}

// ---------------- query patches XP[b][k][p] -> bf16 hi/lo planes ----------------
__global__ void xp_kernel(const float* __restrict__ mb,
                          __nv_bfloat16* __restrict__ XPh, __nv_bfloat16* __restrict__ XPl) {
    size_t total = (size_t)BB*K9*P;
    size_t idx = (size_t)blockIdx.x*blockDim.x + threadIdx.x;
    if (idx >= total) return;
    int p = idx % P; int k = (idx / P) % K9; int b = idx / ((size_t)P*K9);
    int c = k/9, r = k%9; int ky = r/3, kx = r%3;
    int y = p/H + ky - 1, x = p%H + kx - 1;
    float v = 0.f;
    if ((unsigned)y < H && (unsigned)x < H) v = mb[((size_t)b*CHALF + c)*P + y*H + x];
    __nv_bfloat16 hh, ll; split2(v, hh, ll);
    XPh[idx] = hh; XPl[idx] = ll;
}

__device__ __forceinline__ void decode_l(int l, int& Hs, int& loff) {
    if (l < 4096)      { Hs = 64; loff = 0; }
    else if (l < 7345) { Hs = 57; loff = 4096; }
    else if (l < 9946) { Hs = 51; loff = 7345; }
    else               { Hs = 44; loff = 9946; }
}

// ---------------- normalized key patches WN[b][l][k] -> bf16 hi/lo ----------------
__global__ void wn_kernel(const float* __restrict__ refm,
                          __nv_bfloat16* __restrict__ WNh, __nv_bfloat16* __restrict__ WNl) {
    int l = blockIdx.x, b = blockIdx.y;
    int tid = threadIdx.x;
    int Hs, loff; decode_l(l, Hs, loff);
    int Ls = Hs*Hs; int ll = l - loff; int lh = ll/Hs, lw = ll%Hs;
    const float* rp = refm + (size_t)BB*CHALF*loff + (size_t)b*CHALF*Ls;
    __shared__ float vals[K9];
    __shared__ float red[128];
    float ss = 0.f;
    for (int k = tid; k < K9; k += 128) {
        int c = k/9, r = k%9; int ky = r/3, kx = r%3;
        int y = lh + ky - 1, x = lw + kx - 1;
        float v = 0.f;
        if ((unsigned)y < (unsigned)Hs && (unsigned)x < (unsigned)Hs) v = rp[(size_t)c*Ls + y*Hs + x];
        vals[k] = v; ss += v*v;
    }
    red[tid] = ss; __syncthreads();
    for (int o = 64; o > 0; o >>= 1) { if (tid < o) red[tid] += red[tid+o]; __syncthreads(); }
    float rn = 1.0f / fmaxf(sqrtf(red[0]), 1e-4f);
    size_t base = ((size_t)b*LT + l)*K9;
    for (int k = tid; k < K9; k += 128) {
        __nv_bfloat16 hh, lo; split2(vals[k]*rn, hh, lo);
        WNh[base + k] = hh; WNl[base + k] = lo;
    }
}

// ---------------- assembly patches, transposed+padded: RWt[b][j][LTP] bf16 hi/lo ----------------
__global__ void rwt_kernel(const float* __restrict__ base,
                           __nv_bfloat16* __restrict__ RWth, __nv_bfloat16* __restrict__ RWtl) {
    int l = blockIdx.x*blockDim.x + threadIdx.x;
    if (l >= LTP) return;
    int j = blockIdx.y, b = blockIdx.z;
    float v = 0.f;
    if (l < LT) {
        int c = j/9, r = j%9; int ky = r/3, kx = r%3;
        int Hs, loff; decode_l(l, Hs, loff);
        int Ls = Hs*Hs; int ll = l - loff; int lh = ll/Hs, lw = ll%Hs;
        int y = lh + ky - 1, x = lw + kx - 1;
        if ((unsigned)y < (unsigned)Hs && (unsigned)x < (unsigned)Hs)
            v = base[(size_t)BB*COUT*loff + ((size_t)b*COUT + c)*Ls + y*Hs + x];
    }
    __nv_bfloat16 hh, lo; split2(v, hh, lo);
    size_t o = ((size_t)b*K18 + j)*LTP + l;
    RWth[o] = hh; RWtl[o] = lo;
}

// ---------------- bf16-split tensor-core GEMM: C = (Ah+Al)x(Bh+Bl), 128x128 tile ----------------
#define APLANE 10240          // 128 rows * 80B
#define BPLANE 8704           // 32 rows * 272B
#define STAGE_BYTES (2*APLANE + 2*BPLANE)   // 37888

#define LDSM4(R, addr) asm volatile( \
    "ldmatrix.sync.aligned.m8n8.x4.shared.b16 {%0,%1,%2,%3},[%4];" \
    : "=r"((R)[0]),"=r"((R)[1]),"=r"((R)[2]),"=r"((R)[3]) : "r"(addr))
#define LDSM4T(R, addr) asm volatile( \
    "ldmatrix.sync.aligned.m8n8.x4.trans.shared.b16 {%0,%1,%2,%3},[%4];" \
    : "=r"((R)[0]),"=r"((R)[1]),"=r"((R)[2]),"=r"((R)[3]) : "r"(addr))
#define MMA16816(d, a, b0, b1) asm volatile( \
    "mma.sync.aligned.m16n8k16.row.col.f32.bf16.bf16.f32 " \
    "{%0,%1,%2,%3},{%4,%5,%6,%7},{%8,%9},{%0,%1,%2,%3};" \
    : "+f"((d)[0]),"+f"((d)[1]),"+f"((d)[2]),"+f"((d)[3]) \
    : "r"((a)[0]),"r"((a)[1]),"r"((a)[2]),"r"((a)[3]),"r"(b0),"r"(b1))
#define CPASYNC(dst, src, sz) asm volatile( \
    "cp.async.cg.shared.global [%0],[%1],16,%2;" :: "r"(dst),"l"(src),"r"(sz))

__global__ __launch_bounds__(256, 1) void gemm3_kernel(
    const __nv_bfloat16* __restrict__ Ah, const __nv_bfloat16* __restrict__ Al,
    const __nv_bfloat16* __restrict__ Bh, const __nv_bfloat16* __restrict__ Bl,
    float* __restrict__ C, int M, int K, int lda, int ldb,
    size_t sA, size_t sB, size_t sC)
{
    extern __shared__ char smem[];
    int b = blockIdx.z;
    const __nv_bfloat16* pAh = Ah + (size_t)b*sA;
    const __nv_bfloat16* pAl = Al + (size_t)b*sA;
    const __nv_bfloat16* pBh = Bh + (size_t)b*sB;
    const __nv_bfloat16* pBl = Bl + (size_t)b*sB;
    float* pC = C + (size_t)b*sC;
    int row0 = blockIdx.y*128, col0 = blockIdx.x*128;
    int tid = threadIdx.x, lane = tid & 31, wid = tid >> 5;
    int wm = (wid >> 2)*64, wn = (wid & 3)*32;
    uint32_t sb = (uint32_t)__cvta_generic_to_shared(smem);

    float acc[4][4][4];
    #pragma unroll
    for (int i = 0; i < 4; i++)
        #pragma unroll
        for (int j = 0; j < 4; j++)
            #pragma unroll
            for (int r = 0; r < 4; r++) acc[i][j][r] = 0.f;

    const int KIT = K >> 5;

    auto issue = [&](int it) {
        uint32_t st = sb + (uint32_t)(it & 1)*STAGE_BYTES;
        int k0 = it << 5;
        #pragma unroll
        for (int q = 0; q < 2; q++) {
            int v = tid + q*256;
            int r = v >> 2, kv = v & 3;
            int gr = row0 + r;
            int ok = (gr < M) ? 16 : 0;
            int grc = gr < M ? gr : (M-1);
            const __nv_bfloat16* ga = pAh + (size_t)grc*lda + k0 + kv*8;
            uint32_t da = st + (uint32_t)(r*80 + kv*16);
            CPASYNC(da, ga, ok);
            const __nv_bfloat16* ga2 = pAl + (size_t)grc*lda + k0 + kv*8;
            CPASYNC(da + APLANE, ga2, ok);
            int kr = v >> 4, nv = v & 15;
            const __nv_bfloat16* gb = pBh + (size_t)(k0 + kr)*ldb + col0 + nv*8;
            uint32_t db = st + 2*APLANE + (uint32_t)(kr*272 + nv*16);
            CPASYNC(db, gb, 16);
            const __nv_bfloat16* gb2 = pBl + (size_t)(k0 + kr)*ldb + col0 + nv*8;
            CPASYNC(db + BPLANE, gb2, 16);
        }
    };

    issue(0);
    asm volatile("cp.async.commit_group;");

    for (int it = 0; it < KIT; it++) {
        if (it + 1 < KIT) {
            issue(it + 1);
            asm volatile("cp.async.commit_group;");
            asm volatile("cp.async.wait_group 1;");
        } else {
            asm volatile("cp.async.wait_group 0;");
        }
        __syncthreads();
        uint32_t st = sb + (uint32_t)(it & 1)*STAGE_BYTES;
        #pragma unroll
        for (int ks = 0; ks < 2; ks++) {
            int koff = ks*16;
            uint32_t ah[4][4], alr[4][4];
            #pragma unroll
            for (int i = 0; i < 4; i++) {
                uint32_t addr = st + (uint32_t)((wm + i*16 + (lane & 15))*80
                                  + (koff + ((lane >> 4) << 3))*2);
                LDSM4(ah[i], addr);
                LDSM4(alr[i], addr + APLANE);
            }
            uint32_t bh[2][4], blr[2][4];
            #pragma unroll
            for (int hh = 0; hh < 2; hh++) {
                uint32_t addr = st + 2*APLANE
                    + (uint32_t)((koff + hh*8 + (lane & 7))*272 + (wn + ((lane >> 3) << 3))*2);
                LDSM4T(bh[hh], addr);
                LDSM4T(blr[hh], addr + BPLANE);
            }
            #pragma unroll
            for (int i = 0; i < 4; i++)
                #pragma unroll
                for (int j = 0; j < 4; j++) {
                    MMA16816(acc[i][j], ah[i], bh[0][j], bh[1][j]);   // hi*hi
                    MMA16816(acc[i][j], ah[i], blr[0][j], blr[1][j]); // hi*lo
                    MMA16816(acc[i][j], alr[i], bh[0][j], bh[1][j]);  // lo*hi
                }
        }
        __syncthreads();
    }

    #pragma unroll
    for (int i = 0; i < 4; i++) {
        int r = row0 + wm + i*16 + (lane >> 2);
        #pragma unroll
        for (int j = 0; j < 4; j++) {
            int c = col0 + wn + j*8 + ((lane & 3) << 1);
            if (r < M) *(float2*)&pC[(size_t)r*4096 + c] = make_float2(acc[i][j][0], acc[i][j][1]);
            if (r + 8 < M) *(float2*)&pC[(size_t)(r+8)*4096 + c] = make_float2(acc[i][j][2], acc[i][j][3]);
        }
    }
}

// ---------------- softmax over l: pass 1 stores exp in place ----------------
__global__ void softmax_part_kernel(float* __restrict__ scores,
                                    float* __restrict__ pmax, float* __restrict__ psum) {
    int p = blockIdx.x*256 + threadIdx.x;
    int c = blockIdx.y, b = blockIdx.z;
    int l0 = c*SCH, l1 = l0 + SCH; if (l1 > LT) l1 = LT;
    float* s = scores + (size_t)b*LT*P + p;
    float m = -1e30f;
    for (int l = l0; l < l1; l++) m = fmaxf(m, s[(size_t)l*P]);
    float sum = 0.f;
    for (int l = l0; l < l1; l++) {
        float e = __expf(10.f*(s[(size_t)l*P] - m));
        s[(size_t)l*P] = e;
        sum += e;
    }
    pmax[((size_t)b*NCH + c)*P + p] = m;
    psum[((size_t)b*NCH + c)*P + p] = sum;
}

// pass 2: per-chunk rescale factor into psum
__global__ void softmax_comb_kernel(const float* __restrict__ pmax, float* __restrict__ psum) {
    int p = blockIdx.x*256 + threadIdx.x; int b = blockIdx.y;
    float M = -1e30f;
    for (int c = 0; c < NCH; c++) M = fmaxf(M, pmax[((size_t)b*NCH + c)*P + p]);
    float S = 0.f;
    for (int c = 0; c < NCH; c++)
        S += psum[((size_t)b*NCH + c)*P + p] * __expf(10.f*(pmax[((size_t)b*NCH + c)*P + p] - M));
    float invS = 1.0f / S;
    for (int c = 0; c < NCH; c++)
        psum[((size_t)b*NCH + c)*P + p] =
            __expf(10.f*(pmax[((size_t)b*NCH + c)*P + p] - M)) * invS;
}

// pass 3: pure rescale + bf16 split (no exp)
__global__ void softmax_norm_kernel(const float* __restrict__ scores,
                                    const float* __restrict__ psum,
                                    __nv_bfloat16* __restrict__ ah, __nv_bfloat16* __restrict__ al) {
    size_t idx = (size_t)blockIdx.x*256 + threadIdx.x;
    const size_t total = (size_t)BB*LTP*P;
    if (idx >= total) return;
    int p = idx % P; int l = (idx / P) % LTP; int b = idx / ((size_t)P*LTP);
    float v = 0.f;
    if (l < LT) {
        int c = l / SCH;
        v = scores[((size_t)b*LT + l)*P + p] * psum[((size_t)b*NCH + c)*P + p];
    }
    __nv_bfloat16 hh, lo; split2(v, hh, lo);
    ah[idx] = hh; al[idx] = lo;
}

// ---------------- col2im gather for conv_transpose + residual ----------------
__global__ void col2im_kernel(const float* __restrict__ T, const float* __restrict__ h2,
                              float* __restrict__ out) {
    int idx = blockIdx.x*blockDim.x + threadIdx.x;
    const int total = BB*COUT*P;
    if (idx >= total) return;
    int w = idx % H; int hh = (idx / H) % H; int c = (idx / P) % COUT; int b = idx / (P*COUT);
    float acc = 0.f;
    #pragma unroll
    for (int a = 0; a < 3; a++) {
        int y = hh + 1 - a;
        if ((unsigned)y >= H) continue;
        #pragma unroll
        for (int d = 0; d < 3; d++) {
            int x = w + 1 - d;
            if ((unsigned)x >= H) continue;
            acc += T[((size_t)b*K18 + c*9 + a*3 + d)*P + y*H + x];
        }
    }
    out[idx] = h2[idx] + 0.25f*acc;
}

// ---------------- launch ----------------
extern "C" void kernel_launch(void* const* d_in, const int* in_sizes, int n_in,
                              void* d_out, int out_size) {
    (void)in_sizes; (void)n_in; (void)out_size;
    const float* x      = (const float*)d_in[0];
    const float* bb0_w  = (const float*)d_in[1];
    const float* bb0_b  = (const float*)d_in[2];
    const float* bb0_a  = (const float*)d_in[3];
    const float* rb1_w1 = (const float*)d_in[4];
    const float* rb1_b1 = (const float*)d_in[5];
    const float* rb1_w2 = (const float*)d_in[6];
    const float* rb1_b2 = (const float*)d_in[7];
    const float* pamb_w = (const float*)d_in[8];
    const float* pamb_b = (const float*)d_in[9];
    const float* pamb_a = (const float*)d_in[10];
    const float* pam_w  = (const float*)d_in[11];
    const float* pam_b  = (const float*)d_in[12];
    const float* pam_a  = (const float*)d_in[13];
    const float* paa_w  = (const float*)d_in[14];
    const float* paa_b  = (const float*)d_in[15];
    const float* paa_a  = (const float*)d_in[16];
    const float* rb2_w1 = (const float*)d_in[17];
    const float* rb2_b1 = (const float*)d_in[18];
    const float* rb2_w2 = (const float*)d_in[19];
    const float* rb2_b2 = (const float*)d_in[20];
    float* out = (float*)d_out;

    float *h0,*h1,*h2,*tmp,*h3,*mb,*ref,*base,*refm,*scores,*T;
    float *pmax,*psum;
    __nv_bfloat16 *XPh,*XPl,*WNh,*WNl,*RWth,*RWtl,*atth,*attl;
    cudaGetSymbolAddress((void**)&h0, g_h0);
    cudaGetSymbolAddress((void**)&h1, g_h1);
    cudaGetSymbolAddress((void**)&h2, g_h2);
    cudaGetSymbolAddress((void**)&tmp, g_tmp);
    cudaGetSymbolAddress((void**)&h3, g_h3);
    cudaGetSymbolAddress((void**)&mb, g_mb);
    cudaGetSymbolAddress((void**)&ref, g_ref);
    cudaGetSymbolAddress((void**)&base, g_base);
    cudaGetSymbolAddress((void**)&refm, g_refm);
    cudaGetSymbolAddress((void**)&scores, g_scores);
    cudaGetSymbolAddress((void**)&T, g_T);
    cudaGetSymbolAddress((void**)&XPh, g_XPh);
    cudaGetSymbolAddress((void**)&XPl, g_XPl);
    cudaGetSymbolAddress((void**)&WNh, g_WNh);
    cudaGetSymbolAddress((void**)&WNl, g_WNl);
    cudaGetSymbolAddress((void**)&RWth, g_RWth);
    cudaGetSymbolAddress((void**)&RWtl, g_RWtl);
    cudaGetSymbolAddress((void**)&atth, g_atth);
    cudaGetSymbolAddress((void**)&attl, g_attl);
    cudaGetSymbolAddress((void**)&pmax, g_pmax);
    cudaGetSymbolAddress((void**)&psum, g_psum);

    cudaFuncSetAttribute(gemm3_kernel, cudaFuncAttributeMaxDynamicSharedMemorySize, 2*STAGE_BYTES);

    dim3 cb(16,16);
    dim3 cg(4,4,BB*COUT/4);

    // pool + head
    maxpool_kernel<<<(BB*CIN*P + 255)/256, 256>>>(x, h0);
    conv3_kernel<<<cg, cb>>>(h0, bb0_w, bb0_b, nullptr, h1, CIN, COUT, 2, bb0_a);
    // resblock 1
    conv3_kernel<<<cg, cb>>>(h1, rb1_w1, rb1_b1, nullptr, tmp, COUT, COUT, 1, nullptr);
    conv3_kernel<<<cg, cb>>>(tmp, rb1_w2, rb1_b2, h1, h2, COUT, COUT, 0, nullptr);

    // pyramid attention producers
    conv1_kernel<<<dim3(P/256, CHALF, BB), 256>>>(h2, pamb_w, pamb_b, pamb_a, mb, COUT, CHALF, P);
    xp_kernel<<<(int)(((size_t)BB*K9*P + 255)/256), 256>>>(mb, XPh, XPl);

    const int Hs[4]   = {64, 57, 51, 44};
    const int loff[4] = {0, 4096, 7345, 9946};
    for (int s = 0; s < 4; s++) {
        int Ls = Hs[s]*Hs[s];
        const float* refp;
        if (s == 0) refp = h2;
        else {
            int n = BB*COUT*Ls;
            resize_kernel<<<(n + 255)/256, 256>>>(h2, ref, Hs[s]);
            refp = ref;
        }
        conv1_kernel<<<dim3((Ls + 255)/256, COUT, BB), 256>>>(
            refp, paa_w, paa_b, paa_a, base + (size_t)BB*COUT*loff[s], COUT, COUT, Ls);
        conv1_kernel<<<dim3((Ls + 255)/256, CHALF, BB), 256>>>(
            refp, pam_w, pam_b, pam_a, refm + (size_t)BB*CHALF*loff[s], COUT, CHALF, Ls);
    }

    wn_kernel<<<dim3(LT, BB), 128>>>(refm, WNh, WNl);
    rwt_kernel<<<dim3((LTP + 255)/256, K18, BB), 256>>>(base, RWth, RWtl);

    // scores = WN x XP   [LT,576]x[576,4096]
    gemm3_kernel<<<dim3(P/128, (LT + 127)/128, BB), 256, 2*STAGE_BYTES>>>(
        WNh, WNl, XPh, XPl, scores, LT, K9, K9, P,
        (size_t)LT*K9, (size_t)K9*P, (size_t)LT*P);

    // softmax over l -> att bf16 hi/lo (padded rows zeroed)
    softmax_part_kernel<<<dim3(P/256, NCH, BB), 256>>>(scores, pmax, psum);
    softmax_comb_kernel<<<dim3(P/256, BB), 256>>>(pmax, psum);
    softmax_norm_kernel<<<(int)(((size_t)BB*LTP*P + 255)/256), 256>>>(scores, psum, atth, attl);

    // T = RWt x att    [1152,LTP]x[LTP,4096]
    gemm3_kernel<<<dim3(P/128, K18/128, BB), 256, 2*STAGE_BYTES>>>(
        RWth, RWtl, atth, attl, T, K18, LTP, LTP, P,
        (size_t)K18*LTP, (size_t)LTP*P, (size_t)K18*P);

    col2im_kernel<<<(BB*COUT*P + 255)/256, 256>>>(T, h2, h3);

    // resblock 2 -> output
    conv3_kernel<<<cg, cb>>>(h3, rb2_w1, rb2_b1, nullptr, tmp, COUT, COUT, 1, nullptr);
    conv3_kernel<<<cg, cb>>>(tmp, rb2_w2, rb2_b2, h3, out, COUT, COUT, 0, nullptr);
}

// round 6
// speedup vs baseline: 2.9005x; 1.0622x over previous
#include <cuda_runtime.h>
#include <cuda_bf16.h>
#include <cstdint>

// ---------------- dims ----------------
#define BB 2
#define CIN 64
#define COUT 128
#define CHALF 64
#define HIN 128
#define H 64
#define P (H*H)          // 4096
#define LT 11882
#define LTP 11904        // LT padded to 128 multiple (93*128)
#define K9 576
#define K18 1152
#define NCH 32
#define SCH 372

// ---------------- scratch ----------------
__device__ __align__(128) float g_h0[BB*CIN*P];
__device__ __align__(128) float g_h1[BB*COUT*P];
__device__ __align__(128) float g_h2[BB*COUT*P];
__device__ __align__(128) float g_tmp[BB*COUT*P];
__device__ __align__(128) float g_h3[BB*COUT*P];
__device__ __align__(128) float g_mb[BB*CHALF*P];
__device__ __align__(128) float g_ref[BB*COUT*3249];
__device__ __align__(128) float g_base[(size_t)BB*COUT*LT];
__device__ __align__(128) float g_refm[(size_t)BB*CHALF*LT];
__device__ __align__(128) float g_scores[(size_t)BB*LTP*P];
__device__ __align__(128) float g_T[(size_t)BB*K18*P];
__device__ __align__(128) __nv_bfloat16 g_XPth[(size_t)BB*P*K9];
__device__ __align__(128) __nv_bfloat16 g_XPtl[(size_t)BB*P*K9];
__device__ __align__(128) __nv_bfloat16 g_WNh[(size_t)BB*LTP*K9];
__device__ __align__(128) __nv_bfloat16 g_WNl[(size_t)BB*LTP*K9];
__device__ __align__(128) __nv_bfloat16 g_RWth[(size_t)BB*K18*LTP];
__device__ __align__(128) __nv_bfloat16 g_RWtl[(size_t)BB*K18*LTP];
__device__ __align__(128) __nv_bfloat16 g_attTh[(size_t)BB*P*LTP];
__device__ __align__(128) __nv_bfloat16 g_attTl[(size_t)BB*P*LTP];
__device__ __align__(128) float g_pmax[BB*NCH*P];
__device__ __align__(128) float g_psum[BB*NCH*P];

__device__ __forceinline__ void split2(float v, __nv_bfloat16& h, __nv_bfloat16& l) {
    h = __float2bfloat16(v);
    l = __float2bfloat16(v - __bfloat162float(h));
}

// ---------------- maxpool ----------------
__global__ void maxpool_kernel(const float* __restrict__ in, float* __restrict__ out) {
    int idx = blockIdx.x*blockDim.x + threadIdx.x;
    if (idx >= BB*CIN*P) return;
    int x = idx % H; int y = (idx / H) % H; int bc = idx / P;
    const float* p = in + ((size_t)bc*HIN + 2*y)*HIN + 2*x;
    out[idx] = fmaxf(fmaxf(p[0], p[1]), fmaxf(p[HIN], p[HIN+1]));
}

// ---------------- 3x3 conv, 4 outputs per block ----------------
__global__ void conv3_kernel(const float* __restrict__ in, const float* __restrict__ w,
                             const float* __restrict__ bias, const float* __restrict__ res,
                             float* __restrict__ out, int Ci, int Co,
                             int act, const float* __restrict__ alpha_p) {
    int bx = blockIdx.x*16, by = blockIdx.y*16;
    int cop = blockIdx.z % (Co >> 2), b = blockIdx.z / (Co >> 2);
    int co0 = cop*4;
    int tx = threadIdx.x, ty = threadIdx.y;
    int tid = ty*16 + tx;
    __shared__ float tile[8][18][18];
    __shared__ float wsh[8][4][9];
    float acc[4];
    #pragma unroll
    for (int o = 0; o < 4; o++) acc[o] = bias[co0 + o];
    for (int c0 = 0; c0 < Ci; c0 += 8) {
        for (int idx = tid; idx < 8*18*18; idx += 256) {
            int c = idx / 324; int r = idx % 324; int yy = r/18, xx = r%18;
            int gy = by + yy - 1, gx = bx + xx - 1;
            float v = 0.f;
            if (gy >= 0 && gy < H && gx >= 0 && gx < H)
                v = in[(((size_t)b*Ci + c0 + c)*H + gy)*H + gx];
            tile[c][yy][xx] = v;
        }
        for (int idx = tid; idx < 288; idx += 256) {
            int c = idx/36, rr = idx%36, o = rr/9, k = rr%9;
            wsh[c][o][k] = w[((size_t)(co0+o)*Ci + c0 + c)*9 + k];
        }
        __syncthreads();
        #pragma unroll
        for (int c = 0; c < 8; c++)
            #pragma unroll
            for (int ky = 0; ky < 3; ky++)
                #pragma unroll
                for (int kx = 0; kx < 3; kx++) {
                    float t = tile[c][ty+ky][tx+kx];
                    #pragma unroll
                    for (int o = 0; o < 4; o++)
                        acc[o] += t * wsh[c][o][ky*3+kx];
                }
        __syncthreads();
    }
    float a = (act == 2) ? *alpha_p : 0.f;
    #pragma unroll
    for (int o = 0; o < 4; o++) {
        float v = acc[o];
        if (act == 1) v = fmaxf(v, 0.f);
        else if (act == 2) v = v >= 0.f ? v : a*v;
        size_t ofs = (((size_t)b*Co + co0 + o)*H + (by+ty))*H + (bx+tx);
        if (res) v += res[ofs];
        out[ofs] = v;
    }
}

// ---------------- 1x1 conv + PReLU ----------------
__global__ void conv1_kernel(const float* __restrict__ in, const float* __restrict__ w,
                             const float* __restrict__ bias, const float* __restrict__ alpha_p,
                             float* __restrict__ out, int Ci, int Co, int Pn) {
    int p = blockIdx.x*256 + threadIdx.x;
    int o = blockIdx.y, b = blockIdx.z;
    if (p >= Pn) return;
    const float* ip = in + (size_t)b*Ci*Pn + p;
    const float* wp = w + (size_t)o*Ci;
    float acc = bias[o];
    #pragma unroll 8
    for (int i = 0; i < Ci; i++) acc += wp[i] * ip[(size_t)i*Pn];
    float a = *alpha_p;
    out[((size_t)b*Co + o)*Pn + p] = acc >= 0.f ? acc : a*acc;
}

// ---------------- bilinear resize with antialias ----------------
__global__ void resize_kernel(const float* __restrict__ in, float* __restrict__ out, int Hout) {
    int total = BB*COUT*Hout*Hout;
    int idx = blockIdx.x*blockDim.x + threadIdx.x;
    if (idx >= total) return;
    int xo = idx % Hout; int yo = (idx / Hout) % Hout; int bc = idx / (Hout*Hout);
    float inv = (float)H / (float)Hout;
    float sy = (yo + 0.5f)*inv - 0.5f;
    float sx = (xo + 0.5f)*inv - 0.5f;
    float wy[4], wx[4]; int jy[4], jx[4];
    int ny = 0, nx = 0; float sumy = 0.f, sumx = 0.f;
    int lo = (int)ceilf(sy - inv), hi = (int)floorf(sy + inv);
    if (lo < 0) lo = 0; if (hi > H-1) hi = H-1;
    for (int j = lo; j <= hi && ny < 4; j++) {
        float w = 1.0f - fabsf(sy - (float)j)/inv;
        if (w > 0.f) { wy[ny] = w; jy[ny] = j; sumy += w; ny++; }
    }
    lo = (int)ceilf(sx - inv); hi = (int)floorf(sx + inv);
    if (lo < 0) lo = 0; if (hi > H-1) hi = H-1;
    for (int j = lo; j <= hi && nx < 4; j++) {
        float w = 1.0f - fabsf(sx - (float)j)/inv;
        if (w > 0.f) { wx[nx] = w; jx[nx] = j; sumx += w; nx++; }
    }
    const float* ip = in + (size_t)bc*P;
    float acc = 0.f;
    for (int a = 0; a < ny; a++)
        for (int bx2 = 0; bx2 < nx; bx2++)
            acc += wy[a]*wx[bx2]*ip[jy[a]*H + jx[bx2]];
    out[idx] = acc / (sumy*sumx);
}

// ---------------- query patches, transposed: XPT[b][p][k] ----------------
__global__ void xpT_kernel(const float* __restrict__ mb,
                           __nv_bfloat16* __restrict__ Xh, __nv_bfloat16* __restrict__ Xl) {
    size_t idx = (size_t)blockIdx.x*256 + threadIdx.x;
    if (idx >= (size_t)BB*P*K9) return;
    int k = idx % K9; int p = (idx / K9) % P; int b = idx / ((size_t)K9*P);
    int c = k/9, r = k%9; int ky = r/3, kx = r%3;
    int y = p/H + ky - 1, x = p%H + kx - 1;
    float v = 0.f;
    if ((unsigned)y < H && (unsigned)x < H) v = mb[((size_t)b*CHALF + c)*P + y*H + x];
    __nv_bfloat16 hh, ll; split2(v, hh, ll);
    Xh[idx] = hh; Xl[idx] = ll;
}

__device__ __forceinline__ void decode_l(int l, int& Hs, int& loff) {
    if (l < 4096)      { Hs = 64; loff = 0; }
    else if (l < 7345) { Hs = 57; loff = 4096; }
    else if (l < 9946) { Hs = 51; loff = 7345; }
    else               { Hs = 44; loff = 9946; }
}

// ---------------- normalized key patches WN[b][l][k], rows 0..LTP (pad zero) ----------------
__global__ void wn_kernel(const float* __restrict__ refm,
                          __nv_bfloat16* __restrict__ WNh, __nv_bfloat16* __restrict__ WNl) {
    int l = blockIdx.x, b = blockIdx.y;
    int tid = threadIdx.x;
    size_t obase = ((size_t)b*LTP + l)*K9;
    if (l >= LT) {
        for (int k = tid; k < K9; k += 128) {
            WNh[obase + k] = __float2bfloat16(0.f);
            WNl[obase + k] = __float2bfloat16(0.f);
        }
        return;
    }
    int Hs, loff; decode_l(l, Hs, loff);
    int Ls = Hs*Hs; int ll = l - loff; int lh = ll/Hs, lw = ll%Hs;
    const float* rp = refm + (size_t)BB*CHALF*loff + (size_t)b*CHALF*Ls;
    __shared__ float vals[K9];
    __shared__ float red[128];
    float ss = 0.f;
    for (int k = tid; k < K9; k += 128) {
        int c = k/9, r = k%9; int ky = r/3, kx = r%3;
        int y = lh + ky - 1, x = lw + kx - 1;
        float v = 0.f;
        if ((unsigned)y < (unsigned)Hs && (unsigned)x < (unsigned)Hs) v = rp[(size_t)c*Ls + y*Hs + x];
        vals[k] = v; ss += v*v;
    }
    red[tid] = ss; __syncthreads();
    for (int o = 64; o > 0; o >>= 1) { if (tid < o) red[tid] += red[tid+o]; __syncthreads(); }
    float rn = 1.0f / fmaxf(sqrtf(red[0]), 1e-4f);
    for (int k = tid; k < K9; k += 128) {
        __nv_bfloat16 hh, lo; split2(vals[k]*rn, hh, lo);
        WNh[obase + k] = hh; WNl[obase + k] = lo;
    }
}

// ---------------- assembly patches RWt[b][j][LTP] (pad zero) ----------------
__global__ void rwt_kernel(const float* __restrict__ base,
                           __nv_bfloat16* __restrict__ RWth, __nv_bfloat16* __restrict__ RWtl) {
    int l = blockIdx.x*blockDim.x + threadIdx.x;
    if (l >= LTP) return;
    int j = blockIdx.y, b = blockIdx.z;
    float v = 0.f;
    if (l < LT) {
        int c = j/9, r = j%9; int ky = r/3, kx = r%3;
        int Hs, loff; decode_l(l, Hs, loff);
        int Ls = Hs*Hs; int ll = l - loff; int lh = ll/Hs, lw = ll%Hs;
        int y = lh + ky - 1, x = lw + kx - 1;
        if ((unsigned)y < (unsigned)Hs && (unsigned)x < (unsigned)Hs)
            v = base[(size_t)BB*COUT*loff + ((size_t)b*COUT + c)*Ls + y*Hs + x];
    }
    __nv_bfloat16 hh, lo; split2(v, hh, lo);
    size_t o = ((size_t)b*K18 + j)*LTP + l;
    RWth[o] = hh; RWtl[o] = lo;
}

// ---------------- bf16x3 mma.sync GEMM: CTA 128x256, warp 64x64, 3-stage ----------------
// Both A[m][k] and B[n][k] are K-major (80B smem rows). C[m][n] fp32, ldc=4096.
#define AP 10240                 // 128 rows * 80B
#define BP 20480                 // 256 rows * 80B
#define STG (2*AP + 2*BP)        // 61440 per stage
#define NSTG 3

#define LDSM4(R, addr) asm volatile( \
    "ldmatrix.sync.aligned.m8n8.x4.shared.b16 {%0,%1,%2,%3},[%4];" \
    : "=r"((R)[0]),"=r"((R)[1]),"=r"((R)[2]),"=r"((R)[3]) : "r"(addr))
#define MMA16816(d, a, b0, b1) asm volatile( \
    "mma.sync.aligned.m16n8k16.row.col.f32.bf16.bf16.f32 " \
    "{%0,%1,%2,%3},{%4,%5,%6,%7},{%8,%9},{%0,%1,%2,%3};" \
    : "+f"((d)[0]),"+f"((d)[1]),"+f"((d)[2]),"+f"((d)[3]) \
    : "r"((a)[0]),"r"((a)[1]),"r"((a)[2]),"r"((a)[3]),"r"(b0),"r"(b1))
#define CPA16(dst, src) asm volatile( \
    "cp.async.cg.shared.global [%0],[%1],16;" :: "r"(dst),"l"(src))

__global__ __launch_bounds__(256, 1) void gemm3_kernel(
    const __nv_bfloat16* __restrict__ Ah, const __nv_bfloat16* __restrict__ Al,
    const __nv_bfloat16* __restrict__ Bh, const __nv_bfloat16* __restrict__ Bl,
    float* __restrict__ C, int lda, int ldb, int KIT,
    size_t sA, size_t sB, size_t sC)
{
    extern __shared__ char smem[];
    int b = blockIdx.z;
    const __nv_bfloat16* pAh = Ah + (size_t)b*sA;
    const __nv_bfloat16* pAl = Al + (size_t)b*sA;
    const __nv_bfloat16* pBh = Bh + (size_t)b*sB;
    const __nv_bfloat16* pBl = Bl + (size_t)b*sB;
    float* pC = C + (size_t)b*sC;
    int row0 = blockIdx.y*128, col0 = blockIdx.x*256;
    int tid = threadIdx.x, lane = tid & 31, wid = tid >> 5;
    int wm = (wid >> 2)*64, wn = (wid & 3)*64;
    uint32_t sb = (uint32_t)__cvta_generic_to_shared(smem);

    float acc[4][8][4];
    #pragma unroll
    for (int i = 0; i < 4; i++)
        #pragma unroll
        for (int j = 0; j < 8; j++)
            #pragma unroll
            for (int r = 0; r < 4; r++) acc[i][j][r] = 0.f;

    auto issue = [&](int it) {
        uint32_t st = sb + (uint32_t)(it % NSTG)*STG;
        int k0 = it << 5;
        #pragma unroll
        for (int q = 0; q < 4; q++) {           // A: 1024 chunks of 16B
            int v = tid + q*256;
            int pl = v >> 9, r = (v >> 2) & 127, kv = v & 3;
            const __nv_bfloat16* src = (pl ? pAl : pAh) + (size_t)(row0 + r)*lda + k0 + kv*8;
            CPA16(st + pl*AP + (uint32_t)(r*80 + kv*16), src);
        }
        #pragma unroll
        for (int q = 0; q < 8; q++) {           // B: 2048 chunks
            int v = tid + q*256;
            int pl = v >> 10, n = (v >> 2) & 255, kv = v & 3;
            const __nv_bfloat16* src = (pl ? pBl : pBh) + (size_t)(col0 + n)*ldb + k0 + kv*8;
            CPA16(st + 2*AP + pl*BP + (uint32_t)(n*80 + kv*16), src);
        }
    };

    issue(0);
    asm volatile("cp.async.commit_group;");
    issue(1);
    asm volatile("cp.async.commit_group;");

    for (int it = 0; it < KIT; it++) {
        if (it == KIT - 1) asm volatile("cp.async.wait_group 0;");
        else               asm volatile("cp.async.wait_group 1;");
        __syncthreads();
        if (it + 2 < KIT) {
            issue(it + 2);
            asm volatile("cp.async.commit_group;");
        }
        uint32_t st = sb + (uint32_t)(it % NSTG)*STG;
        #pragma unroll
        for (int ks = 0; ks < 2; ks++) {
            int koff = ks*16;
            uint32_t ah[4][4], al_[4][4];
            #pragma unroll
            for (int i = 0; i < 4; i++) {
                uint32_t addr = st + (uint32_t)((wm + i*16 + (lane & 15))*80
                                  + (koff + ((lane >> 4) << 3))*2);
                LDSM4(ah[i], addr);
                LDSM4(al_[i], addr + AP);
            }
            // B fragments: non-trans ldmatrix over n-rows (80B stride, K-major)
            // bf[kh][g][m]: n = wn + g*32 + m*8 + lane/4, k-pair at koff + kh*8
            uint32_t bf[2][2][4];
            #pragma unroll
            for (int kh = 0; kh < 2; kh++)
                #pragma unroll
                for (int g = 0; g < 2; g++) {
                    uint32_t addr = st + 2*AP
                        + (uint32_t)((wn + g*32 + lane)*80 + (koff + kh*8)*2);
                    LDSM4(bf[kh][g], addr);
                }
            #pragma unroll
            for (int i = 0; i < 4; i++)
                #pragma unroll
                for (int j = 0; j < 8; j++)
                    MMA16816(acc[i][j], ah[i], bf[0][j>>2][j&3], bf[1][j>>2][j&3]);
            #pragma unroll
            for (int i = 0; i < 4; i++)
                #pragma unroll
                for (int j = 0; j < 8; j++)
                    MMA16816(acc[i][j], al_[i], bf[0][j>>2][j&3], bf[1][j>>2][j&3]);
            // reload B lo planes into same regs
            #pragma unroll
            for (int kh = 0; kh < 2; kh++)
                #pragma unroll
                for (int g = 0; g < 2; g++) {
                    uint32_t addr = st + 2*AP + BP
                        + (uint32_t)((wn + g*32 + lane)*80 + (koff + kh*8)*2);
                    LDSM4(bf[kh][g], addr);
                }
            #pragma unroll
            for (int i = 0; i < 4; i++)
                #pragma unroll
                for (int j = 0; j < 8; j++)
                    MMA16816(acc[i][j], ah[i], bf[0][j>>2][j&3], bf[1][j>>2][j&3]);
        }
        __syncthreads();
    }

    #pragma unroll
    for (int i = 0; i < 4; i++) {
        int r = row0 + wm + i*16 + (lane >> 2);
        #pragma unroll
        for (int j = 0; j < 8; j++) {
            int c = col0 + wn + j*8 + ((lane & 3) << 1);
            *(float2*)&pC[(size_t)r*4096 + c] = make_float2(acc[i][j][0], acc[i][j][1]);
            *(float2*)&pC[(size_t)(r+8)*4096 + c] = make_float2(acc[i][j][2], acc[i][j][3]);
        }
    }
}

// ---------------- softmax pass 1 (stores exp in place) ----------------
__global__ void softmax_part_kernel(float* __restrict__ scores,
                                    float* __restrict__ pmax, float* __restrict__ psum) {
    int p = blockIdx.x*256 + threadIdx.x;
    int c = blockIdx.y, b = blockIdx.z;
    int l0 = c*SCH, l1 = l0 + SCH; if (l1 > LT) l1 = LT;
    float* s = scores + (size_t)b*LTP*P + p;
    float m = -1e30f;
    for (int l = l0; l < l1; l++) m = fmaxf(m, s[(size_t)l*P]);
    float sum = 0.f;
    for (int l = l0; l < l1; l++) {
        float e = __expf(10.f*(s[(size_t)l*P] - m));
        s[(size_t)l*P] = e;
        sum += e;
    }
    pmax[((size_t)b*NCH + c)*P + p] = m;
    psum[((size_t)b*NCH + c)*P + p] = sum;
}

// pass 2: per-chunk rescale factor
__global__ void softmax_comb_kernel(const float* __restrict__ pmax, float* __restrict__ psum) {
    int p = blockIdx.x*256 + threadIdx.x; int b = blockIdx.y;
    float M = -1e30f;
    for (int c = 0; c < NCH; c++) M = fmaxf(M, pmax[((size_t)b*NCH + c)*P + p]);
    float S = 0.f;
    for (int c = 0; c < NCH; c++)
        S += psum[((size_t)b*NCH + c)*P + p] * __expf(10.f*(pmax[((size_t)b*NCH + c)*P + p] - M));
    float invS = 1.0f / S;
    for (int c = 0; c < NCH; c++)
        psum[((size_t)b*NCH + c)*P + p] =
            __expf(10.f*(pmax[((size_t)b*NCH + c)*P + p] - M)) * invS;
}

// pass 3: rescale + transpose -> attT[b][p][l] bf16 hi/lo
__global__ void attT_kernel(const float* __restrict__ scores, const float* __restrict__ psum,
                            __nv_bfloat16* __restrict__ Th, __nv_bfloat16* __restrict__ Tl) {
    __shared__ float t[32][33];
    int p0 = blockIdx.x*32, l0 = blockIdx.y*32, b = blockIdx.z;
    int tx = threadIdx.x, ty = threadIdx.y;
    #pragma unroll
    for (int i = 0; i < 4; i++) {
        int l = l0 + ty + i*8;
        float v = 0.f;
        if (l < LT)
            v = scores[((size_t)b*LTP + l)*P + p0 + tx] *
                psum[((size_t)b*NCH + l/SCH)*P + p0 + tx];
        t[ty + i*8][tx] = v;
    }
    __syncthreads();
    #pragma unroll
    for (int i = 0; i < 4; i++) {
        int p = p0 + ty + i*8;
        float v = t[tx][ty + i*8];
        __nv_bfloat16 hh, lo; split2(v, hh, lo);
        size_t o = ((size_t)b*P + p)*LTP + l0 + tx;
        Th[o] = hh; Tl[o] = lo;
    }
}

// ---------------- col2im + residual ----------------
__global__ void col2im_kernel(const float* __restrict__ T, const float* __restrict__ h2,
                              float* __restrict__ out) {
    int idx = blockIdx.x*blockDim.x + threadIdx.x;
    if (idx >= BB*COUT*P) return;
    int w = idx % H; int hh = (idx / H) % H; int c = (idx / P) % COUT; int b = idx / (P*COUT);
    float acc = 0.f;
    #pragma unroll
    for (int a = 0; a < 3; a++) {
        int y = hh + 1 - a;
        if ((unsigned)y >= H) continue;
        #pragma unroll
        for (int d = 0; d < 3; d++) {
            int x = w + 1 - d;
            if ((unsigned)x >= H) continue;
            acc += T[((size_t)b*K18 + c*9 + a*3 + d)*P + y*H + x];
        }
    }
    out[idx] = h2[idx] + 0.25f*acc;
}

// ---------------- launch ----------------
extern "C" void kernel_launch(void* const* d_in, const int* in_sizes, int n_in,
                              void* d_out, int out_size) {
    (void)in_sizes; (void)n_in; (void)out_size;
    const float* x      = (const float*)d_in[0];
    const float* bb0_w  = (const float*)d_in[1];
    const float* bb0_b  = (const float*)d_in[2];
    const float* bb0_a  = (const float*)d_in[3];
    const float* rb1_w1 = (const float*)d_in[4];
    const float* rb1_b1 = (const float*)d_in[5];
    const float* rb1_w2 = (const float*)d_in[6];
    const float* rb1_b2 = (const float*)d_in[7];
    const float* pamb_w = (const float*)d_in[8];
    const float* pamb_b = (const float*)d_in[9];
    const float* pamb_a = (const float*)d_in[10];
    const float* pam_w  = (const float*)d_in[11];
    const float* pam_b  = (const float*)d_in[12];
    const float* pam_a  = (const float*)d_in[13];
    const float* paa_w  = (const float*)d_in[14];
    const float* paa_b  = (const float*)d_in[15];
    const float* paa_a  = (const float*)d_in[16];
    const float* rb2_w1 = (const float*)d_in[17];
    const float* rb2_b1 = (const float*)d_in[18];
    const float* rb2_w2 = (const float*)d_in[19];
    const float* rb2_b2 = (const float*)d_in[20];
    float* out = (float*)d_out;

    float *h0,*h1,*h2,*tmp,*h3,*mb,*ref,*base,*refm,*scores,*T,*pmax,*psum;
    __nv_bfloat16 *XPth,*XPtl,*WNh,*WNl,*RWth,*RWtl,*attTh,*attTl;
    cudaGetSymbolAddress((void**)&h0, g_h0);
    cudaGetSymbolAddress((void**)&h1, g_h1);
    cudaGetSymbolAddress((void**)&h2, g_h2);
    cudaGetSymbolAddress((void**)&tmp, g_tmp);
    cudaGetSymbolAddress((void**)&h3, g_h3);
    cudaGetSymbolAddress((void**)&mb, g_mb);
    cudaGetSymbolAddress((void**)&ref, g_ref);
    cudaGetSymbolAddress((void**)&base, g_base);
    cudaGetSymbolAddress((void**)&refm, g_refm);
    cudaGetSymbolAddress((void**)&scores, g_scores);
    cudaGetSymbolAddress((void**)&T, g_T);
    cudaGetSymbolAddress((void**)&XPth, g_XPth);
    cudaGetSymbolAddress((void**)&XPtl, g_XPtl);
    cudaGetSymbolAddress((void**)&WNh, g_WNh);
    cudaGetSymbolAddress((void**)&WNl, g_WNl);
    cudaGetSymbolAddress((void**)&RWth, g_RWth);
    cudaGetSymbolAddress((void**)&RWtl, g_RWtl);
    cudaGetSymbolAddress((void**)&attTh, g_attTh);
    cudaGetSymbolAddress((void**)&attTl, g_attTl);
    cudaGetSymbolAddress((void**)&pmax, g_pmax);
    cudaGetSymbolAddress((void**)&psum, g_psum);

    cudaFuncSetAttribute(gemm3_kernel, cudaFuncAttributeMaxDynamicSharedMemorySize, NSTG*STG);

    dim3 cb(16,16);
    dim3 cg(4,4,BB*COUT/4);

    maxpool_kernel<<<(BB*CIN*P + 255)/256, 256>>>(x, h0);
    conv3_kernel<<<cg, cb>>>(h0, bb0_w, bb0_b, nullptr, h1, CIN, COUT, 2, bb0_a);
    conv3_kernel<<<cg, cb>>>(h1, rb1_w1, rb1_b1, nullptr, tmp, COUT, COUT, 1, nullptr);
    conv3_kernel<<<cg, cb>>>(tmp, rb1_w2, rb1_b2, h1, h2, COUT, COUT, 0, nullptr);

    conv1_kernel<<<dim3(P/256, CHALF, BB), 256>>>(h2, pamb_w, pamb_b, pamb_a, mb, COUT, CHALF, P);
    xpT_kernel<<<(int)(((size_t)BB*P*K9 + 255)/256), 256>>>(mb, XPth, XPtl);

    const int Hs[4]   = {64, 57, 51, 44};
    const int loff[4] = {0, 4096, 7345, 9946};
    for (int s = 0; s < 4; s++) {
        int Ls = Hs[s]*Hs[s];
        const float* refp;
        if (s == 0) refp = h2;
        else {
            int n = BB*COUT*Ls;
            resize_kernel<<<(n + 255)/256, 256>>>(h2, ref, Hs[s]);
            refp = ref;
        }
        conv1_kernel<<<dim3((Ls + 255)/256, COUT, BB), 256>>>(
            refp, paa_w, paa_b, paa_a, base + (size_t)BB*COUT*loff[s], COUT, COUT, Ls);
        conv1_kernel<<<dim3((Ls + 255)/256, CHALF, BB), 256>>>(
            refp, pam_w, pam_b, pam_a, refm + (size_t)BB*CHALF*loff[s], COUT, CHALF, Ls);
    }

    wn_kernel<<<dim3(LTP, BB), 128>>>(refm, WNh, WNl);
    rwt_kernel<<<dim3((LTP + 255)/256, K18, BB), 256>>>(base, RWth, RWtl);

    // scores[l][p] = WN[l][:] . XPT[p][:]   (M=LTP, N=4096, K=576)
    gemm3_kernel<<<dim3(P/256, LTP/128, BB), 256, NSTG*STG>>>(
        WNh, WNl, XPth, XPtl, scores, K9, K9, K9/32,
        (size_t)LTP*K9, (size_t)P*K9, (size_t)LTP*P);

    softmax_part_kernel<<<dim3(P/256, NCH, BB), 256>>>(scores, pmax, psum);
    softmax_comb_kernel<<<dim3(P/256, BB), 256>>>(pmax, psum);
    attT_kernel<<<dim3(P/32, LTP/32, BB), dim3(32,8)>>>(scores, psum, attTh, attTl);

    // T[j][p] = RWt[j][:] . attT[p][:]   (M=1152, N=4096, K=LTP)
    gemm3_kernel<<<dim3(P/256, K18/128, BB), 256, NSTG*STG>>>(
        RWth, RWtl, attTh, attTl, T, LTP, LTP, LTP/32,
        (size_t)K18*LTP, (size_t)P*LTP, (size_t)K18*P);

    col2im_kernel<<<(BB*COUT*P + 255)/256, 256>>>(T, h2, h3);

    conv3_kernel<<<cg, cb>>>(h3, rb2_w1, rb2_b1, nullptr, tmp, COUT, COUT, 1, nullptr);
    conv3_kernel<<<cg, cb>>>(tmp, rb2_w2, rb2_b2, h3, out, COUT, COUT, 0, nullptr);
}

// round 7
// speedup vs baseline: 2.9678x; 1.0232x over previous
#include <cuda_runtime.h>
#include <cuda_bf16.h>
#include <cstdint>

// ---------------- dims ----------------
#define BB 2
#define CIN 64
#define COUT 128
#define CHALF 64
#define HIN 128
#define H 64
#define P (H*H)          // 4096
#define LT 11882
#define LTP 11904        // 93*128
#define K9 576
#define K18 1152
#define NCH 32
#define SCH 372

// ---------------- scratch ----------------
__device__ __align__(128) float g_h0[BB*CIN*P];
__device__ __align__(128) float g_h1[BB*COUT*P];
__device__ __align__(128) float g_h2[BB*COUT*P];
__device__ __align__(128) float g_tmp[BB*COUT*P];
__device__ __align__(128) float g_h3[BB*COUT*P];
__device__ __align__(128) float g_mb[BB*CHALF*P];
__device__ __align__(128) float g_ref[BB*COUT*3249];
__device__ __align__(128) float g_base[(size_t)BB*COUT*LT];
__device__ __align__(128) float g_refm[(size_t)BB*CHALF*LT];
__device__ __align__(128) float g_scores[(size_t)BB*LTP*P];   // also conv Craw scratch
__device__ __align__(128) float g_T[(size_t)BB*K18*P];
__device__ __align__(128) __nv_bfloat16 g_ICh[(size_t)BB*P*K18];   // im2col / XPT planes
__device__ __align__(128) __nv_bfloat16 g_ICl[(size_t)BB*P*K18];
__device__ __align__(128) __nv_bfloat16 g_Awh[COUT*K18];
__device__ __align__(128) __nv_bfloat16 g_Awl[COUT*K18];
__device__ __align__(128) __nv_bfloat16 g_WNh[(size_t)BB*LTP*K9];
__device__ __align__(128) __nv_bfloat16 g_WNl[(size_t)BB*LTP*K9];
__device__ __align__(128) __nv_bfloat16 g_RWth[(size_t)BB*K18*LTP];
__device__ __align__(128) __nv_bfloat16 g_RWtl[(size_t)BB*K18*LTP];
__device__ __align__(128) __nv_bfloat16 g_attTh[(size_t)BB*P*LTP];
__device__ __align__(128) __nv_bfloat16 g_attTl[(size_t)BB*P*LTP];
__device__ __align__(128) float g_pmax[BB*NCH*P];
__device__ __align__(128) float g_psum[BB*NCH*P];

__device__ __forceinline__ void split2(float v, __nv_bfloat16& h, __nv_bfloat16& l) {
    h = __float2bfloat16(v);
    l = __float2bfloat16(v - __bfloat162float(h));
}

// ---------------- maxpool ----------------
__global__ void maxpool_kernel(const float* __restrict__ in, float* __restrict__ out) {
    int idx = blockIdx.x*blockDim.x + threadIdx.x;
    if (idx >= BB*CIN*P) return;
    int x = idx % H; int y = (idx / H) % H; int bc = idx / P;
    const float* p = in + ((size_t)bc*HIN + 2*y)*HIN + 2*x;
    out[idx] = fmaxf(fmaxf(p[0], p[1]), fmaxf(p[HIN], p[HIN+1]));
}

// ---------------- im2col (3x3 pad1) -> bf16 hi/lo planes [b][p][k], k=c*9+ky*3+kx ----------------
__global__ void imcol_kernel(const float* __restrict__ in,
                             __nv_bfloat16* __restrict__ Xh, __nv_bfloat16* __restrict__ Xl,
                             int Ci) {
    int K = Ci*9;
    size_t total = (size_t)BB*P*K;
    size_t idx = (size_t)blockIdx.x*256 + threadIdx.x;
    if (idx >= total) return;
    int k = idx % K; int p = (idx / K) % P; int b = idx / ((size_t)K*P);
    int c = k/9, r = k%9; int ky = r/3, kx = r%3;
    int y = p/H + ky - 1, x = p%H + kx - 1;
    float v = 0.f;
    if ((unsigned)y < H && (unsigned)x < H) v = in[((size_t)b*Ci + c)*P + y*H + x];
    __nv_bfloat16 hh, ll; split2(v, hh, ll);
    Xh[idx] = hh; Xl[idx] = ll;
}

// ---------------- weight split: w flat [co][ci][3][3] fp32 -> bf16 hi/lo ----------------
__global__ void wsplit_kernel(const float* __restrict__ w,
                              __nv_bfloat16* __restrict__ Ah, __nv_bfloat16* __restrict__ Al,
                              int n) {
    int idx = blockIdx.x*256 + threadIdx.x;
    if (idx >= n) return;
    __nv_bfloat16 hh, ll; split2(w[idx], hh, ll);
    Ah[idx] = hh; Al[idx] = ll;
}

// ---------------- conv epilogue: bias + act + optional residual ----------------
__global__ void epi_kernel(const float* __restrict__ Craw, const float* __restrict__ bias,
                           const float* __restrict__ alpha_p, const float* __restrict__ res,
                           float* __restrict__ out, int act) {
    int idx = blockIdx.x*256 + threadIdx.x;
    if (idx >= BB*COUT*P) return;
    int co = (idx / P) % COUT;
    float v = Craw[idx] + bias[co];
    if (act == 1) v = fmaxf(v, 0.f);
    else if (act == 2) { float a = *alpha_p; v = v >= 0.f ? v : a*v; }
    if (res) v += res[idx];
    out[idx] = v;
}

// ---------------- 1x1 conv + PReLU ----------------
__global__ void conv1_kernel(const float* __restrict__ in, const float* __restrict__ w,
                             const float* __restrict__ bias, const float* __restrict__ alpha_p,
                             float* __restrict__ out, int Ci, int Co, int Pn) {
    int p = blockIdx.x*256 + threadIdx.x;
    int o = blockIdx.y, b = blockIdx.z;
    if (p >= Pn) return;
    const float* ip = in + (size_t)b*Ci*Pn + p;
    const float* wp = w + (size_t)o*Ci;
    float acc = bias[o];
    #pragma unroll 8
    for (int i = 0; i < Ci; i++) acc += wp[i] * ip[(size_t)i*Pn];
    float a = *alpha_p;
    out[((size_t)b*Co + o)*Pn + p] = acc >= 0.f ? acc : a*acc;
}

// ---------------- bilinear resize with antialias ----------------
__global__ void resize_kernel(const float* __restrict__ in, float* __restrict__ out, int Hout) {
    int total = BB*COUT*Hout*Hout;
    int idx = blockIdx.x*blockDim.x + threadIdx.x;
    if (idx >= total) return;
    int xo = idx % Hout; int yo = (idx / Hout) % Hout; int bc = idx / (Hout*Hout);
    float inv = (float)H / (float)Hout;
    float sy = (yo + 0.5f)*inv - 0.5f;
    float sx = (xo + 0.5f)*inv - 0.5f;
    float wy[4], wx[4]; int jy[4], jx[4];
    int ny = 0, nx = 0; float sumy = 0.f, sumx = 0.f;
    int lo = (int)ceilf(sy - inv), hi = (int)floorf(sy + inv);
    if (lo < 0) lo = 0; if (hi > H-1) hi = H-1;
    for (int j = lo; j <= hi && ny < 4; j++) {
        float w = 1.0f - fabsf(sy - (float)j)/inv;
        if (w > 0.f) { wy[ny] = w; jy[ny] = j; sumy += w; ny++; }
    }
    lo = (int)ceilf(sx - inv); hi = (int)floorf(sx + inv);
    if (lo < 0) lo = 0; if (hi > H-1) hi = H-1;
    for (int j = lo; j <= hi && nx < 4; j++) {
        float w = 1.0f - fabsf(sx - (float)j)/inv;
        if (w > 0.f) { wx[nx] = w; jx[nx] = j; sumx += w; nx++; }
    }
    const float* ip = in + (size_t)bc*P;
    float acc = 0.f;
    for (int a = 0; a < ny; a++)
        for (int bx2 = 0; bx2 < nx; bx2++)
            acc += wy[a]*wx[bx2]*ip[jy[a]*H + jx[bx2]];
    out[idx] = acc / (sumy*sumx);
}

__device__ __forceinline__ void decode_l(int l, int& Hs, int& loff) {
    if (l < 4096)      { Hs = 64; loff = 0; }
    else if (l < 7345) { Hs = 57; loff = 4096; }
    else if (l < 9946) { Hs = 51; loff = 7345; }
    else               { Hs = 44; loff = 9946; }
}

// ---------------- normalized key patches WN[b][l][k], rows 0..LTP (pad zero) ----------------
__global__ void wn_kernel(const float* __restrict__ refm,
                          __nv_bfloat16* __restrict__ WNh, __nv_bfloat16* __restrict__ WNl) {
    int l = blockIdx.x, b = blockIdx.y;
    int tid = threadIdx.x;
    size_t obase = ((size_t)b*LTP + l)*K9;
    if (l >= LT) {
        for (int k = tid; k < K9; k += 128) {
            WNh[obase + k] = __float2bfloat16(0.f);
            WNl[obase + k] = __float2bfloat16(0.f);
        }
        return;
    }
    int Hs, loff; decode_l(l, Hs, loff);
    int Ls = Hs*Hs; int ll = l - loff; int lh = ll/Hs, lw = ll%Hs;
    const float* rp = refm + (size_t)BB*CHALF*loff + (size_t)b*CHALF*Ls;
    __shared__ float vals[K9];
    __shared__ float red[128];
    float ss = 0.f;
    for (int k = tid; k < K9; k += 128) {
        int c = k/9, r = k%9; int ky = r/3, kx = r%3;
        int y = lh + ky - 1, x = lw + kx - 1;
        float v = 0.f;
        if ((unsigned)y < (unsigned)Hs && (unsigned)x < (unsigned)Hs) v = rp[(size_t)c*Ls + y*Hs + x];
        vals[k] = v; ss += v*v;
    }
    red[tid] = ss; __syncthreads();
    for (int o = 64; o > 0; o >>= 1) { if (tid < o) red[tid] += red[tid+o]; __syncthreads(); }
    float rn = 1.0f / fmaxf(sqrtf(red[0]), 1e-4f);
    for (int k = tid; k < K9; k += 128) {
        __nv_bfloat16 hh, lo; split2(vals[k]*rn, hh, lo);
        WNh[obase + k] = hh; WNl[obase + k] = lo;
    }
}

// ---------------- assembly patches RWt[b][j][LTP] (pad zero) ----------------
__global__ void rwt_kernel(const float* __restrict__ base,
                           __nv_bfloat16* __restrict__ RWth, __nv_bfloat16* __restrict__ RWtl) {
    int l = blockIdx.x*blockDim.x + threadIdx.x;
    if (l >= LTP) return;
    int j = blockIdx.y, b = blockIdx.z;
    float v = 0.f;
    if (l < LT) {
        int c = j/9, r = j%9; int ky = r/3, kx = r%3;
        int Hs, loff; decode_l(l, Hs, loff);
        int Ls = Hs*Hs; int ll = l - loff; int lh = ll/Hs, lw = ll%Hs;
        int y = lh + ky - 1, x = lw + kx - 1;
        if ((unsigned)y < (unsigned)Hs && (unsigned)x < (unsigned)Hs)
            v = base[(size_t)BB*COUT*loff + ((size_t)b*COUT + c)*Ls + y*Hs + x];
    }
    __nv_bfloat16 hh, lo; split2(v, hh, lo);
    size_t o = ((size_t)b*K18 + j)*LTP + l;
    RWth[o] = hh; RWtl[o] = lo;
}

// ---------------- bf16x3 mma.sync GEMM: CTA 128x256, warp 64x64, 3-stage ----------------
// A[m][k], B[n][k] K-major (80B smem rows). C[m][n] fp32, ldc=4096.
#define AP 10240
#define BP 20480
#define STG (2*AP + 2*BP)
#define NSTG 3

#define LDSM4(R, addr) asm volatile( \
    "ldmatrix.sync.aligned.m8n8.x4.shared.b16 {%0,%1,%2,%3},[%4];" \
    : "=r"((R)[0]),"=r"((R)[1]),"=r"((R)[2]),"=r"((R)[3]) : "r"(addr))
#define MMA16816(d, a, b0, b1) asm volatile( \
    "mma.sync.aligned.m16n8k16.row.col.f32.bf16.bf16.f32 " \
    "{%0,%1,%2,%3},{%4,%5,%6,%7},{%8,%9},{%0,%1,%2,%3};" \
    : "+f"((d)[0]),"+f"((d)[1]),"+f"((d)[2]),"+f"((d)[3]) \
    : "r"((a)[0]),"r"((a)[1]),"r"((a)[2]),"r"((a)[3]),"r"(b0),"r"(b1))
#define CPA16(dst, src) asm volatile( \
    "cp.async.cg.shared.global [%0],[%1],16;" :: "r"(dst),"l"(src))

__global__ __launch_bounds__(256, 1) void gemm3_kernel(
    const __nv_bfloat16* __restrict__ Ah, const __nv_bfloat16* __restrict__ Al,
    const __nv_bfloat16* __restrict__ Bh, const __nv_bfloat16* __restrict__ Bl,
    float* __restrict__ C, int lda, int ldb, int KIT,
    size_t sA, size_t sB, size_t sC)
{
    extern __shared__ char smem[];
    int b = blockIdx.z;
    const __nv_bfloat16* pAh = Ah + (size_t)b*sA;
    const __nv_bfloat16* pAl = Al + (size_t)b*sA;
    const __nv_bfloat16* pBh = Bh + (size_t)b*sB;
    const __nv_bfloat16* pBl = Bl + (size_t)b*sB;
    float* pC = C + (size_t)b*sC;
    int row0 = blockIdx.y*128, col0 = blockIdx.x*256;
    int tid = threadIdx.x, lane = tid & 31, wid = tid >> 5;
    int wm = (wid >> 2)*64, wn = (wid & 3)*64;
    uint32_t sb = (uint32_t)__cvta_generic_to_shared(smem);

    float acc[4][8][4];
    #pragma unroll
    for (int i = 0; i < 4; i++)
        #pragma unroll
        for (int j = 0; j < 8; j++)
            #pragma unroll
            for (int r = 0; r < 4; r++) acc[i][j][r] = 0.f;

    auto issue = [&](int it) {
        uint32_t st = sb + (uint32_t)(it % NSTG)*STG;
        int k0 = it << 5;
        #pragma unroll
        for (int q = 0; q < 4; q++) {
            int v = tid + q*256;
            int pl = v >> 9, r = (v >> 2) & 127, kv = v & 3;
            const __nv_bfloat16* src = (pl ? pAl : pAh) + (size_t)(row0 + r)*lda + k0 + kv*8;
            CPA16(st + pl*AP + (uint32_t)(r*80 + kv*16), src);
        }
        #pragma unroll
        for (int q = 0; q < 8; q++) {
            int v = tid + q*256;
            int pl = v >> 10, n = (v >> 2) & 255, kv = v & 3;
            const __nv_bfloat16* src = (pl ? pBl : pBh) + (size_t)(col0 + n)*ldb + k0 + kv*8;
            CPA16(st + 2*AP + pl*BP + (uint32_t)(n*80 + kv*16), src);
        }
    };

    issue(0);
    asm volatile("cp.async.commit_group;");
    issue(1);
    asm volatile("cp.async.commit_group;");

    for (int it = 0; it < KIT; it++) {
        if (it == KIT - 1) asm volatile("cp.async.wait_group 0;");
        else               asm volatile("cp.async.wait_group 1;");
        __syncthreads();
        if (it + 2 < KIT) {
            issue(it + 2);
            asm volatile("cp.async.commit_group;");
        }
        uint32_t st = sb + (uint32_t)(it % NSTG)*STG;
        #pragma unroll
        for (int ks = 0; ks < 2; ks++) {
            int koff = ks*16;
            uint32_t ah[4][4], al_[4][4];
            #pragma unroll
            for (int i = 0; i < 4; i++) {
                uint32_t addr = st + (uint32_t)((wm + i*16 + (lane & 15))*80
                                  + (koff + ((lane >> 4) << 3))*2);
                LDSM4(ah[i], addr);
                LDSM4(al_[i], addr + AP);
            }
            uint32_t bf[2][2][4];
            #pragma unroll
            for (int kh = 0; kh < 2; kh++)
                #pragma unroll
                for (int g = 0; g < 2; g++) {
                    uint32_t addr = st + 2*AP
                        + (uint32_t)((wn + g*32 + lane)*80 + (koff + kh*8)*2);
                    LDSM4(bf[kh][g], addr);
                }
            #pragma unroll
            for (int i = 0; i < 4; i++)
                #pragma unroll
                for (int j = 0; j < 8; j++)
                    MMA16816(acc[i][j], ah[i], bf[0][j>>2][j&3], bf[1][j>>2][j&3]);
            #pragma unroll
            for (int i = 0; i < 4; i++)
                #pragma unroll
                for (int j = 0; j < 8; j++)
                    MMA16816(acc[i][j], al_[i], bf[0][j>>2][j&3], bf[1][j>>2][j&3]);
            #pragma unroll
            for (int kh = 0; kh < 2; kh++)
                #pragma unroll
                for (int g = 0; g < 2; g++) {
                    uint32_t addr = st + 2*AP + BP
                        + (uint32_t)((wn + g*32 + lane)*80 + (koff + kh*8)*2);
                    LDSM4(bf[kh][g], addr);
                }
            #pragma unroll
            for (int i = 0; i < 4; i++)
                #pragma unroll
                for (int j = 0; j < 8; j++)
                    MMA16816(acc[i][j], ah[i], bf[0][j>>2][j&3], bf[1][j>>2][j&3]);
        }
        // NOTE: no trailing sync — top-of-iter barrier already orders
        // compute(it-1) before issue(it+2)'s overwrite of stage (it-1)%3.
    }

    #pragma unroll
    for (int i = 0; i < 4; i++) {
        int r = row0 + wm + i*16 + (lane >> 2);
        #pragma unroll
        for (int j = 0; j < 8; j++) {
            int c = col0 + wn + j*8 + ((lane & 3) << 1);
            *(float2*)&pC[(size_t)r*4096 + c] = make_float2(acc[i][j][0], acc[i][j][1]);
            *(float2*)&pC[(size_t)(r+8)*4096 + c] = make_float2(acc[i][j][2], acc[i][j][3]);
        }
    }
}

// ---------------- softmax pass 1 (stores exp in place) ----------------
__global__ void softmax_part_kernel(float* __restrict__ scores,
                                    float* __restrict__ pmax, float* __restrict__ psum) {
    int p = blockIdx.x*256 + threadIdx.x;
    int c = blockIdx.y, b = blockIdx.z;
    int l0 = c*SCH, l1 = l0 + SCH; if (l1 > LT) l1 = LT;
    float* s = scores + (size_t)b*LTP*P + p;
    float m = -1e30f;
    for (int l = l0; l < l1; l++) m = fmaxf(m, s[(size_t)l*P]);
    float sum = 0.f;
    for (int l = l0; l < l1; l++) {
        float e = __expf(10.f*(s[(size_t)l*P] - m));
        s[(size_t)l*P] = e;
        sum += e;
    }
    pmax[((size_t)b*NCH + c)*P + p] = m;
    psum[((size_t)b*NCH + c)*P + p] = sum;
}

__global__ void softmax_comb_kernel(const float* __restrict__ pmax, float* __restrict__ psum) {
    int p = blockIdx.x*256 + threadIdx.x; int b = blockIdx.y;
    float M = -1e30f;
    for (int c = 0; c < NCH; c++) M = fmaxf(M, pmax[((size_t)b*NCH + c)*P + p]);
    float S = 0.f;
    for (int c = 0; c < NCH; c++)
        S += psum[((size_t)b*NCH + c)*P + p] * __expf(10.f*(pmax[((size_t)b*NCH + c)*P + p] - M));
    float invS = 1.0f / S;
    for (int c = 0; c < NCH; c++)
        psum[((size_t)b*NCH + c)*P + p] =
            __expf(10.f*(pmax[((size_t)b*NCH + c)*P + p] - M)) * invS;
}

// pass 3: rescale + transpose -> attT[b][p][l] bf16 hi/lo
__global__ void attT_kernel(const float* __restrict__ scores, const float* __restrict__ psum,
                            __nv_bfloat16* __restrict__ Th, __nv_bfloat16* __restrict__ Tl) {
    __shared__ float t[32][33];
    int p0 = blockIdx.x*32, l0 = blockIdx.y*32, b = blockIdx.z;
    int tx = threadIdx.x, ty = threadIdx.y;
    #pragma unroll
    for (int i = 0; i < 4; i++) {
        int l = l0 + ty + i*8;
        float v = 0.f;
        if (l < LT)
            v = scores[((size_t)b*LTP + l)*P + p0 + tx] *
                psum[((size_t)b*NCH + l/SCH)*P + p0 + tx];
        t[ty + i*8][tx] = v;
    }
    __syncthreads();
    #pragma unroll
    for (int i = 0; i < 4; i++) {
        int p = p0 + ty + i*8;
        float v = t[tx][ty + i*8];
        __nv_bfloat16 hh, lo; split2(v, hh, lo);
        size_t o = ((size_t)b*P + p)*LTP + l0 + tx;
        Th[o] = hh; Tl[o] = lo;
    }
}

// ---------------- col2im + residual ----------------
__global__ void col2im_kernel(const float* __restrict__ T, const float* __restrict__ h2,
                              float* __restrict__ out) {
    int idx = blockIdx.x*blockDim.x + threadIdx.x;
    if (idx >= BB*COUT*P) return;
    int w = idx % H; int hh = (idx / H) % H; int c = (idx / P) % COUT; int b = idx / (P*COUT);
    float acc = 0.f;
    #pragma unroll
    for (int a = 0; a < 3; a++) {
        int y = hh + 1 - a;
        if ((unsigned)y >= H) continue;
        #pragma unroll
        for (int d = 0; d < 3; d++) {
            int x = w + 1 - d;
            if ((unsigned)x >= H) continue;
            acc += T[((size_t)b*K18 + c*9 + a*3 + d)*P + y*H + x];
        }
    }
    out[idx] = h2[idx] + 0.25f*acc;
}

// ---------------- launch ----------------
extern "C" void kernel_launch(void* const* d_in, const int* in_sizes, int n_in,
                              void* d_out, int out_size) {
    (void)in_sizes; (void)n_in; (void)out_size;
    const float* x      = (const float*)d_in[0];
    const float* bb0_w  = (const float*)d_in[1];
    const float* bb0_b  = (const float*)d_in[2];
    const float* bb0_a  = (const float*)d_in[3];
    const float* rb1_w1 = (const float*)d_in[4];
    const float* rb1_b1 = (const float*)d_in[5];
    const float* rb1_w2 = (const float*)d_in[6];
    const float* rb1_b2 = (const float*)d_in[7];
    const float* pamb_w = (const float*)d_in[8];
    const float* pamb_b = (const float*)d_in[9];
    const float* pamb_a = (const float*)d_in[10];
    const float* pam_w  = (const float*)d_in[11];
    const float* pam_b  = (const float*)d_in[12];
    const float* pam_a  = (const float*)d_in[13];
    const float* paa_w  = (const float*)d_in[14];
    const float* paa_b  = (const float*)d_in[15];
    const float* paa_a  = (const float*)d_in[16];
    const float* rb2_w1 = (const float*)d_in[17];
    const float* rb2_b1 = (const float*)d_in[18];
    const float* rb2_w2 = (const float*)d_in[19];
    const float* rb2_b2 = (const float*)d_in[20];
    float* out = (float*)d_out;

    float *h0,*h1,*h2,*tmp,*h3,*mb,*ref,*base,*refm,*scores,*T,*pmax,*psum;
    __nv_bfloat16 *ICh,*ICl,*Awh,*Awl,*WNh,*WNl,*RWth,*RWtl,*attTh,*attTl;
    cudaGetSymbolAddress((void**)&h0, g_h0);
    cudaGetSymbolAddress((void**)&h1, g_h1);
    cudaGetSymbolAddress((void**)&h2, g_h2);
    cudaGetSymbolAddress((void**)&tmp, g_tmp);
    cudaGetSymbolAddress((void**)&h3, g_h3);
    cudaGetSymbolAddress((void**)&mb, g_mb);
    cudaGetSymbolAddress((void**)&ref, g_ref);
    cudaGetSymbolAddress((void**)&base, g_base);
    cudaGetSymbolAddress((void**)&refm, g_refm);
    cudaGetSymbolAddress((void**)&scores, g_scores);
    cudaGetSymbolAddress((void**)&T, g_T);
    cudaGetSymbolAddress((void**)&ICh, g_ICh);
    cudaGetSymbolAddress((void**)&ICl, g_ICl);
    cudaGetSymbolAddress((void**)&Awh, g_Awh);
    cudaGetSymbolAddress((void**)&Awl, g_Awl);
    cudaGetSymbolAddress((void**)&WNh, g_WNh);
    cudaGetSymbolAddress((void**)&WNl, g_WNl);
    cudaGetSymbolAddress((void**)&RWth, g_RWth);
    cudaGetSymbolAddress((void**)&RWtl, g_RWtl);
    cudaGetSymbolAddress((void**)&attTh, g_attTh);
    cudaGetSymbolAddress((void**)&attTl, g_attTl);
    cudaGetSymbolAddress((void**)&pmax, g_pmax);
    cudaGetSymbolAddress((void**)&psum, g_psum);

    cudaFuncSetAttribute(gemm3_kernel, cudaFuncAttributeMaxDynamicSharedMemorySize, NSTG*STG);

    // conv3 via implicit GEMM: Craw parked in scores buffer (free until GEMM1)
    float* Craw = scores;
    auto conv3g = [&](const float* in, const float* w, const float* bias,
                      const float* alpha, const float* res, float* o, int Ci, int act) {
        int K = Ci*9;
        wsplit_kernel<<<(COUT*K + 255)/256, 256>>>(w, Awh, Awl, COUT*K);
        imcol_kernel<<<(int)(((size_t)BB*P*K + 255)/256), 256>>>(in, ICh, ICl, Ci);
        gemm3_kernel<<<dim3(P/256, 1, BB), 256, NSTG*STG>>>(
            Awh, Awl, ICh, ICl, Craw, K, K, K/32,
            0, (size_t)P*K, (size_t)COUT*P);
        epi_kernel<<<(BB*COUT*P + 255)/256, 256>>>(Craw, bias, alpha, res, o, act);
    };

    maxpool_kernel<<<(BB*CIN*P + 255)/256, 256>>>(x, h0);
    conv3g(h0, bb0_w, bb0_b, bb0_a, nullptr, h1, CIN, 2);
    conv3g(h1, rb1_w1, rb1_b1, nullptr, nullptr, tmp, COUT, 1);
    conv3g(tmp, rb1_w2, rb1_b2, nullptr, h1, h2, COUT, 0);

    conv1_kernel<<<dim3(P/256, CHALF, BB), 256>>>(h2, pamb_w, pamb_b, pamb_a, mb, COUT, CHALF, P);
    imcol_kernel<<<(int)(((size_t)BB*P*K9 + 255)/256), 256>>>(mb, ICh, ICl, CHALF);  // XPT

    const int Hs[4]   = {64, 57, 51, 44};
    const int loff[4] = {0, 4096, 7345, 9946};
    for (int s = 0; s < 4; s++) {
        int Ls = Hs[s]*Hs[s];
        const float* refp;
        if (s == 0) refp = h2;
        else {
            int n = BB*COUT*Ls;
            resize_kernel<<<(n + 255)/256, 256>>>(h2, ref, Hs[s]);
            refp = ref;
        }
        conv1_kernel<<<dim3((Ls + 255)/256, COUT, BB), 256>>>(
            refp, paa_w, paa_b, paa_a, base + (size_t)BB*COUT*loff[s], COUT, COUT, Ls);
        conv1_kernel<<<dim3((Ls + 255)/256, CHALF, BB), 256>>>(
            refp, pam_w, pam_b, pam_a, refm + (size_t)BB*CHALF*loff[s], COUT, CHALF, Ls);
    }

    wn_kernel<<<dim3(LTP, BB), 128>>>(refm, WNh, WNl);
    rwt_kernel<<<dim3((LTP + 255)/256, K18, BB), 256>>>(base, RWth, RWtl);

    // scores[l][p] = WN[l][:] . XPT[p][:]   (M=LTP, N=4096, K=576)
    gemm3_kernel<<<dim3(P/256, LTP/128, BB), 256, NSTG*STG>>>(
        WNh, WNl, ICh, ICl, scores, K9, K9, K9/32,
        (size_t)LTP*K9, (size_t)P*K9, (size_t)LTP*P);

    softmax_part_kernel<<<dim3(P/256, NCH, BB), 256>>>(scores, pmax, psum);
    softmax_comb_kernel<<<dim3(P/256, BB), 256>>>(pmax, psum);
    attT_kernel<<<dim3(P/32, LTP/32, BB), dim3(32,8)>>>(scores, psum, attTh, attTl);

    // T[j][p] = RWt[j][:] . attT[p][:]   (M=1152, N=4096, K=LTP)
    gemm3_kernel<<<dim3(P/256, K18/128, BB), 256, NSTG*STG>>>(
        RWth, RWtl, attTh, attTl, T, LTP, LTP, LTP/32,
        (size_t)K18*LTP, (size_t)P*LTP, (size_t)K18*P);

    col2im_kernel<<<(BB*COUT*P + 255)/256, 256>>>(T, h2, h3);

    conv3g(h3, rb2_w1, rb2_b1, nullptr, nullptr, tmp, COUT, 1);
    conv3g(tmp, rb2_w2, rb2_b2, nullptr, h3, out, COUT, 0);
}

// round 11
// speedup vs baseline: 3.0441x; 1.0257x over previous
#include <cuda_runtime.h>
#include <cuda_bf16.h>
#include <cstdint>

// ---------------- dims ----------------
#define BB 2
#define CIN 64
#define COUT 128
#define CHALF 64
#define HIN 128
#define H 64
#define P (H*H)          // 4096
#define LT 11882
#define LTP 11904        // 93*128
#define K9 576
#define K18 1152
#define NCH 32
#define SCH 372

// ---------------- scratch ----------------
__device__ __align__(128) float g_h0[BB*CIN*P];
__device__ __align__(128) float g_h1[BB*COUT*P];
__device__ __align__(128) float g_h2[BB*COUT*P];
__device__ __align__(128) float g_tmp[BB*COUT*P];
__device__ __align__(128) float g_h3[BB*COUT*P];
__device__ __align__(128) float g_mb[BB*CHALF*P];
__device__ __align__(128) float g_ref[BB*COUT*3249];
__device__ __align__(128) float g_base[(size_t)BB*COUT*LT];
__device__ __align__(128) float g_refm[(size_t)BB*CHALF*LT];
__device__ __align__(128) float g_scores[(size_t)BB*LTP*P];   // also conv Craw scratch
__device__ __align__(128) float g_T[(size_t)BB*K18*P];
__device__ __align__(128) __nv_bfloat16 g_ICh[(size_t)BB*P*K18];   // im2col / XPT planes
__device__ __align__(128) __nv_bfloat16 g_ICl[(size_t)BB*P*K18];
__device__ __align__(128) __nv_bfloat16 g_Awh[COUT*K18];
__device__ __align__(128) __nv_bfloat16 g_Awl[COUT*K18];
__device__ __align__(128) __nv_bfloat16 g_WNh[(size_t)BB*LTP*K9];
__device__ __align__(128) __nv_bfloat16 g_WNl[(size_t)BB*LTP*K9];
__device__ __align__(128) __nv_bfloat16 g_RWth[(size_t)BB*K18*LTP];
__device__ __align__(128) __nv_bfloat16 g_RWtl[(size_t)BB*K18*LTP];
__device__ __align__(128) __nv_bfloat16 g_attTh[(size_t)BB*P*LTP];
__device__ __align__(128) __nv_bfloat16 g_attTl[(size_t)BB*P*LTP];
__device__ __align__(128) float g_pmax[BB*NCH*P];
__device__ __align__(128) float g_psum[BB*NCH*P];

__device__ __forceinline__ void split2(float v, __nv_bfloat16& h, __nv_bfloat16& l) {
    h = __float2bfloat16(v);
    l = __float2bfloat16(v - __bfloat162float(h));
}

// ---------------- maxpool ----------------
__global__ void maxpool_kernel(const float* __restrict__ in, float* __restrict__ out) {
    int idx = blockIdx.x*blockDim.x + threadIdx.x;
    if (idx >= BB*CIN*P) return;
    int x = idx % H; int y = (idx / H) % H; int bc = idx / P;
    const float* p = in + ((size_t)bc*HIN + 2*y)*HIN + 2*x;
    out[idx] = fmaxf(fmaxf(p[0], p[1]), fmaxf(p[HIN], p[HIN+1]));
}

// ---------------- im2col (3x3 pad1), Ci compile-time -> constant-divisor index math ----------------
template<int Ci>
__global__ void imcol_kernel(const float* __restrict__ in,
                             __nv_bfloat16* __restrict__ Xh, __nv_bfloat16* __restrict__ Xl) {
    constexpr int K = Ci*9;
    int idx = blockIdx.x*256 + threadIdx.x;   // within one batch: [p][k]
    int b = blockIdx.y;
    if (idx >= P*K) return;
    int k = idx % K; int p = idx / K;
    int c = k/9, r = k%9; int ky = r/3, kx = r - ky*3;
    int y = (p >> 6) + ky - 1, x = (p & 63) + kx - 1;
    float v = 0.f;
    if ((unsigned)y < H && (unsigned)x < H) v = in[((size_t)b*Ci + c)*P + y*H + x];
    __nv_bfloat16 hh, ll; split2(v, hh, ll);
    size_t o = (size_t)b*P*K + idx;
    Xh[o] = hh; Xl[o] = ll;
}

// ---------------- weight split ----------------
__global__ void wsplit_kernel(const float* __restrict__ w,
                              __nv_bfloat16* __restrict__ Ah, __nv_bfloat16* __restrict__ Al,
                              int n) {
    int idx = blockIdx.x*256 + threadIdx.x;
    if (idx >= n) return;
    __nv_bfloat16 hh, ll; split2(w[idx], hh, ll);
    Ah[idx] = hh; Al[idx] = ll;
}

// ---------------- conv epilogue: bias + act + optional residual ----------------
__global__ void epi_kernel(const float* __restrict__ Craw, const float* __restrict__ bias,
                           const float* __restrict__ alpha_p, const float* __restrict__ res,
                           float* __restrict__ out, int act) {
    int idx = blockIdx.x*256 + threadIdx.x;
    if (idx >= BB*COUT*P) return;
    int co = (idx / P) % COUT;
    float v = Craw[idx] + bias[co];
    if (act == 1) v = fmaxf(v, 0.f);
    else if (act == 2) { float a = *alpha_p; v = v >= 0.f ? v : a*v; }
    if (res) v += res[idx];
    out[idx] = v;
}

// ---------------- 1x1 conv + PReLU, 4 output channels per block ----------------
__global__ void conv1_kernel(const float* __restrict__ in, const float* __restrict__ w,
                             const float* __restrict__ bias, const float* __restrict__ alpha_p,
                             float* __restrict__ out, int Ci, int Co, int Pn) {
    int p = blockIdx.x*256 + threadIdx.x;
    int o0 = blockIdx.y*4, b = blockIdx.z;
    if (p >= Pn) return;
    const float* ip = in + (size_t)b*Ci*Pn + p;
    float acc[4];
    #pragma unroll
    for (int o = 0; o < 4; o++) acc[o] = bias[o0 + o];
    #pragma unroll 4
    for (int i = 0; i < Ci; i++) {
        float t = ip[(size_t)i*Pn];
        #pragma unroll
        for (int o = 0; o < 4; o++) acc[o] += w[(size_t)(o0+o)*Ci + i] * t;
    }
    float a = *alpha_p;
    #pragma unroll
    for (int o = 0; o < 4; o++) {
        float v = acc[o];
        out[((size_t)b*Co + o0 + o)*Pn + p] = v >= 0.f ? v : a*v;
    }
}

// ---------------- bilinear resize with antialias ----------------
__global__ void resize_kernel(const float* __restrict__ in, float* __restrict__ out, int Hout) {
    int total = BB*COUT*Hout*Hout;
    int idx = blockIdx.x*blockDim.x + threadIdx.x;
    if (idx >= total) return;
    int xo = idx % Hout; int yo = (idx / Hout) % Hout; int bc = idx / (Hout*Hout);
    float inv = (float)H / (float)Hout;
    float sy = (yo + 0.5f)*inv - 0.5f;
    float sx = (xo + 0.5f)*inv - 0.5f;
    float wy[4], wx[4]; int jy[4], jx[4];
    int ny = 0, nx = 0; float sumy = 0.f, sumx = 0.f;
    int lo = (int)ceilf(sy - inv), hi = (int)floorf(sy + inv);
    if (lo < 0) lo = 0; if (hi > H-1) hi = H-1;
    for (int j = lo; j <= hi && ny < 4; j++) {
        float w = 1.0f - fabsf(sy - (float)j)/inv;
        if (w > 0.f) { wy[ny] = w; jy[ny] = j; sumy += w; ny++; }
    }
    lo = (int)ceilf(sx - inv); hi = (int)floorf(sx + inv);
    if (lo < 0) lo = 0; if (hi > H-1) hi = H-1;
    for (int j = lo; j <= hi && nx < 4; j++) {
        float w = 1.0f - fabsf(sx - (float)j)/inv;
        if (w > 0.f) { wx[nx] = w; jx[nx] = j; sumx += w; nx++; }
    }
    const float* ip = in + (size_t)bc*P;
    float acc = 0.f;
    for (int a = 0; a < ny; a++)
        for (int bx2 = 0; bx2 < nx; bx2++)
            acc += wy[a]*wx[bx2]*ip[jy[a]*H + jx[bx2]];
    out[idx] = acc / (sumy*sumx);
}

__device__ __forceinline__ void decode_l(int l, int& Hs, int& loff) {
    if (l < 4096)      { Hs = 64; loff = 0; }
    else if (l < 7345) { Hs = 57; loff = 4096; }
    else if (l < 9946) { Hs = 51; loff = 7345; }
    else               { Hs = 44; loff = 9946; }
}

// ---------------- normalized key patches WN[b][l][k], rows 0..LTP (pad zero) ----------------
__global__ void wn_kernel(const float* __restrict__ refm,
                          __nv_bfloat16* __restrict__ WNh, __nv_bfloat16* __restrict__ WNl) {
    int l = blockIdx.x, b = blockIdx.y;
    int tid = threadIdx.x;
    size_t obase = ((size_t)b*LTP + l)*K9;
    if (l >= LT) {
        for (int k = tid; k < K9; k += 128) {
            WNh[obase + k] = __float2bfloat16(0.f);
            WNl[obase + k] = __float2bfloat16(0.f);
        }
        return;
    }
    int Hs, loff; decode_l(l, Hs, loff);
    int Ls = Hs*Hs; int ll = l - loff; int lh = ll/Hs, lw = ll%Hs;
    const float* rp = refm + (size_t)BB*CHALF*loff + (size_t)b*CHALF*Ls;
    __shared__ float vals[K9];
    __shared__ float red[128];
    float ss = 0.f;
    for (int k = tid; k < K9; k += 128) {
        int c = k/9, r = k%9; int ky = r/3, kx = r%3;
        int y = lh + ky - 1, x = lw + kx - 1;
        float v = 0.f;
        if ((unsigned)y < (unsigned)Hs && (unsigned)x < (unsigned)Hs) v = rp[(size_t)c*Ls + y*Hs + x];
        vals[k] = v; ss += v*v;
    }
    red[tid] = ss; __syncthreads();
    for (int o = 64; o > 0; o >>= 1) { if (tid < o) red[tid] += red[tid+o]; __syncthreads(); }
    float rn = 1.0f / fmaxf(sqrtf(red[0]), 1e-4f);
    for (int k = tid; k < K9; k += 128) {
        __nv_bfloat16 hh, lo; split2(vals[k]*rn, hh, lo);
        WNh[obase + k] = hh; WNl[obase + k] = lo;
    }
}

// ---------------- assembly patches RWt[b][j][LTP] (pad zero) ----------------
__global__ void rwt_kernel(const float* __restrict__ base,
                           __nv_bfloat16* __restrict__ RWth, __nv_bfloat16* __restrict__ RWtl) {
    int l = blockIdx.x*blockDim.x + threadIdx.x;
    if (l >= LTP) return;
    int j = blockIdx.y, b = blockIdx.z;
    float v = 0.f;
    if (l < LT) {
        int c = j/9, r = j%9; int ky = r/3, kx = r%3;
        int Hs, loff; decode_l(l, Hs, loff);
        int Ls = Hs*Hs; int ll = l - loff; int lh = ll/Hs, lw = ll%Hs;
        int y = lh + ky - 1, x = lw + kx - 1;
        if ((unsigned)y < (unsigned)Hs && (unsigned)x < (unsigned)Hs)
            v = base[(size_t)BB*COUT*loff + ((size_t)b*COUT + c)*Ls + y*Hs + x];
    }
    __nv_bfloat16 hh, lo; split2(v, hh, lo);
    size_t o = ((size_t)b*K18 + j)*LTP + l;
    RWth[o] = hh; RWtl[o] = lo;
}

// ---------------- bf16x3 mma.sync GEMM: CTA 128x256, warp 64x64, 3-stage ----------------
#define AP 10240
#define BP 20480
#define STG (2*AP + 2*BP)
#define NSTG 3

#define LDSM4(R, addr) asm volatile( \
    "ldmatrix.sync.aligned.m8n8.x4.shared.b16 {%0,%1,%2,%3},[%4];" \
    : "=r"((R)[0]),"=r"((R)[1]),"=r"((R)[2]),"=r"((R)[3]) : "r"(addr))
#define MMA16816(d, a, b0, b1) asm volatile( \
    "mma.sync.aligned.m16n8k16.row.col.f32.bf16.bf16.f32 " \
    "{%0,%1,%2,%3},{%4,%5,%6,%7},{%8,%9},{%0,%1,%2,%3};" \
    : "+f"((d)[0]),"+f"((d)[1]),"+f"((d)[2]),"+f"((d)[3]) \
    : "r"((a)[0]),"r"((a)[1]),"r"((a)[2]),"r"((a)[3]),"r"(b0),"r"(b1))
#define CPA16(dst, src) asm volatile( \
    "cp.async.cg.shared.global [%0],[%1],16;" :: "r"(dst),"l"(src))

__global__ __launch_bounds__(256, 1) void gemm3_kernel(
    const __nv_bfloat16* __restrict__ Ah, const __nv_bfloat16* __restrict__ Al,
    const __nv_bfloat16* __restrict__ Bh, const __nv_bfloat16* __restrict__ Bl,
    float* __restrict__ C, int lda, int ldb, int KIT,
    size_t sA, size_t sB, size_t sC)
{
    extern __shared__ char smem[];
    int b = blockIdx.z;
    const __nv_bfloat16* pAh = Ah + (size_t)b*sA;
    const __nv_bfloat16* pAl = Al + (size_t)b*sA;
    const __nv_bfloat16* pBh = Bh + (size_t)b*sB;
    const __nv_bfloat16* pBl = Bl + (size_t)b*sB;
    float* pC = C + (size_t)b*sC;
    int row0 = blockIdx.y*128, col0 = blockIdx.x*256;
    int tid = threadIdx.x, lane = tid & 31, wid = tid >> 5;
    int wm = (wid >> 2)*64, wn = (wid & 3)*64;
    uint32_t sb = (uint32_t)__cvta_generic_to_shared(smem);

    float acc[4][8][4];
    #pragma unroll
    for (int i = 0; i < 4; i++)
        #pragma unroll
        for (int j = 0; j < 8; j++)
            #pragma unroll
            for (int r = 0; r < 4; r++) acc[i][j][r] = 0.f;

    auto issue = [&](int it) {
        uint32_t st = sb + (uint32_t)(it % NSTG)*STG;
        int k0 = it << 5;
        #pragma unroll
        for (int q = 0; q < 4; q++) {
            int v = tid + q*256;
            int pl = v >> 9, r = (v >> 2) & 127, kv = v & 3;
            const __nv_bfloat16* src = (pl ? pAl : pAh) + (size_t)(row0 + r)*lda + k0 + kv*8;
            CPA16(st + pl*AP + (uint32_t)(r*80 + kv*16), src);
        }
        #pragma unroll
        for (int q = 0; q < 8; q++) {
            int v = tid + q*256;
            int pl = v >> 10, n = (v >> 2) & 255, kv = v & 3;
            const __nv_bfloat16* src = (pl ? pBl : pBh) + (size_t)(col0 + n)*ldb + k0 + kv*8;
            CPA16(st + 2*AP + pl*BP + (uint32_t)(n*80 + kv*16), src);
        }
    };

    issue(0);
    asm volatile("cp.async.commit_group;");
    issue(1);
    asm volatile("cp.async.commit_group;");

    for (int it = 0; it < KIT; it++) {
        if (it == KIT - 1) asm volatile("cp.async.wait_group 0;");
        else               asm volatile("cp.async.wait_group 1;");
        __syncthreads();
        if (it + 2 < KIT) {
            issue(it + 2);
            asm volatile("cp.async.commit_group;");
        }
        uint32_t st = sb + (uint32_t)(it % NSTG)*STG;
        #pragma unroll
        for (int ks = 0; ks < 2; ks++) {
            int koff = ks*16;
            uint32_t ah[4][4], al_[4][4];
            #pragma unroll
            for (int i = 0; i < 4; i++) {
                uint32_t addr = st + (uint32_t)((wm + i*16 + (lane & 15))*80
                                  + (koff + ((lane >> 4) << 3))*2);
                LDSM4(ah[i], addr);
                LDSM4(al_[i], addr + AP);
            }
            uint32_t bf[2][2][4];
            #pragma unroll
            for (int kh = 0; kh < 2; kh++)
                #pragma unroll
                for (int g = 0; g < 2; g++) {
                    uint32_t addr = st + 2*AP
                        + (uint32_t)((wn + g*32 + lane)*80 + (koff + kh*8)*2);
                    LDSM4(bf[kh][g], addr);
                }
            #pragma unroll
            for (int i = 0; i < 4; i++)
                #pragma unroll
                for (int j = 0; j < 8; j++)
                    MMA16816(acc[i][j], ah[i], bf[0][j>>2][j&3], bf[1][j>>2][j&3]);
            #pragma unroll
            for (int i = 0; i < 4; i++)
                #pragma unroll
                for (int j = 0; j < 8; j++)
                    MMA16816(acc[i][j], al_[i], bf[0][j>>2][j&3], bf[1][j>>2][j&3]);
            #pragma unroll
            for (int kh = 0; kh < 2; kh++)
                #pragma unroll
                for (int g = 0; g < 2; g++) {
                    uint32_t addr = st + 2*AP + BP
                        + (uint32_t)((wn + g*32 + lane)*80 + (koff + kh*8)*2);
                    LDSM4(bf[kh][g], addr);
                }
            #pragma unroll
            for (int i = 0; i < 4; i++)
                #pragma unroll
                for (int j = 0; j < 8; j++)
                    MMA16816(acc[i][j], ah[i], bf[0][j>>2][j&3], bf[1][j>>2][j&3]);
        }
    }

    #pragma unroll
    for (int i = 0; i < 4; i++) {
        int r = row0 + wm + i*16 + (lane >> 2);
        #pragma unroll
        for (int j = 0; j < 8; j++) {
            int c = col0 + wn + j*8 + ((lane & 3) << 1);
            *(float2*)&pC[(size_t)r*4096 + c] = make_float2(acc[i][j][0], acc[i][j][1]);
            *(float2*)&pC[(size_t)(r+8)*4096 + c] = make_float2(acc[i][j][2], acc[i][j][3]);
        }
    }
}

// ---------------- softmax pass 1 (stores exp in place) ----------------
__global__ void softmax_part_kernel(float* __restrict__ scores,
                                    float* __restrict__ pmax, float* __restrict__ psum) {
    int p = blockIdx.x*256 + threadIdx.x;
    int c = blockIdx.y, b = blockIdx.z;
    int l0 = c*SCH, l1 = l0 + SCH; if (l1 > LT) l1 = LT;
    float* s = scores + (size_t)b*LTP*P + p;
    float m = -1e30f;
    for (int l = l0; l < l1; l++) m = fmaxf(m, s[(size_t)l*P]);
    float sum = 0.f;
    for (int l = l0; l < l1; l++) {
        float e = __expf(10.f*(s[(size_t)l*P] - m));
        s[(size_t)l*P] = e;
        sum += e;
    }
    pmax[((size_t)b*NCH + c)*P + p] = m;
    psum[((size_t)b*NCH + c)*P + p] = sum;
}

__global__ void softmax_comb_kernel(const float* __restrict__ pmax, float* __restrict__ psum) {
    int p = blockIdx.x*256 + threadIdx.x; int b = blockIdx.y;
    float M = -1e30f;
    for (int c = 0; c < NCH; c++) M = fmaxf(M, pmax[((size_t)b*NCH + c)*P + p]);
    float S = 0.f;
    for (int c = 0; c < NCH; c++)
        S += psum[((size_t)b*NCH + c)*P + p] * __expf(10.f*(pmax[((size_t)b*NCH + c)*P + p] - M));
    float invS = 1.0f / S;
    for (int c = 0; c < NCH; c++)
        psum[((size_t)b*NCH + c)*P + p] =
            __expf(10.f*(pmax[((size_t)b*NCH + c)*P + p] - M)) * invS;
}

// pass 3: rescale + transpose -> attT[b][p][l] bf16 hi/lo
__global__ void attT_kernel(const float* __restrict__ scores, const float* __restrict__ psum,
                            __nv_bfloat16* __restrict__ Th, __nv_bfloat16* __restrict__ Tl) {
    __shared__ float t[32][33];
    int p0 = blockIdx.x*32, l0 = blockIdx.y*32, b = blockIdx.z;
    int tx = threadIdx.x, ty = threadIdx.y;
    #pragma unroll
    for (int i = 0; i < 4; i++) {
        int l = l0 + ty + i*8;
        float v = 0.f;
        if (l < LT)
            v = scores[((size_t)b*LTP + l)*P + p0 + tx] *
                psum[((size_t)b*NCH + l/SCH)*P + p0 + tx];
        t[ty + i*8][tx] = v;
    }
    __syncthreads();
    #pragma unroll
    for (int i = 0; i < 4; i++) {
        int p = p0 + ty + i*8;
        float v = t[tx][ty + i*8];
        __nv_bfloat16 hh, lo; split2(v, hh, lo);
        size_t o = ((size_t)b*P + p)*LTP + l0 + tx;
        Th[o] = hh; Tl[o] = lo;
    }
}

// ---------------- col2im + residual ----------------
__global__ void col2im_kernel(const float* __restrict__ T, const float* __restrict__ h2,
                              float* __restrict__ out) {
    int idx = blockIdx.x*blockDim.x + threadIdx.x;
    if (idx >= BB*COUT*P) return;
    int w = idx % H; int hh = (idx / H) % H; int c = (idx / P) % COUT; int b = idx / (P*COUT);
    float acc = 0.f;
    #pragma unroll
    for (int a = 0; a < 3; a++) {
        int y = hh + 1 - a;
        if ((unsigned)y >= H) continue;
        #pragma unroll
        for (int d = 0; d < 3; d++) {
            int x = w + 1 - d;
            if ((unsigned)x >= H) continue;
            acc += T[((size_t)b*K18 + c*9 + a*3 + d)*P + y*H + x];
        }
    }
    out[idx] = h2[idx] + 0.25f*acc;
}

// ---------------- launch ----------------
extern "C" void kernel_launch(void* const* d_in, const int* in_sizes, int n_in,
                              void* d_out, int out_size) {
    (void)in_sizes; (void)n_in; (void)out_size;
    const float* x      = (const float*)d_in[0];
    const float* bb0_w  = (const float*)d_in[1];
    const float* bb0_b  = (const float*)d_in[2];
    const float* bb0_a  = (const float*)d_in[3];
    const float* rb1_w1 = (const float*)d_in[4];
    const float* rb1_b1 = (const float*)d_in[5];
    const float* rb1_w2 = (const float*)d_in[6];
    const float* rb1_b2 = (const float*)d_in[7];
    const float* pamb_w = (const float*)d_in[8];
    const float* pamb_b = (const float*)d_in[9];
    const float* pamb_a = (const float*)d_in[10];
    const float* pam_w  = (const float*)d_in[11];
    const float* pam_b  = (const float*)d_in[12];
    const float* pam_a  = (const float*)d_in[13];
    const float* paa_w  = (const float*)d_in[14];
    const float* paa_b  = (const float*)d_in[15];
    const float* paa_a  = (const float*)d_in[16];
    const float* rb2_w1 = (const float*)d_in[17];
    const float* rb2_b1 = (const float*)d_in[18];
    const float* rb2_w2 = (const float*)d_in[19];
    const float* rb2_b2 = (const float*)d_in[20];
    float* out = (float*)d_out;

    float *h0,*h1,*h2,*tmp,*h3,*mb,*ref,*base,*refm,*scores,*T,*pmax,*psum;
    __nv_bfloat16 *ICh,*ICl,*Awh,*Awl,*WNh,*WNl,*RWth,*RWtl,*attTh,*attTl;
    cudaGetSymbolAddress((void**)&h0, g_h0);
    cudaGetSymbolAddress((void**)&h1, g_h1);
    cudaGetSymbolAddress((void**)&h2, g_h2);
    cudaGetSymbolAddress((void**)&tmp, g_tmp);
    cudaGetSymbolAddress((void**)&h3, g_h3);
    cudaGetSymbolAddress((void**)&mb, g_mb);
    cudaGetSymbolAddress((void**)&ref, g_ref);
    cudaGetSymbolAddress((void**)&base, g_base);
    cudaGetSymbolAddress((void**)&refm, g_refm);
    cudaGetSymbolAddress((void**)&scores, g_scores);
    cudaGetSymbolAddress((void**)&T, g_T);
    cudaGetSymbolAddress((void**)&ICh, g_ICh);
    cudaGetSymbolAddress((void**)&ICl, g_ICl);
    cudaGetSymbolAddress((void**)&Awh, g_Awh);
    cudaGetSymbolAddress((void**)&Awl, g_Awl);
    cudaGetSymbolAddress((void**)&WNh, g_WNh);
    cudaGetSymbolAddress((void**)&WNl, g_WNl);
    cudaGetSymbolAddress((void**)&RWth, g_RWth);
    cudaGetSymbolAddress((void**)&RWtl, g_RWtl);
    cudaGetSymbolAddress((void**)&attTh, g_attTh);
    cudaGetSymbolAddress((void**)&attTl, g_attTl);
    cudaGetSymbolAddress((void**)&pmax, g_pmax);
    cudaGetSymbolAddress((void**)&psum, g_psum);

    cudaFuncSetAttribute(gemm3_kernel, cudaFuncAttributeMaxDynamicSharedMemorySize, NSTG*STG);

    float* Craw = scores;
    auto conv3g = [&](const float* in, const float* w, const float* bias,
                      const float* alpha, const float* res, float* o, int Ci, int act) {
        int K = Ci*9;
        wsplit_kernel<<<(COUT*K + 255)/256, 256>>>(w, Awh, Awl, COUT*K);
        if (Ci == CIN)
            imcol_kernel<CIN><<<dim3((P*CIN*9 + 255)/256, BB), 256>>>(in, ICh, ICl);
        else
            imcol_kernel<COUT><<<dim3((P*COUT*9 + 255)/256, BB), 256>>>(in, ICh, ICl);
        gemm3_kernel<<<dim3(P/256, 1, BB), 256, NSTG*STG>>>(
            Awh, Awl, ICh, ICl, Craw, K, K, K/32,
            0, (size_t)P*K, (size_t)COUT*P);
        epi_kernel<<<(BB*COUT*P + 255)/256, 256>>>(Craw, bias, alpha, res, o, act);
    };

    maxpool_kernel<<<(BB*CIN*P + 255)/256, 256>>>(x, h0);
    conv3g(h0, bb0_w, bb0_b, bb0_a, nullptr, h1, CIN, 2);
    conv3g(h1, rb1_w1, rb1_b1, nullptr, nullptr, tmp, COUT, 1);
    conv3g(tmp, rb1_w2, rb1_b2, nullptr, h1, h2, COUT, 0);

    conv1_kernel<<<dim3(P/256, CHALF/4, BB), 256>>>(h2, pamb_w, pamb_b, pamb_a, mb, COUT, CHALF, P);
    imcol_kernel<CHALF><<<dim3((P*K9 + 255)/256, BB), 256>>>(mb, ICh, ICl);   // XPT

    const int Hs[4]   = {64, 57, 51, 44};
    const int loff[4] = {0, 4096, 7345, 9946};
    for (int s = 0; s < 4; s++) {
        int Ls = Hs[s]*Hs[s];
        const float* refp;
        if (s == 0) refp = h2;
        else {
            int n = BB*COUT*Ls;
            resize_kernel<<<(n + 255)/256, 256>>>(h2, ref, Hs[s]);
            refp = ref;
        }
        conv1_kernel<<<dim3((Ls + 255)/256, COUT/4, BB), 256>>>(
            refp, paa_w, paa_b, paa_a, base + (size_t)BB*COUT*loff[s], COUT, COUT, Ls);
        conv1_kernel<<<dim3((Ls + 255)/256, CHALF/4, BB), 256>>>(
            refp, pam_w, pam_b, pam_a, refm + (size_t)BB*CHALF*loff[s], COUT, CHALF, Ls);
    }

    wn_kernel<<<dim3(LTP, BB), 128>>>(refm, WNh, WNl);
    rwt_kernel<<<dim3((LTP + 255)/256, K18, BB), 256>>>(base, RWth, RWtl);

    // scores[l][p] = WN[l][:] . XPT[p][:]   (M=LTP, N=4096, K=576)
    gemm3_kernel<<<dim3(P/256, LTP/128, BB), 256, NSTG*STG>>>(
        WNh, WNl, ICh, ICl, scores, K9, K9, K9/32,
        (size_t)LTP*K9, (size_t)P*K9, (size_t)LTP*P);

    softmax_part_kernel<<<dim3(P/256, NCH, BB), 256>>>(scores, pmax, psum);
    softmax_comb_kernel<<<dim3(P/256, BB), 256>>>(pmax, psum);
    attT_kernel<<<dim3(P/32, LTP/32, BB), dim3(32,8)>>>(scores, psum, attTh, attTl);

    // T[j][p] = RWt[j][:] . attT[p][:]   (M=1152, N=4096, K=LTP)
    gemm3_kernel<<<dim3(P/256, K18/128, BB), 256, NSTG*STG>>>(
        RWth, RWtl, attTh, attTl, T, LTP, LTP, LTP/32,
        (size_t)K18*LTP, (size_t)P*LTP, (size_t)K18*P);

    col2im_kernel<<<(BB*COUT*P + 255)/256, 256>>>(T, h2, h3);

    conv3g(h3, rb2_w1, rb2_b1, nullptr, nullptr, tmp, COUT, 1);
    conv3g(tmp, rb2_w2, rb2_b2, nullptr, h3, out, COUT, 0);
}

// round 12
// speedup vs baseline: 3.3416x; 1.0977x over previous
#include <cuda_runtime.h>
#include <cuda_bf16.h>
#include <cstdint>

// ---------------- dims ----------------
#define BB 2
#define CIN 64
#define COUT 128
#define CHALF 64
#define HIN 128
#define H 64
#define P (H*H)          // 4096
#define LT 11882
#define LTP 11904        // 93*128
#define K9 576
#define K18 1152
#define NCH 32
#define SCH 372

// ---------------- scratch ----------------
__device__ __align__(128) float g_h0[BB*CIN*P];
__device__ __align__(128) float g_h1[BB*COUT*P];
__device__ __align__(128) float g_h2[BB*COUT*P];
__device__ __align__(128) float g_tmp[BB*COUT*P];
__device__ __align__(128) float g_h3[BB*COUT*P];
__device__ __align__(128) float g_mb[BB*CHALF*P];
__device__ __align__(128) float g_ref[BB*COUT*3249];
__device__ __align__(128) float g_base[(size_t)BB*COUT*LT];
__device__ __align__(128) float g_refm[(size_t)BB*CHALF*LT];
__device__ __align__(128) float g_scores[(size_t)BB*LTP*P];   // also conv Craw/Craw2 scratch
__device__ __align__(128) float g_T[(size_t)BB*K18*P];
__device__ __align__(128) __nv_bfloat16 g_ICh[(size_t)BB*P*K18];
__device__ __align__(128) __nv_bfloat16 g_ICl[(size_t)BB*P*K18];
__device__ __align__(128) __nv_bfloat16 g_Awh[COUT*K18];
__device__ __align__(128) __nv_bfloat16 g_Awl[COUT*K18];
__device__ __align__(128) __nv_bfloat16 g_WNh[(size_t)BB*LTP*K9];
__device__ __align__(128) __nv_bfloat16 g_WNl[(size_t)BB*LTP*K9];
__device__ __align__(128) __nv_bfloat16 g_RWth[(size_t)BB*K18*LTP];
__device__ __align__(128) __nv_bfloat16 g_RWtl[(size_t)BB*K18*LTP];
__device__ __align__(128) __nv_bfloat16 g_attTh[(size_t)BB*P*LTP];
__device__ __align__(128) __nv_bfloat16 g_attTl[(size_t)BB*P*LTP];
__device__ __align__(128) float g_pmax[BB*NCH*P];
__device__ __align__(128) float g_psum[BB*NCH*P];

__device__ __forceinline__ void split2(float v, __nv_bfloat16& h, __nv_bfloat16& l) {
    h = __float2bfloat16(v);
    l = __float2bfloat16(v - __bfloat162float(h));
}

// ---------------- maxpool ----------------
__global__ void maxpool_kernel(const float* __restrict__ in, float* __restrict__ out) {
    int idx = blockIdx.x*blockDim.x + threadIdx.x;
    if (idx >= BB*CIN*P) return;
    int x = idx % H; int y = (idx / H) % H; int bc = idx / P;
    const float* p = in + ((size_t)bc*HIN + 2*y)*HIN + 2*x;
    out[idx] = fmaxf(fmaxf(p[0], p[1]), fmaxf(p[HIN], p[HIN+1]));
}

// ---------------- im2col (3x3 pad1), Ci compile-time ----------------
template<int Ci>
__global__ void imcol_kernel(const float* __restrict__ in,
                             __nv_bfloat16* __restrict__ Xh, __nv_bfloat16* __restrict__ Xl) {
    constexpr int K = Ci*9;
    int idx = blockIdx.x*256 + threadIdx.x;
    int b = blockIdx.y;
    if (idx >= P*K) return;
    int k = idx % K; int p = idx / K;
    int c = k/9, r = k%9; int ky = r/3, kx = r - ky*3;
    int y = (p >> 6) + ky - 1, x = (p & 63) + kx - 1;
    float v = 0.f;
    if ((unsigned)y < H && (unsigned)x < H) v = in[((size_t)b*Ci + c)*P + y*H + x];
    __nv_bfloat16 hh, ll; split2(v, hh, ll);
    size_t o = (size_t)b*P*K + idx;
    Xh[o] = hh; Xl[o] = ll;
}

// ---------------- weight split ----------------
__global__ void wsplit_kernel(const float* __restrict__ w,
                              __nv_bfloat16* __restrict__ Ah, __nv_bfloat16* __restrict__ Al,
                              int n) {
    int idx = blockIdx.x*256 + threadIdx.x;
    if (idx >= n) return;
    __nv_bfloat16 hh, ll; split2(w[idx], hh, ll);
    Ah[idx] = hh; Al[idx] = ll;
}

// ---------------- conv epilogue: sum split-K partials + bias + act + residual ----------------
__global__ void epi_kernel(const float* __restrict__ Craw, const float* __restrict__ Craw2,
                           const float* __restrict__ bias,
                           const float* __restrict__ alpha_p, const float* __restrict__ res,
                           float* __restrict__ out, int act) {
    int idx = blockIdx.x*256 + threadIdx.x;
    if (idx >= BB*COUT*P) return;
    int co = (idx / P) % COUT;
    float v = Craw[idx] + Craw2[idx] + bias[co];
    if (act == 1) v = fmaxf(v, 0.f);
    else if (act == 2) { float a = *alpha_p; v = v >= 0.f ? v : a*v; }
    if (res) v += res[idx];
    out[idx] = v;
}

// ---------------- 1x1 conv + PReLU, 4 outputs per block ----------------
__global__ void conv1_kernel(const float* __restrict__ in, const float* __restrict__ w,
                             const float* __restrict__ bias, const float* __restrict__ alpha_p,
                             float* __restrict__ out, int Ci, int Co, int Pn) {
    int p = blockIdx.x*256 + threadIdx.x;
    int o0 = blockIdx.y*4, b = blockIdx.z;
    if (p >= Pn) return;
    const float* ip = in + (size_t)b*Ci*Pn + p;
    float acc[4];
    #pragma unroll
    for (int o = 0; o < 4; o++) acc[o] = bias[o0 + o];
    #pragma unroll 4
    for (int i = 0; i < Ci; i++) {
        float t = ip[(size_t)i*Pn];
        #pragma unroll
        for (int o = 0; o < 4; o++) acc[o] += w[(size_t)(o0+o)*Ci + i] * t;
    }
    float a = *alpha_p;
    #pragma unroll
    for (int o = 0; o < 4; o++) {
        float v = acc[o];
        out[((size_t)b*Co + o0 + o)*Pn + p] = v >= 0.f ? v : a*v;
    }
}

// ---------------- bilinear resize with antialias ----------------
__global__ void resize_kernel(const float* __restrict__ in, float* __restrict__ out, int Hout) {
    int total = BB*COUT*Hout*Hout;
    int idx = blockIdx.x*blockDim.x + threadIdx.x;
    if (idx >= total) return;
    int xo = idx % Hout; int yo = (idx / Hout) % Hout; int bc = idx / (Hout*Hout);
    float inv = (float)H / (float)Hout;
    float sy = (yo + 0.5f)*inv - 0.5f;
    float sx = (xo + 0.5f)*inv - 0.5f;
    float wy[4], wx[4]; int jy[4], jx[4];
    int ny = 0, nx = 0; float sumy = 0.f, sumx = 0.f;
    int lo = (int)ceilf(sy - inv), hi = (int)floorf(sy + inv);
    if (lo < 0) lo = 0; if (hi > H-1) hi = H-1;
    for (int j = lo; j <= hi && ny < 4; j++) {
        float w = 1.0f - fabsf(sy - (float)j)/inv;
        if (w > 0.f) { wy[ny] = w; jy[ny] = j; sumy += w; ny++; }
    }
    lo = (int)ceilf(sx - inv); hi = (int)floorf(sx + inv);
    if (lo < 0) lo = 0; if (hi > H-1) hi = H-1;
    for (int j = lo; j <= hi && nx < 4; j++) {
        float w = 1.0f - fabsf(sx - (float)j)/inv;
        if (w > 0.f) { wx[nx] = w; jx[nx] = j; sumx += w; nx++; }
    }
    const float* ip = in + (size_t)bc*P;
    float acc = 0.f;
    for (int a = 0; a < ny; a++)
        for (int bx2 = 0; bx2 < nx; bx2++)
            acc += wy[a]*wx[bx2]*ip[jy[a]*H + jx[bx2]];
    out[idx] = acc / (sumy*sumx);
}

__device__ __forceinline__ void decode_l(int l, int& Hs, int& loff) {
    if (l < 4096)      { Hs = 64; loff = 0; }
    else if (l < 7345) { Hs = 57; loff = 4096; }
    else if (l < 9946) { Hs = 51; loff = 7345; }
    else               { Hs = 44; loff = 9946; }
}

// ---------------- normalized key patches WN[b][l][k], rows 0..LTP (pad zero) ----------------
__global__ void wn_kernel(const float* __restrict__ refm,
                          __nv_bfloat16* __restrict__ WNh, __nv_bfloat16* __restrict__ WNl) {
    int l = blockIdx.x, b = blockIdx.y;
    int tid = threadIdx.x;
    size_t obase = ((size_t)b*LTP + l)*K9;
    if (l >= LT) {
        for (int k = tid; k < K9; k += 128) {
            WNh[obase + k] = __float2bfloat16(0.f);
            WNl[obase + k] = __float2bfloat16(0.f);
        }
        return;
    }
    int Hs, loff; decode_l(l, Hs, loff);
    int Ls = Hs*Hs; int ll = l - loff; int lh = ll/Hs, lw = ll%Hs;
    const float* rp = refm + (size_t)BB*CHALF*loff + (size_t)b*CHALF*Ls;
    __shared__ float vals[K9];
    __shared__ float red[128];
    float ss = 0.f;
    for (int k = tid; k < K9; k += 128) {
        int c = k/9, r = k%9; int ky = r/3, kx = r%3;
        int y = lh + ky - 1, x = lw + kx - 1;
        float v = 0.f;
        if ((unsigned)y < (unsigned)Hs && (unsigned)x < (unsigned)Hs) v = rp[(size_t)c*Ls + y*Hs + x];
        vals[k] = v; ss += v*v;
    }
    red[tid] = ss; __syncthreads();
    for (int o = 64; o > 0; o >>= 1) { if (tid < o) red[tid] += red[tid+o]; __syncthreads(); }
    float rn = 1.0f / fmaxf(sqrtf(red[0]), 1e-4f);
    for (int k = tid; k < K9; k += 128) {
        __nv_bfloat16 hh, lo; split2(vals[k]*rn, hh, lo);
        WNh[obase + k] = hh; WNl[obase + k] = lo;
    }
}

// ---------------- assembly patches RWt[b][j][LTP] (pad zero) ----------------
__global__ void rwt_kernel(const float* __restrict__ base,
                           __nv_bfloat16* __restrict__ RWth, __nv_bfloat16* __restrict__ RWtl) {
    int l = blockIdx.x*blockDim.x + threadIdx.x;
    if (l >= LTP) return;
    int j = blockIdx.y, b = blockIdx.z;
    float v = 0.f;
    if (l < LT) {
        int c = j/9, r = j%9; int ky = r/3, kx = r%3;
        int Hs, loff; decode_l(l, Hs, loff);
        int Ls = Hs*Hs; int ll = l - loff; int lh = ll/Hs, lw = ll%Hs;
        int y = lh + ky - 1, x = lw + kx - 1;
        if ((unsigned)y < (unsigned)Hs && (unsigned)x < (unsigned)Hs)
            v = base[(size_t)BB*COUT*loff + ((size_t)b*COUT + c)*Ls + y*Hs + x];
    }
    __nv_bfloat16 hh, lo; split2(v, hh, lo);
    size_t o = ((size_t)b*K18 + j)*LTP + l;
    RWth[o] = hh; RWtl[o] = lo;
}

// ---------------- bf16x3 mma.sync GEMM: CTA 128x128, warp 64x32, 2-stage, occ 2 ----------------
// A[m][k], B[n][k] K-major (80B smem rows). C[m][n] fp32, ldc=4096.
// blockIdx.z encodes (batch, split-k half): half = z % nsplit, b = z / nsplit.
#define AP2 10240                 // 128 rows * 80B per plane
#define STG2 (4*AP2)              // Ah | Al | Bh | Bl = 40960 per stage
#define NSTG2 2

#define LDSM4(R, addr) asm volatile( \
    "ldmatrix.sync.aligned.m8n8.x4.shared.b16 {%0,%1,%2,%3},[%4];" \
    : "=r"((R)[0]),"=r"((R)[1]),"=r"((R)[2]),"=r"((R)[3]) : "r"(addr))
#define MMA16816(d, a, b0, b1) asm volatile( \
    "mma.sync.aligned.m16n8k16.row.col.f32.bf16.bf16.f32 " \
    "{%0,%1,%2,%3},{%4,%5,%6,%7},{%8,%9},{%0,%1,%2,%3};" \
    : "+f"((d)[0]),"+f"((d)[1]),"+f"((d)[2]),"+f"((d)[3]) \
    : "r"((a)[0]),"r"((a)[1]),"r"((a)[2]),"r"((a)[3]),"r"(b0),"r"(b1))
#define CPA16(dst, src) asm volatile( \
    "cp.async.cg.shared.global [%0],[%1],16;" :: "r"(dst),"l"(src))

__global__ __launch_bounds__(256, 2) void gemm3_kernel(
    const __nv_bfloat16* __restrict__ Ah, const __nv_bfloat16* __restrict__ Al,
    const __nv_bfloat16* __restrict__ Bh, const __nv_bfloat16* __restrict__ Bl,
    float* __restrict__ C, int lda, int ldb, int KIT,
    size_t sA, size_t sB, size_t sC,
    int nsplit, int koffE, size_t sSplit)
{
    extern __shared__ char smem[];
    int zz = blockIdx.z;
    int half = zz % nsplit, b = zz / nsplit;
    int kofs = half * koffE;
    const __nv_bfloat16* pAh = Ah + (size_t)b*sA + kofs;
    const __nv_bfloat16* pAl = Al + (size_t)b*sA + kofs;
    const __nv_bfloat16* pBh = Bh + (size_t)b*sB + kofs;
    const __nv_bfloat16* pBl = Bl + (size_t)b*sB + kofs;
    float* pC = C + (size_t)b*sC + (size_t)half*sSplit;
    int row0 = blockIdx.y*128, col0 = blockIdx.x*128;
    int tid = threadIdx.x, lane = tid & 31, wid = tid >> 5;
    int wm = (wid >> 2)*64, wn = (wid & 3)*32;
    uint32_t sb = (uint32_t)__cvta_generic_to_shared(smem);

    float acc[4][4][4];
    #pragma unroll
    for (int i = 0; i < 4; i++)
        #pragma unroll
        for (int j = 0; j < 4; j++)
            #pragma unroll
            for (int r = 0; r < 4; r++) acc[i][j][r] = 0.f;

    auto issue = [&](int it) {
        uint32_t st = sb + (uint32_t)(it & 1)*STG2;
        int k0 = it << 5;
        #pragma unroll
        for (int q = 0; q < 4; q++) {           // A: 1024 chunks of 16B
            int v = tid + q*256;
            int pl = v >> 9, r = (v >> 2) & 127, kv = v & 3;
            const __nv_bfloat16* src = (pl ? pAl : pAh) + (size_t)(row0 + r)*lda + k0 + kv*8;
            CPA16(st + pl*AP2 + (uint32_t)(r*80 + kv*16), src);
        }
        #pragma unroll
        for (int q = 0; q < 4; q++) {           // B: 1024 chunks
            int v = tid + q*256;
            int pl = v >> 9, n = (v >> 2) & 127, kv = v & 3;
            const __nv_bfloat16* src = (pl ? pBl : pBh) + (size_t)(col0 + n)*ldb + k0 + kv*8;
            CPA16(st + 2*AP2 + pl*AP2 + (uint32_t)(n*80 + kv*16), src);
        }
    };

    issue(0);
    asm volatile("cp.async.commit_group;");

    for (int it = 0; it < KIT; it++) {
        if (it + 1 < KIT) {
            __syncthreads();                      // compute(it-1) done before overwriting its stage
            issue(it + 1);
            asm volatile("cp.async.commit_group;");
            asm volatile("cp.async.wait_group 1;");
        } else {
            asm volatile("cp.async.wait_group 0;");
        }
        __syncthreads();
        uint32_t st = sb + (uint32_t)(it & 1)*STG2;
        #pragma unroll
        for (int ks = 0; ks < 2; ks++) {
            int koff = ks*16;
            uint32_t ah[4][4], al_[4][4];
            #pragma unroll
            for (int i = 0; i < 4; i++) {
                uint32_t addr = st + (uint32_t)((wm + i*16 + (lane & 15))*80
                                  + (koff + ((lane >> 4) << 3))*2);
                LDSM4(ah[i], addr);
                LDSM4(al_[i], addr + AP2);
            }
            uint32_t bf0[4], bf1[4];
            {
                uint32_t addr = st + 2*AP2 + (uint32_t)((wn + lane)*80 + koff*2);
                LDSM4(bf0, addr);
                LDSM4(bf1, addr + 16);            // koff+8 k-pair
            }
            #pragma unroll
            for (int i = 0; i < 4; i++)
                #pragma unroll
                for (int j = 0; j < 4; j++)
                    MMA16816(acc[i][j], ah[i], bf0[j], bf1[j]);
            #pragma unroll
            for (int i = 0; i < 4; i++)
                #pragma unroll
                for (int j = 0; j < 4; j++)
                    MMA16816(acc[i][j], al_[i], bf0[j], bf1[j]);
            {
                uint32_t addr = st + 3*AP2 + (uint32_t)((wn + lane)*80 + koff*2);
                LDSM4(bf0, addr);
                LDSM4(bf1, addr + 16);
            }
            #pragma unroll
            for (int i = 0; i < 4; i++)
                #pragma unroll
                for (int j = 0; j < 4; j++)
                    MMA16816(acc[i][j], ah[i], bf0[j], bf1[j]);
        }
    }

    #pragma unroll
    for (int i = 0; i < 4; i++) {
        int r = row0 + wm + i*16 + (lane >> 2);
        #pragma unroll
        for (int j = 0; j < 4; j++) {
            int c = col0 + wn + j*8 + ((lane & 3) << 1);
            *(float2*)&pC[(size_t)r*4096 + c] = make_float2(acc[i][j][0], acc[i][j][1]);
            *(float2*)&pC[(size_t)(r+8)*4096 + c] = make_float2(acc[i][j][2], acc[i][j][3]);
        }
    }
}

// ---------------- softmax pass 1 (stores exp in place) ----------------
__global__ void softmax_part_kernel(float* __restrict__ scores,
                                    float* __restrict__ pmax, float* __restrict__ psum) {
    int p = blockIdx.x*256 + threadIdx.x;
    int c = blockIdx.y, b = blockIdx.z;
    int l0 = c*SCH, l1 = l0 + SCH; if (l1 > LT) l1 = LT;
    float* s = scores + (size_t)b*LTP*P + p;
    float m = -1e30f;
    for (int l = l0; l < l1; l++) m = fmaxf(m, s[(size_t)l*P]);
    float sum = 0.f;
    for (int l = l0; l < l1; l++) {
        float e = __expf(10.f*(s[(size_t)l*P] - m));
        s[(size_t)l*P] = e;
        sum += e;
    }
    pmax[((size_t)b*NCH + c)*P + p] = m;
    psum[((size_t)b*NCH + c)*P + p] = sum;
}

__global__ void softmax_comb_kernel(const float* __restrict__ pmax, float* __restrict__ psum) {
    int p = blockIdx.x*256 + threadIdx.x; int b = blockIdx.y;
    float M = -1e30f;
    for (int c = 0; c < NCH; c++) M = fmaxf(M, pmax[((size_t)b*NCH + c)*P + p]);
    float S = 0.f;
    for (int c = 0; c < NCH; c++)
        S += psum[((size_t)b*NCH + c)*P + p] * __expf(10.f*(pmax[((size_t)b*NCH + c)*P + p] - M));
    float invS = 1.0f / S;
    for (int c = 0; c < NCH; c++)
        psum[((size_t)b*NCH + c)*P + p] =
            __expf(10.f*(pmax[((size_t)b*NCH + c)*P + p] - M)) * invS;
}

// pass 3: rescale + transpose -> attT[b][p][l] bf16 hi/lo
__global__ void attT_kernel(const float* __restrict__ scores, const float* __restrict__ psum,
                            __nv_bfloat16* __restrict__ Th, __nv_bfloat16* __restrict__ Tl) {
    __shared__ float t[32][33];
    int p0 = blockIdx.x*32, l0 = blockIdx.y*32, b = blockIdx.z;
    int tx = threadIdx.x, ty = threadIdx.y;
    #pragma unroll
    for (int i = 0; i < 4; i++) {
        int l = l0 + ty + i*8;
        float v = 0.f;
        if (l < LT)
            v = scores[((size_t)b*LTP + l)*P + p0 + tx] *
                psum[((size_t)b*NCH + l/SCH)*P + p0 + tx];
        t[ty + i*8][tx] = v;
    }
    __syncthreads();
    #pragma unroll
    for (int i = 0; i < 4; i++) {
        int p = p0 + ty + i*8;
        float v = t[tx][ty + i*8];
        __nv_bfloat16 hh, lo; split2(v, hh, lo);
        size_t o = ((size_t)b*P + p)*LTP + l0 + tx;
        Th[o] = hh; Tl[o] = lo;
    }
}

// ---------------- col2im + residual ----------------
__global__ void col2im_kernel(const float* __restrict__ T, const float* __restrict__ h2,
                              float* __restrict__ out) {
    int idx = blockIdx.x*blockDim.x + threadIdx.x;
    if (idx >= BB*COUT*P) return;
    int w = idx % H; int hh = (idx / H) % H; int c = (idx / P) % COUT; int b = idx / (P*COUT);
    float acc = 0.f;
    #pragma unroll
    for (int a = 0; a < 3; a++) {
        int y = hh + 1 - a;
        if ((unsigned)y >= H) continue;
        #pragma unroll
        for (int d = 0; d < 3; d++) {
            int x = w + 1 - d;
            if ((unsigned)x >= H) continue;
            acc += T[((size_t)b*K18 + c*9 + a*3 + d)*P + y*H + x];
        }
    }
    out[idx] = h2[idx] + 0.25f*acc;
}

// ---------------- launch ----------------
extern "C" void kernel_launch(void* const* d_in, const int* in_sizes, int n_in,
                              void* d_out, int out_size) {
    (void)in_sizes; (void)n_in; (void)out_size;
    const float* x      = (const float*)d_in[0];
    const float* bb0_w  = (const float*)d_in[1];
    const float* bb0_b  = (const float*)d_in[2];
    const float* bb0_a  = (const float*)d_in[3];
    const float* rb1_w1 = (const float*)d_in[4];
    const float* rb1_b1 = (const float*)d_in[5];
    const float* rb1_w2 = (const float*)d_in[6];
    const float* rb1_b2 = (const float*)d_in[7];
    const float* pamb_w = (const float*)d_in[8];
    const float* pamb_b = (const float*)d_in[9];
    const float* pamb_a = (const float*)d_in[10];
    const float* pam_w  = (const float*)d_in[11];
    const float* pam_b  = (const float*)d_in[12];
    const float* pam_a  = (const float*)d_in[13];
    const float* paa_w  = (const float*)d_in[14];
    const float* paa_b  = (const float*)d_in[15];
    const float* paa_a  = (const float*)d_in[16];
    const float* rb2_w1 = (const float*)d_in[17];
    const float* rb2_b1 = (const float*)d_in[18];
    const float* rb2_w2 = (const float*)d_in[19];
    const float* rb2_b2 = (const float*)d_in[20];
    float* out = (float*)d_out;

    float *h0,*h1,*h2,*tmp,*h3,*mb,*ref,*base,*refm,*scores,*T,*pmax,*psum;
    __nv_bfloat16 *ICh,*ICl,*Awh,*Awl,*WNh,*WNl,*RWth,*RWtl,*attTh,*attTl;
    cudaGetSymbolAddress((void**)&h0, g_h0);
    cudaGetSymbolAddress((void**)&h1, g_h1);
    cudaGetSymbolAddress((void**)&h2, g_h2);
    cudaGetSymbolAddress((void**)&tmp, g_tmp);
    cudaGetSymbolAddress((void**)&h3, g_h3);
    cudaGetSymbolAddress((void**)&mb, g_mb);
    cudaGetSymbolAddress((void**)&ref, g_ref);
    cudaGetSymbolAddress((void**)&base, g_base);
    cudaGetSymbolAddress((void**)&refm, g_refm);
    cudaGetSymbolAddress((void**)&scores, g_scores);
    cudaGetSymbolAddress((void**)&T, g_T);
    cudaGetSymbolAddress((void**)&ICh, g_ICh);
    cudaGetSymbolAddress((void**)&ICl, g_ICl);
    cudaGetSymbolAddress((void**)&Awh, g_Awh);
    cudaGetSymbolAddress((void**)&Awl, g_Awl);
    cudaGetSymbolAddress((void**)&WNh, g_WNh);
    cudaGetSymbolAddress((void**)&WNl, g_WNl);
    cudaGetSymbolAddress((void**)&RWth, g_RWth);
    cudaGetSymbolAddress((void**)&RWtl, g_RWtl);
    cudaGetSymbolAddress((void**)&attTh, g_attTh);
    cudaGetSymbolAddress((void**)&attTl, g_attTl);
    cudaGetSymbolAddress((void**)&pmax, g_pmax);
    cudaGetSymbolAddress((void**)&psum, g_psum);

    cudaFuncSetAttribute(gemm3_kernel, cudaFuncAttributeMaxDynamicSharedMemorySize, NSTG2*STG2);

    float* Craw  = scores;
    float* Craw2 = scores + (size_t)BB*COUT*P;
    auto conv3g = [&](const float* in, const float* w, const float* bias,
                      const float* alpha, const float* res, float* o, int Ci, int act) {
        int K = Ci*9, Kh = K/2;     // 288 or 576 (both /32 exact)
        wsplit_kernel<<<(COUT*K + 255)/256, 256>>>(w, Awh, Awl, COUT*K);
        if (Ci == CIN)
            imcol_kernel<CIN><<<dim3((P*CIN*9 + 255)/256, BB), 256>>>(in, ICh, ICl);
        else
            imcol_kernel<COUT><<<dim3((P*COUT*9 + 255)/256, BB), 256>>>(in, ICh, ICl);
        // split-K x2 folded into grid.z: half writes Craw / Craw2
        gemm3_kernel<<<dim3(P/128, 1, BB*2), 256, NSTG2*STG2>>>(
            Awh, Awl, ICh, ICl, Craw, K, K, Kh/32,
            0, (size_t)P*K, (size_t)COUT*P,
            2, Kh, (size_t)BB*COUT*P);
        epi_kernel<<<(BB*COUT*P + 255)/256, 256>>>(Craw, Craw2, bias, alpha, res, o, act);
    };

    maxpool_kernel<<<(BB*CIN*P + 255)/256, 256>>>(x, h0);
    conv3g(h0, bb0_w, bb0_b, bb0_a, nullptr, h1, CIN, 2);
    conv3g(h1, rb1_w1, rb1_b1, nullptr, nullptr, tmp, COUT, 1);
    conv3g(tmp, rb1_w2, rb1_b2, nullptr, h1, h2, COUT, 0);

    conv1_kernel<<<dim3(P/256, CHALF/4, BB), 256>>>(h2, pamb_w, pamb_b, pamb_a, mb, COUT, CHALF, P);
    imcol_kernel<CHALF><<<dim3((P*K9 + 255)/256, BB), 256>>>(mb, ICh, ICl);   // XPT

    const int Hs[4]   = {64, 57, 51, 44};
    const int loff[4] = {0, 4096, 7345, 9946};
    for (int s = 0; s < 4; s++) {
        int Ls = Hs[s]*Hs[s];
        const float* refp;
        if (s == 0) refp = h2;
        else {
            int n = BB*COUT*Ls;
            resize_kernel<<<(n + 255)/256, 256>>>(h2, ref, Hs[s]);
            refp = ref;
        }
        conv1_kernel<<<dim3((Ls + 255)/256, COUT/4, BB), 256>>>(
            refp, paa_w, paa_b, paa_a, base + (size_t)BB*COUT*loff[s], COUT, COUT, Ls);
        conv1_kernel<<<dim3((Ls + 255)/256, CHALF/4, BB), 256>>>(
            refp, pam_w, pam_b, pam_a, refm + (size_t)BB*CHALF*loff[s], COUT, CHALF, Ls);
    }

    wn_kernel<<<dim3(LTP, BB), 128>>>(refm, WNh, WNl);
    rwt_kernel<<<dim3((LTP + 255)/256, K18, BB), 256>>>(base, RWth, RWtl);

    // scores[l][p] = WN[l][:] . XPT[p][:]   (M=LTP, N=4096, K=576)
    gemm3_kernel<<<dim3(P/128, LTP/128, BB), 256, NSTG2*STG2>>>(
        WNh, WNl, ICh, ICl, scores, K9, K9, K9/32,
        (size_t)LTP*K9, (size_t)P*K9, (size_t)LTP*P,
        1, 0, 0);

    softmax_part_kernel<<<dim3(P/256, NCH, BB), 256>>>(scores, pmax, psum);
    softmax_comb_kernel<<<dim3(P/256, BB), 256>>>(pmax, psum);
    attT_kernel<<<dim3(P/32, LTP/32, BB), dim3(32,8)>>>(scores, psum, attTh, attTl);

    // T[j][p] = RWt[j][:] . attT[p][:]   (M=1152, N=4096, K=LTP)
    gemm3_kernel<<<dim3(P/128, K18/128, BB), 256, NSTG2*STG2>>>(
        RWth, RWtl, attTh, attTl, T, LTP, LTP, LTP/32,
        (size_t)K18*LTP, (size_t)P*LTP, (size_t)K18*P,
        1, 0, 0);

    col2im_kernel<<<(BB*COUT*P + 255)/256, 256>>>(T, h2, h3);

    conv3g(h3, rb2_w1, rb2_b1, nullptr, nullptr, tmp, COUT, 1);
    conv3g(tmp, rb2_w2, rb2_b2, nullptr, h3, out, COUT, 0);
}

// round 13
// speedup vs baseline: 5.2336x; 1.5662x over previous
#include <cuda_runtime.h>
#include <cuda_bf16.h>
#include <cstdint>

// ---------------- dims ----------------
#define BB 2
#define CIN 64
#define COUT 128
#define CHALF 64
#define HIN 128
#define H 64
#define P (H*H)          // 4096
#define LT 11882
#define LTP 11904        // 93*128
#define K9 576
#define K18 1152
#define NCH 32
#define SCH 372

// ---------------- scratch ----------------
__device__ __align__(128) float g_h0[BB*CIN*P];
__device__ __align__(128) float g_h1[BB*COUT*P];
__device__ __align__(128) float g_h2[BB*COUT*P];
__device__ __align__(128) float g_tmp[BB*COUT*P];
__device__ __align__(128) float g_h3[BB*COUT*P];
__device__ __align__(128) float g_mb[BB*CHALF*P];
__device__ __align__(128) float g_ref[BB*COUT*3249];
__device__ __align__(128) float g_base[(size_t)BB*COUT*LT];
__device__ __align__(128) float g_refm[(size_t)BB*CHALF*LT];
__device__ __align__(128) float g_R[(size_t)BB*LTP*P];        // R = refm^T mb
__device__ __align__(128) float g_scores[(size_t)BB*LTP*P];   // scores / conv Craw scratch
__device__ __align__(128) float g_T[(size_t)BB*K18*P];        // attention GEMM partials
__device__ __align__(128) __nv_bfloat16 g_ICh[(size_t)BB*P*K18];
__device__ __align__(128) __nv_bfloat16 g_ICl[(size_t)BB*P*K18];
__device__ __align__(128) __nv_bfloat16 g_Awh[COUT*K18];
__device__ __align__(128) __nv_bfloat16 g_Awl[COUT*K18];
__device__ __align__(128) __nv_bfloat16 g_refmTh[(size_t)BB*LTP*CHALF];
__device__ __align__(128) __nv_bfloat16 g_refmTl[(size_t)BB*LTP*CHALF];
__device__ __align__(128) __nv_bfloat16 g_mbTh[(size_t)BB*P*CHALF];
__device__ __align__(128) __nv_bfloat16 g_mbTl[(size_t)BB*P*CHALF];
__device__ __align__(128) __nv_bfloat16 g_baseTh[(size_t)BB*COUT*LTP];
__device__ __align__(128) __nv_bfloat16 g_baseTl[(size_t)BB*COUT*LTP];
__device__ __align__(128) __nv_bfloat16 g_Gh[(size_t)BB*P*LTP];
__device__ __align__(128) __nv_bfloat16 g_Gl[(size_t)BB*P*LTP];
__device__ __align__(128) float g_E[BB*LTP];
__device__ __align__(128) float g_ninv[BB*LTP];
__device__ __align__(128) float g_pmax[BB*NCH*P];
__device__ __align__(128) float g_psum[BB*NCH*P];

__device__ __forceinline__ void split2(float v, __nv_bfloat16& h, __nv_bfloat16& l) {
    h = __float2bfloat16(v);
    l = __float2bfloat16(v - __bfloat162float(h));
}

__device__ __forceinline__ void decode_l(int l, int& Hs, int& loff) {
    if (l < 4096)      { Hs = 64; loff = 0; }
    else if (l < 7345) { Hs = 57; loff = 4096; }
    else if (l < 9946) { Hs = 51; loff = 7345; }
    else               { Hs = 44; loff = 9946; }
}

// ---------------- maxpool ----------------
__global__ void maxpool_kernel(const float* __restrict__ in, float* __restrict__ out) {
    int idx = blockIdx.x*blockDim.x + threadIdx.x;
    if (idx >= BB*CIN*P) return;
    int x = idx % H; int y = (idx / H) % H; int bc = idx / P;
    const float* p = in + ((size_t)bc*HIN + 2*y)*HIN + 2*x;
    out[idx] = fmaxf(fmaxf(p[0], p[1]), fmaxf(p[HIN], p[HIN+1]));
}

// ---------------- im2col (3x3 pad1), Ci compile-time ----------------
template<int Ci>
__global__ void imcol_kernel(const float* __restrict__ in,
                             __nv_bfloat16* __restrict__ Xh, __nv_bfloat16* __restrict__ Xl) {
    constexpr int K = Ci*9;
    int idx = blockIdx.x*256 + threadIdx.x;
    int b = blockIdx.y;
    if (idx >= P*K) return;
    int k = idx % K; int p = idx / K;
    int c = k/9, r = k%9; int ky = r/3, kx = r - ky*3;
    int y = (p >> 6) + ky - 1, x = (p & 63) + kx - 1;
    float v = 0.f;
    if ((unsigned)y < H && (unsigned)x < H) v = in[((size_t)b*Ci + c)*P + y*H + x];
    __nv_bfloat16 hh, ll; split2(v, hh, ll);
    size_t o = (size_t)b*P*K + idx;
    Xh[o] = hh; Xl[o] = ll;
}

// ---------------- weight split ----------------
__global__ void wsplit_kernel(const float* __restrict__ w,
                              __nv_bfloat16* __restrict__ Ah, __nv_bfloat16* __restrict__ Al,
                              int n) {
    int idx = blockIdx.x*256 + threadIdx.x;
    if (idx >= n) return;
    __nv_bfloat16 hh, ll; split2(w[idx], hh, ll);
    Ah[idx] = hh; Al[idx] = ll;
}

// ---------------- epilogue: scale*(C1+C2) + bias + act + residual ----------------
__global__ void epi_kernel(const float* __restrict__ Craw, const float* __restrict__ Craw2,
                           const float* __restrict__ bias,
                           const float* __restrict__ alpha_p, const float* __restrict__ res,
                           float* __restrict__ out, int act, float scale) {
    int idx = blockIdx.x*256 + threadIdx.x;
    if (idx >= BB*COUT*P) return;
    int co = (idx / P) % COUT;
    float v = (Craw[idx] + Craw2[idx])*scale + (bias ? bias[co] : 0.f);
    if (act == 1) v = fmaxf(v, 0.f);
    else if (act == 2) { float a = *alpha_p; v = v >= 0.f ? v : a*v; }
    if (res) v += res[idx];
    out[idx] = v;
}

// ---------------- 1x1 conv + PReLU, 4 outputs per block ----------------
__global__ void conv1_kernel(const float* __restrict__ in, const float* __restrict__ w,
                             const float* __restrict__ bias, const float* __restrict__ alpha_p,
                             float* __restrict__ out, int Ci, int Co, int Pn) {
    int p = blockIdx.x*256 + threadIdx.x;
    int o0 = blockIdx.y*4, b = blockIdx.z;
    if (p >= Pn) return;
    const float* ip = in + (size_t)b*Ci*Pn + p;
    float acc[4];
    #pragma unroll
    for (int o = 0; o < 4; o++) acc[o] = bias[o0 + o];
    #pragma unroll 4
    for (int i = 0; i < Ci; i++) {
        float t = ip[(size_t)i*Pn];
        #pragma unroll
        for (int o = 0; o < 4; o++) acc[o] += w[(size_t)(o0+o)*Ci + i] * t;
    }
    float a = *alpha_p;
    #pragma unroll
    for (int o = 0; o < 4; o++) {
        float v = acc[o];
        out[((size_t)b*Co + o0 + o)*Pn + p] = v >= 0.f ? v : a*v;
    }
}

// ---------------- bilinear resize with antialias ----------------
__global__ void resize_kernel(const float* __restrict__ in, float* __restrict__ out, int Hout) {
    int total = BB*COUT*Hout*Hout;
    int idx = blockIdx.x*blockDim.x + threadIdx.x;
    if (idx >= total) return;
    int xo = idx % Hout; int yo = (idx / Hout) % Hout; int bc = idx / (Hout*Hout);
    float inv = (float)H / (float)Hout;
    float sy = (yo + 0.5f)*inv - 0.5f;
    float sx = (xo + 0.5f)*inv - 0.5f;
    float wy[4], wx[4]; int jy[4], jx[4];
    int ny = 0, nx = 0; float sumy = 0.f, sumx = 0.f;
    int lo = (int)ceilf(sy - inv), hi = (int)floorf(sy + inv);
    if (lo < 0) lo = 0; if (hi > H-1) hi = H-1;
    for (int j = lo; j <= hi && ny < 4; j++) {
        float w = 1.0f - fabsf(sy - (float)j)/inv;
        if (w > 0.f) { wy[ny] = w; jy[ny] = j; sumy += w; ny++; }
    }
    lo = (int)ceilf(sx - inv); hi = (int)floorf(sx + inv);
    if (lo < 0) lo = 0; if (hi > H-1) hi = H-1;
    for (int j = lo; j <= hi && nx < 4; j++) {
        float w = 1.0f - fabsf(sx - (float)j)/inv;
        if (w > 0.f) { wx[nx] = w; jx[nx] = j; sumx += w; nx++; }
    }
    const float* ip = in + (size_t)bc*P;
    float acc = 0.f;
    for (int a = 0; a < ny; a++)
        for (int bx2 = 0; bx2 < nx; bx2++)
            acc += wy[a]*wx[bx2]*ip[jy[a]*H + jx[bx2]];
    out[idx] = acc / (sumy*sumx);
}

// ---------------- refmT[b][l][c] + E[b][l] = sum_c refm^2 ----------------
__global__ void refmT_kernel(const float* __restrict__ refm,
                             __nv_bfloat16* __restrict__ Th, __nv_bfloat16* __restrict__ Tl,
                             float* __restrict__ E) {
    int l = blockIdx.x, b = blockIdx.y, c = threadIdx.x;   // 64 threads
    float v = 0.f;
    if (l < LT) {
        int Hs, loff; decode_l(l, Hs, loff);
        int Ls = Hs*Hs;
        v = refm[(size_t)BB*CHALF*loff + ((size_t)b*CHALF + c)*Ls + (l - loff)];
    }
    __nv_bfloat16 hh, ll; split2(v, hh, ll);
    size_t o = ((size_t)b*LTP + l)*CHALF + c;
    Th[o] = hh; Tl[o] = ll;
    __shared__ float red[64];
    red[c] = v*v; __syncthreads();
    for (int s = 32; s > 0; s >>= 1) { if (c < s) red[c] += red[c+s]; __syncthreads(); }
    if (c == 0) E[(size_t)b*LTP + l] = red[0];
}

// ---------------- ninv[b][l] = 1/max(sqrt(9-sum of E), 1e-4) ----------------
__global__ void ninv_kernel(const float* __restrict__ E, float* __restrict__ ninv) {
    int l = blockIdx.x*256 + threadIdx.x; int b = blockIdx.y;
    if (l >= LT) return;
    int Hs, loff; decode_l(l, Hs, loff);
    int ll = l - loff; int lh = ll/Hs, lw = ll%Hs;
    float a = 0.f;
    #pragma unroll
    for (int u = -1; u <= 1; u++) {
        if ((unsigned)(lh+u) >= (unsigned)Hs) continue;
        #pragma unroll
        for (int v = -1; v <= 1; v++) {
            if ((unsigned)(lw+v) >= (unsigned)Hs) continue;
            a += E[(size_t)b*LTP + l + u*Hs + v];
        }
    }
    ninv[(size_t)b*LTP + l] = 1.0f / fmaxf(sqrtf(a), 1e-4f);
}

// ---------------- mbT[b][p][c] split ----------------
__global__ void mbT_kernel(const float* __restrict__ mb,
                           __nv_bfloat16* __restrict__ Th, __nv_bfloat16* __restrict__ Tl) {
    int idx = blockIdx.x*256 + threadIdx.x;
    if (idx >= BB*P*CHALF) return;
    int c = idx % CHALF; int p = (idx / CHALF) % P; int b = idx / (CHALF*P);
    float v = mb[((size_t)b*CHALF + c)*P + p];
    __nv_bfloat16 hh, ll; split2(v, hh, ll);
    Th[idx] = hh; Tl[idx] = ll;
}

// ---------------- baseT[b][c][l] split (pad zero) ----------------
__global__ void baseT_kernel(const float* __restrict__ base,
                             __nv_bfloat16* __restrict__ Th, __nv_bfloat16* __restrict__ Tl) {
    int idx = blockIdx.x*256 + threadIdx.x;
    if (idx >= BB*COUT*LTP) return;
    int l = idx % LTP; int c = (idx / LTP) % COUT; int b = idx / (LTP*COUT);
    float v = 0.f;
    if (l < LT) {
        int Hs, loff; decode_l(l, Hs, loff);
        int Ls = Hs*Hs;
        v = base[(size_t)BB*COUT*loff + ((size_t)b*COUT + c)*Ls + (l - loff)];
    }
    __nv_bfloat16 hh, ll; split2(v, hh, ll);
    Th[idx] = hh; Tl[idx] = ll;
}

// ---------------- assembly: scores[l][p] = ninv[l] * sum_{u,v} R[l+(u,v)][p+(u,v)] ----------------
__global__ void assembly_kernel(const float* __restrict__ R, const float* __restrict__ ninv,
                                float* __restrict__ scores) {
    int p = blockIdx.x*256 + threadIdx.x;
    int l = blockIdx.y, b = blockIdx.z;
    int Hs, loff; decode_l(l, Hs, loff);
    int ll = l - loff; int lh = ll/Hs, lw = ll%Hs;
    int py = p >> 6, px = p & 63;
    float s = 0.f;
    #pragma unroll
    for (int u = -1; u <= 1; u++) {
        if ((unsigned)(lh+u) >= (unsigned)Hs) continue;
        if ((unsigned)(py+u) >= 64u) continue;
        #pragma unroll
        for (int v = -1; v <= 1; v++) {
            if ((unsigned)(lw+v) >= (unsigned)Hs) continue;
            if ((unsigned)(px+v) >= 64u) continue;
            s += R[((size_t)b*LTP + l + u*Hs + v)*P + p + u*64 + v];
        }
    }
    scores[((size_t)b*LTP + l)*P + p] = s * ninv[(size_t)b*LTP + l];
}

// ---------------- softmax pass 1 (stores exp in place) ----------------
__global__ void softmax_part_kernel(float* __restrict__ scores,
                                    float* __restrict__ pmax, float* __restrict__ psum) {
    int p = blockIdx.x*256 + threadIdx.x;
    int c = blockIdx.y, b = blockIdx.z;
    int l0 = c*SCH, l1 = l0 + SCH; if (l1 > LT) l1 = LT;
    float* s = scores + (size_t)b*LTP*P + p;
    float m = -1e30f;
    for (int l = l0; l < l1; l++) m = fmaxf(m, s[(size_t)l*P]);
    float sum = 0.f;
    for (int l = l0; l < l1; l++) {
        float e = __expf(10.f*(s[(size_t)l*P] - m));
        s[(size_t)l*P] = e;
        sum += e;
    }
    pmax[((size_t)b*NCH + c)*P + p] = m;
    psum[((size_t)b*NCH + c)*P + p] = sum;
}

__global__ void softmax_comb_kernel(const float* __restrict__ pmax, float* __restrict__ psum) {
    int p = blockIdx.x*256 + threadIdx.x; int b = blockIdx.y;
    float M = -1e30f;
    for (int c = 0; c < NCH; c++) M = fmaxf(M, pmax[((size_t)b*NCH + c)*P + p]);
    float S = 0.f;
    for (int c = 0; c < NCH; c++)
        S += psum[((size_t)b*NCH + c)*P + p] * __expf(10.f*(pmax[((size_t)b*NCH + c)*P + p] - M));
    float invS = 1.0f / S;
    for (int c = 0; c < NCH; c++)
        psum[((size_t)b*NCH + c)*P + p] =
            __expf(10.f*(pmax[((size_t)b*NCH + c)*P + p] - M)) * invS;
}

// ---------------- G[b][p][m] = sum_{u,v} att[m+(u,v)][p+(u,v)], bf16 hi/lo, transposed ----------------
__global__ void G_kernel(const float* __restrict__ scores, const float* __restrict__ psum,
                         __nv_bfloat16* __restrict__ Th, __nv_bfloat16* __restrict__ Tl) {
    __shared__ float t[32][33];
    int p0 = blockIdx.x*32, m0 = blockIdx.y*32, b = blockIdx.z;
    int tx = threadIdx.x, ty = threadIdx.y;
    #pragma unroll
    for (int i = 0; i < 4; i++) {
        int m = m0 + ty + i*8;
        float g = 0.f;
        if (m < LT) {
            int Hs, loff; decode_l(m, Hs, loff);
            int mm = m - loff; int mh = mm/Hs, mw = mm%Hs;
            int p = p0 + tx; int py = p >> 6, px = p & 63;
            #pragma unroll
            for (int u = -1; u <= 1; u++) {
                if ((unsigned)(mh+u) >= (unsigned)Hs) continue;
                if ((unsigned)(py+u) >= 64u) continue;
                #pragma unroll
                for (int v = -1; v <= 1; v++) {
                    if ((unsigned)(mw+v) >= (unsigned)Hs) continue;
                    if ((unsigned)(px+v) >= 64u) continue;
                    int lp = m + u*Hs + v; int pp = p + u*64 + v;
                    g += scores[((size_t)b*LTP + lp)*P + pp] *
                         psum[((size_t)b*NCH + lp/SCH)*P + pp];
                }
            }
        }
        t[ty + i*8][tx] = g;
    }
    __syncthreads();
    #pragma unroll
    for (int i = 0; i < 4; i++) {
        int p = p0 + ty + i*8;
        float v = t[tx][ty + i*8];
        __nv_bfloat16 hh, lo; split2(v, hh, lo);
        size_t o = ((size_t)b*P + p)*LTP + m0 + tx;
        Th[o] = hh; Tl[o] = lo;
    }
}

// ---------------- bf16x3 mma.sync GEMM: CTA 128x128, warp 64x32, 2-stage, occ 2 ----------------
#define AP2 10240
#define STG2 (4*AP2)
#define NSTG2 2

#define LDSM4(R, addr) asm volatile( \
    "ldmatrix.sync.aligned.m8n8.x4.shared.b16 {%0,%1,%2,%3},[%4];" \
    : "=r"((R)[0]),"=r"((R)[1]),"=r"((R)[2]),"=r"((R)[3]) : "r"(addr))
#define MMA16816(d, a, b0, b1) asm volatile( \
    "mma.sync.aligned.m16n8k16.row.col.f32.bf16.bf16.f32 " \
    "{%0,%1,%2,%3},{%4,%5,%6,%7},{%8,%9},{%0,%1,%2,%3};" \
    : "+f"((d)[0]),"+f"((d)[1]),"+f"((d)[2]),"+f"((d)[3]) \
    : "r"((a)[0]),"r"((a)[1]),"r"((a)[2]),"r"((a)[3]),"r"(b0),"r"(b1))
#define CPA16(dst, src) asm volatile( \
    "cp.async.cg.shared.global [%0],[%1],16;" :: "r"(dst),"l"(src))

__global__ __launch_bounds__(256, 2) void gemm3_kernel(
    const __nv_bfloat16* __restrict__ Ah, const __nv_bfloat16* __restrict__ Al,
    const __nv_bfloat16* __restrict__ Bh, const __nv_bfloat16* __restrict__ Bl,
    float* __restrict__ C, int lda, int ldb, int KIT,
    size_t sA, size_t sB, size_t sC,
    int nsplit, int koffE, size_t sSplit)
{
    extern __shared__ char smem[];
    int zz = blockIdx.z;
    int half = zz % nsplit, b = zz / nsplit;
    int kofs = half * koffE;
    const __nv_bfloat16* pAh = Ah + (size_t)b*sA + kofs;
    const __nv_bfloat16* pAl = Al + (size_t)b*sA + kofs;
    const __nv_bfloat16* pBh = Bh + (size_t)b*sB + kofs;
    const __nv_bfloat16* pBl = Bl + (size_t)b*sB + kofs;
    float* pC = C + (size_t)b*sC + (size_t)half*sSplit;
    int row0 = blockIdx.y*128, col0 = blockIdx.x*128;
    int tid = threadIdx.x, lane = tid & 31, wid = tid >> 5;
    int wm = (wid >> 2)*64, wn = (wid & 3)*32;
    uint32_t sb = (uint32_t)__cvta_generic_to_shared(smem);

    float acc[4][4][4];
    #pragma unroll
    for (int i = 0; i < 4; i++)
        #pragma unroll
        for (int j = 0; j < 4; j++)
            #pragma unroll
            for (int r = 0; r < 4; r++) acc[i][j][r] = 0.f;

    auto issue = [&](int it) {
        uint32_t st = sb + (uint32_t)(it & 1)*STG2;
        int k0 = it << 5;
        #pragma unroll
        for (int q = 0; q < 4; q++) {
            int v = tid + q*256;
            int pl = v >> 9, r = (v >> 2) & 127, kv = v & 3;
            const __nv_bfloat16* src = (pl ? pAl : pAh) + (size_t)(row0 + r)*lda + k0 + kv*8;
            CPA16(st + pl*AP2 + (uint32_t)(r*80 + kv*16), src);
        }
        #pragma unroll
        for (int q = 0; q < 4; q++) {
            int v = tid + q*256;
            int pl = v >> 9, n = (v >> 2) & 127, kv = v & 3;
            const __nv_bfloat16* src = (pl ? pBl : pBh) + (size_t)(col0 + n)*ldb + k0 + kv*8;
            CPA16(st + 2*AP2 + pl*AP2 + (uint32_t)(n*80 + kv*16), src);
        }
    };

    issue(0);
    asm volatile("cp.async.commit_group;");

    for (int it = 0; it < KIT; it++) {
        if (it + 1 < KIT) {
            __syncthreads();
            issue(it + 1);
            asm volatile("cp.async.commit_group;");
            asm volatile("cp.async.wait_group 1;");
        } else {
            asm volatile("cp.async.wait_group 0;");
        }
        __syncthreads();
        uint32_t st = sb + (uint32_t)(it & 1)*STG2;
        #pragma unroll
        for (int ks = 0; ks < 2; ks++) {
            int koff = ks*16;
            uint32_t ah[4][4], al_[4][4];
            #pragma unroll
            for (int i = 0; i < 4; i++) {
                uint32_t addr = st + (uint32_t)((wm + i*16 + (lane & 15))*80
                                  + (koff + ((lane >> 4) << 3))*2);
                LDSM4(ah[i], addr);
                LDSM4(al_[i], addr + AP2);
            }
            uint32_t bf0[4], bf1[4];
            {
                uint32_t addr = st + 2*AP2 + (uint32_t)((wn + lane)*80 + koff*2);
                LDSM4(bf0, addr);
                LDSM4(bf1, addr + 16);
            }
            #pragma unroll
            for (int i = 0; i < 4; i++)
                #pragma unroll
                for (int j = 0; j < 4; j++)
                    MMA16816(acc[i][j], ah[i], bf0[j], bf1[j]);
            #pragma unroll
            for (int i = 0; i < 4; i++)
                #pragma unroll
                for (int j = 0; j < 4; j++)
                    MMA16816(acc[i][j], al_[i], bf0[j], bf1[j]);
            {
                uint32_t addr = st + 3*AP2 + (uint32_t)((wn + lane)*80 + koff*2);
                LDSM4(bf0, addr);
                LDSM4(bf1, addr + 16);
            }
            #pragma unroll
            for (int i = 0; i < 4; i++)
                #pragma unroll
                for (int j = 0; j < 4; j++)
                    MMA16816(acc[i][j], ah[i], bf0[j], bf1[j]);
        }
    }

    #pragma unroll
    for (int i = 0; i < 4; i++) {
        int r = row0 + wm + i*16 + (lane >> 2);
        #pragma unroll
        for (int j = 0; j < 4; j++) {
            int c = col0 + wn + j*8 + ((lane & 3) << 1);
            *(float2*)&pC[(size_t)r*4096 + c] = make_float2(acc[i][j][0], acc[i][j][1]);
            *(float2*)&pC[(size_t)(r+8)*4096 + c] = make_float2(acc[i][j][2], acc[i][j][3]);
        }
    }
}

// ---------------- launch ----------------
extern "C" void kernel_launch(void* const* d_in, const int* in_sizes, int n_in,
                              void* d_out, int out_size) {
    (void)in_sizes; (void)n_in; (void)out_size;
    const float* x      = (const float*)d_in[0];
    const float* bb0_w  = (const float*)d_in[1];
    const float* bb0_b  = (const float*)d_in[2];
    const float* bb0_a  = (const float*)d_in[3];
    const float* rb1_w1 = (const float*)d_in[4];
    const float* rb1_b1 = (const float*)d_in[5];
    const float* rb1_w2 = (const float*)d_in[6];
    const float* rb1_b2 = (const float*)d_in[7];
    const float* pamb_w = (const float*)d_in[8];
    const float* pamb_b = (const float*)d_in[9];
    const float* pamb_a = (const float*)d_in[10];
    const float* pam_w  = (const float*)d_in[11];
    const float* pam_b  = (const float*)d_in[12];
    const float* pam_a  = (const float*)d_in[13];
    const float* paa_w  = (const float*)d_in[14];
    const float* paa_b  = (const float*)d_in[15];
    const float* paa_a  = (const float*)d_in[16];
    const float* rb2_w1 = (const float*)d_in[17];
    const float* rb2_b1 = (const float*)d_in[18];
    const float* rb2_w2 = (const float*)d_in[19];
    const float* rb2_b2 = (const float*)d_in[20];
    float* out = (float*)d_out;

    float *h0,*h1,*h2,*tmp,*h3,*mb,*ref,*base,*refm,*R,*scores,*T,*pmax,*psum,*E,*ninv;
    __nv_bfloat16 *ICh,*ICl,*Awh,*Awl,*refmTh,*refmTl,*mbTh,*mbTl,*baseTh,*baseTl,*Gh,*Gl;
    cudaGetSymbolAddress((void**)&h0, g_h0);
    cudaGetSymbolAddress((void**)&h1, g_h1);
    cudaGetSymbolAddress((void**)&h2, g_h2);
    cudaGetSymbolAddress((void**)&tmp, g_tmp);
    cudaGetSymbolAddress((void**)&h3, g_h3);
    cudaGetSymbolAddress((void**)&mb, g_mb);
    cudaGetSymbolAddress((void**)&ref, g_ref);
    cudaGetSymbolAddress((void**)&base, g_base);
    cudaGetSymbolAddress((void**)&refm, g_refm);
    cudaGetSymbolAddress((void**)&R, g_R);
    cudaGetSymbolAddress((void**)&scores, g_scores);
    cudaGetSymbolAddress((void**)&T, g_T);
    cudaGetSymbolAddress((void**)&ICh, g_ICh);
    cudaGetSymbolAddress((void**)&ICl, g_ICl);
    cudaGetSymbolAddress((void**)&Awh, g_Awh);
    cudaGetSymbolAddress((void**)&Awl, g_Awl);
    cudaGetSymbolAddress((void**)&refmTh, g_refmTh);
    cudaGetSymbolAddress((void**)&refmTl, g_refmTl);
    cudaGetSymbolAddress((void**)&mbTh, g_mbTh);
    cudaGetSymbolAddress((void**)&mbTl, g_mbTl);
    cudaGetSymbolAddress((void**)&baseTh, g_baseTh);
    cudaGetSymbolAddress((void**)&baseTl, g_baseTl);
    cudaGetSymbolAddress((void**)&Gh, g_Gh);
    cudaGetSymbolAddress((void**)&Gl, g_Gl);
    cudaGetSymbolAddress((void**)&E, g_E);
    cudaGetSymbolAddress((void**)&ninv, g_ninv);
    cudaGetSymbolAddress((void**)&pmax, g_pmax);
    cudaGetSymbolAddress((void**)&psum, g_psum);

    cudaFuncSetAttribute(gemm3_kernel, cudaFuncAttributeMaxDynamicSharedMemorySize, NSTG2*STG2);

    float* Craw  = scores;
    float* Craw2 = scores + (size_t)BB*COUT*P;
    auto conv3g = [&](const float* in, const float* w, const float* bias,
                      const float* alpha, const float* res, float* o, int Ci, int act) {
        int K = Ci*9, Kh = K/2;
        wsplit_kernel<<<(COUT*K + 255)/256, 256>>>(w, Awh, Awl, COUT*K);
        if (Ci == CIN)
            imcol_kernel<CIN><<<dim3((P*CIN*9 + 255)/256, BB), 256>>>(in, ICh, ICl);
        else
            imcol_kernel<COUT><<<dim3((P*COUT*9 + 255)/256, BB), 256>>>(in, ICh, ICl);
        gemm3_kernel<<<dim3(P/128, 1, BB*2), 256, NSTG2*STG2>>>(
            Awh, Awl, ICh, ICl, Craw, K, K, Kh/32,
            0, (size_t)P*K, (size_t)COUT*P,
            2, Kh, (size_t)BB*COUT*P);
        epi_kernel<<<(BB*COUT*P + 255)/256, 256>>>(Craw, Craw2, bias, alpha, res, o, act, 1.0f);
    };

    maxpool_kernel<<<(BB*CIN*P + 255)/256, 256>>>(x, h0);
    conv3g(h0, bb0_w, bb0_b, bb0_a, nullptr, h1, CIN, 2);
    conv3g(h1, rb1_w1, rb1_b1, nullptr, nullptr, tmp, COUT, 1);
    conv3g(tmp, rb1_w2, rb1_b2, nullptr, h1, h2, COUT, 0);

    // pyramid producers
    conv1_kernel<<<dim3(P/256, CHALF/4, BB), 256>>>(h2, pamb_w, pamb_b, pamb_a, mb, COUT, CHALF, P);
    const int Hs[4]   = {64, 57, 51, 44};
    const int loff[4] = {0, 4096, 7345, 9946};
    for (int s = 0; s < 4; s++) {
        int Ls = Hs[s]*Hs[s];
        const float* refp;
        if (s == 0) refp = h2;
        else {
            int n = BB*COUT*Ls;
            resize_kernel<<<(n + 255)/256, 256>>>(h2, ref, Hs[s]);
            refp = ref;
        }
        conv1_kernel<<<dim3((Ls + 255)/256, COUT/4, BB), 256>>>(
            refp, paa_w, paa_b, paa_a, base + (size_t)BB*COUT*loff[s], COUT, COUT, Ls);
        conv1_kernel<<<dim3((Ls + 255)/256, CHALF/4, BB), 256>>>(
            refp, pam_w, pam_b, pam_a, refm + (size_t)BB*CHALF*loff[s], COUT, CHALF, Ls);
    }

    mbT_kernel<<<(BB*P*CHALF + 255)/256, 256>>>(mb, mbTh, mbTl);
    refmT_kernel<<<dim3(LTP, BB), 64>>>(refm, refmTh, refmTl, E);
    ninv_kernel<<<dim3((LT + 255)/256, BB), 256>>>(E, ninv);
    baseT_kernel<<<(BB*COUT*LTP + 255)/256, 256>>>(base, baseTh, baseTl);

    // R[m][p] = refm^T mb  (M=LTP, N=4096, K=64)
    gemm3_kernel<<<dim3(P/128, LTP/128, BB), 256, NSTG2*STG2>>>(
        refmTh, refmTl, mbTh, mbTl, R, CHALF, CHALF, CHALF/32,
        (size_t)LTP*CHALF, (size_t)P*CHALF, (size_t)LTP*P,
        1, 0, 0);

    // scores = 9-point diagonal sum of R, normalized
    assembly_kernel<<<dim3(P/256, LT, BB), 256>>>(R, ninv, scores);

    softmax_part_kernel<<<dim3(P/256, NCH, BB), 256>>>(scores, pmax, psum);
    softmax_comb_kernel<<<dim3(P/256, BB), 256>>>(pmax, psum);

    // G = 9-point diagonal sum of attention, transposed + bf16 split
    G_kernel<<<dim3(P/32, LTP/32, BB), dim3(32,8)>>>(scores, psum, Gh, Gl);

    // out_raw = base x G  (M=128, N=4096, K=LTP), split-K x2
    gemm3_kernel<<<dim3(P/128, 1, BB*2), 256, NSTG2*STG2>>>(
        baseTh, baseTl, Gh, Gl, T, LTP, LTP, (LTP/2)/32,
        (size_t)COUT*LTP, (size_t)P*LTP, (size_t)COUT*P,
        2, LTP/2, (size_t)BB*COUT*P);

    // h3 = h2 + 0.25*out_raw
    epi_kernel<<<(BB*COUT*P + 255)/256, 256>>>(T, T + (size_t)BB*COUT*P,
                                               nullptr, nullptr, h2, h3, 0, 0.25f);

    conv3g(h3, rb2_w1, rb2_b1, nullptr, nullptr, tmp, COUT, 1);
    conv3g(tmp, rb2_w2, rb2_b2, nullptr, h3, out, COUT, 0);
}